// round 1
// baseline (speedup 1.0000x reference)
#include <cuda_runtime.h>

#define BATCH 8
#define CIN   256
#define CC    128
#define NPIX  2304
#define EPSB  1e-5f

// ---------------- scratch (__device__ globals: the allowed scratch mechanism) ----
__device__ __align__(16) float g_qt[BATCH*CC*NPIX];
__device__ __align__(16) float g_st[BATCH*CC*NPIX];
__device__ __align__(16) float g_vq[BATCH*CC*NPIX];
__device__ __align__(16) float g_vs[BATCH*CC*NPIX];
__device__ __align__(16) float g_kx[BATCH*CC*NPIX];
__device__ __align__(16) float g_qx[BATCH*CC*NPIX];
__device__ __align__(16) float g_A[(size_t)BATCH*NPIX*NPIX];   // 170 MB score matrix
__device__ float g_rmax[BATCH*NPIX];
__device__ float g_rinv[BATCH*NPIX];
__device__ float g_cmax[BATCH*NPIX];
__device__ float g_cinv[BATCH*NPIX];
__device__ float g_gq[BATCH*CC];
__device__ float g_gs[BATCH*CC];

// ---------------- shared inner product step: 16-deep k-slice, 8x4 per-thread ----
template<int SA, int SB>
__device__ __forceinline__ void mma16(const float* As, const float* Bs,
                                      int tm, int tn, float acc[8][4]) {
#pragma unroll
    for (int k = 0; k < 16; ++k) {
        float4 b4 = *(const float4*)&Bs[k*SB + tn];
#pragma unroll
        for (int i = 0; i < 8; ++i) {
            float a = As[k*SA + tm + i];
            acc[i][0] += a*b4.x; acc[i][1] += a*b4.y;
            acc[i][2] += a*b4.z; acc[i][3] += a*b4.w;
        }
    }
}

// ---------------- 1x1 conv as GEMM: out[b][o][p] = sum_k w[o][k] x[b][k][p] ----
// optional fused BatchNorm (bng != nullptr)
__global__ __launch_bounds__(256) void gemm_wx(
    const float* __restrict__ x, const float* __restrict__ w,
    const float* __restrict__ bias,
    const float* __restrict__ bng, const float* __restrict__ bnb,
    const float* __restrict__ bnm, const float* __restrict__ bnv,
    float* __restrict__ out, int K)
{
    const int b  = blockIdx.y;
    const int p0 = blockIdx.x * 64;
    const float* xb = x + (size_t)b * K * NPIX;
    float* ob = out + (size_t)b * CC * NPIX;
    __shared__ __align__(16) float As[16*132];
    __shared__ __align__(16) float Bs[16*64];
    const int tid = threadIdx.x;
    const int tn = (tid & 15) * 4;
    const int tm = (tid >> 4) * 8;
    const int kc = tid & 15, orow = tid >> 4;
    const int pc = tid & 63, kr4 = tid >> 6;
    float acc[8][4] = {};
    for (int k0 = 0; k0 < K; k0 += 16) {
#pragma unroll
        for (int ps = 0; ps < 8; ++ps) {
            int o = orow + ps*16;
            As[kc*132 + o] = w[o*K + k0 + kc];
        }
#pragma unroll
        for (int ps = 0; ps < 4; ++ps) {
            int k = kr4 + ps*4;
            Bs[k*64 + pc] = xb[(size_t)(k0+k)*NPIX + p0 + pc];
        }
        __syncthreads();
        mma16<132,64>(As, Bs, tm, tn, acc);
        __syncthreads();
    }
#pragma unroll
    for (int i = 0; i < 8; ++i) {
        int o = tm + i;
        float sc = 1.0f, cb = bias[o];
        if (bng) {
            sc = bng[o] * rsqrtf(bnv[o] + EPSB);
            cb = (bias[o] - bnm[o]) * sc + bnb[o];
        }
        float4 r;
        r.x = acc[i][0]*sc + cb; r.y = acc[i][1]*sc + cb;
        r.z = acc[i][2]*sc + cb; r.w = acc[i][3]*sc + cb;
        *(float4*)&ob[(size_t)o*NPIX + p0 + tn] = r;
    }
}

// ---------------- score: A[b][n][m] = sum_c kx[b][c][n] * qx[b][c][m] ----------
__global__ __launch_bounds__(256) void score_kernel()
{
    const int b  = blockIdx.z;
    const int n0 = blockIdx.y * 128;
    const int m0 = blockIdx.x * 64;
    const float* kx = g_kx + (size_t)b*CC*NPIX;
    const float* qx = g_qx + (size_t)b*CC*NPIX;
    float* Ab = g_A + (size_t)b*NPIX*NPIX;
    __shared__ __align__(16) float As[16*128];
    __shared__ __align__(16) float Bs[16*64];
    const int tid = threadIdx.x;
    const int tn = (tid & 15)*4, tm = (tid >> 4)*8;
    const int nc = tid & 127, kr2 = tid >> 7;
    const int pc = tid & 63,  kr4 = tid >> 6;
    float acc[8][4] = {};
    for (int k0 = 0; k0 < CC; k0 += 16) {
#pragma unroll
        for (int ps = 0; ps < 8; ++ps) {
            int k = kr2 + ps*2;
            As[k*128 + nc] = kx[(size_t)(k0+k)*NPIX + n0 + nc];
        }
#pragma unroll
        for (int ps = 0; ps < 4; ++ps) {
            int k = kr4 + ps*4;
            Bs[k*64 + pc] = qx[(size_t)(k0+k)*NPIX + m0 + pc];
        }
        __syncthreads();
        mma16<128,64>(As, Bs, tm, tn, acc);
        __syncthreads();
    }
#pragma unroll
    for (int i = 0; i < 8; ++i) {
        float4 r; r.x = acc[i][0]; r.y = acc[i][1]; r.z = acc[i][2]; r.w = acc[i][3];
        *(float4*)&Ab[(size_t)(n0+tm+i)*NPIX + m0 + tn] = r;
    }
}

// ---------------- row softmax stats (over m, per row n) ------------------------
__global__ __launch_bounds__(256) void row_stats_kernel()
{
    const int n = blockIdx.x, b = blockIdx.y;
    const float* row = g_A + ((size_t)b*NPIX + n)*NPIX;
    const int tid = threadIdx.x;
    float v[9];
    float mx = -1e30f;
#pragma unroll
    for (int i = 0; i < 9; ++i) { v[i] = row[tid + i*256]; mx = fmaxf(mx, v[i]); }
    __shared__ float s1[8], s2[8];
#pragma unroll
    for (int o = 16; o; o >>= 1) mx = fmaxf(mx, __shfl_xor_sync(~0u, mx, o));
    if ((tid & 31) == 0) s1[tid >> 5] = mx;
    __syncthreads();
    mx = s1[0];
#pragma unroll
    for (int j = 1; j < 8; ++j) mx = fmaxf(mx, s1[j]);
    float s = 0.f;
#pragma unroll
    for (int i = 0; i < 9; ++i) s += __expf(v[i] - mx);
#pragma unroll
    for (int o = 16; o; o >>= 1) s += __shfl_xor_sync(~0u, s, o);
    if ((tid & 31) == 0) s2[tid >> 5] = s;
    __syncthreads();
    if (tid == 0) {
        float t = 0.f;
#pragma unroll
        for (int j = 0; j < 8; ++j) t += s2[j];
        g_rmax[b*NPIX + n] = mx;
        g_rinv[b*NPIX + n] = 1.0f / t;
    }
}

// ---------------- column softmax stats (over n, per column m) ------------------
__global__ __launch_bounds__(256) void col_stats_kernel()
{
    const int m = blockIdx.x * 256 + threadIdx.x;
    const int b = blockIdx.y;
    const float* Ab = g_A + (size_t)b*NPIX*NPIX;
    float mx = -1e30f, s = 0.f;
    for (int n = 0; n < NPIX; ++n) {
        float x = Ab[(size_t)n*NPIX + m];
        if (x <= mx) s += __expf(x - mx);
        else { s = s * __expf(mx - x) + 1.0f; mx = x; }
    }
    g_cmax[b*NPIX + m] = mx;
    g_cinv[b*NPIX + m] = 1.0f / s;
}

// ---------------- channel gate: avg-pool -> MLP(128->8->128) -> sigmoid --------
__global__ __launch_bounds__(256) void gate_kernel(
    const float* __restrict__ w1, const float* __restrict__ b1,
    const float* __restrict__ w2, const float* __restrict__ b2)
{
    const int b = blockIdx.y;
    const float* t = (blockIdx.x == 0 ? g_qt : g_st) + (size_t)b*CC*NPIX;
    float* go = (blockIdx.x == 0 ? g_gq : g_gs) + b*CC;
    __shared__ float pool[CC];
    __shared__ float hsh[8];
    const int tid = threadIdx.x, lane = tid & 31, wid = tid >> 5;
    for (int ch = wid; ch < CC; ch += 8) {
        const float* row = t + (size_t)ch*NPIX;
        float s = 0.f;
        for (int i = lane; i < NPIX; i += 32) s += row[i];
#pragma unroll
        for (int o = 16; o; o >>= 1) s += __shfl_xor_sync(~0u, s, o);
        if (lane == 0) pool[ch] = s * (1.0f/NPIX);
    }
    __syncthreads();
    if (tid < 8) {
        float h = b1[tid];
        for (int i = 0; i < CC; ++i) h += pool[i] * w1[tid*CC + i];
        hsh[tid] = fmaxf(h, 0.f);
    }
    __syncthreads();
    if (tid < CC) {
        float z = b2[tid];
#pragma unroll
        for (int j = 0; j < 8; ++j) z += hsh[j] * w2[tid*8 + j];
        go[tid] = 1.0f / (1.0f + __expf(-z));
    }
}

// ---------------- E_s = gate_s * (rowSoftmax(A) @ v_s) + s' --------------------
// out[co][n] = gs[co] * (sum_m exp(A[n][m]-rmax[n]) * vs[co][m]) * rinv[n] + st[co][n]
__global__ __launch_bounds__(256) void attn_s_kernel(float* __restrict__ Es)
{
    const int b  = blockIdx.y;
    const int n0 = blockIdx.x * 64;
    const float* Ab = g_A  + (size_t)b*NPIX*NPIX;
    const float* vs = g_vs + (size_t)b*CC*NPIX;
    const float* st = g_st + (size_t)b*CC*NPIX;
    float* Eb = Es + (size_t)b*CC*NPIX;
    __shared__ __align__(16) float As[16*132];
    __shared__ __align__(16) float Bs[16*68];
    __shared__ float rmax_s[64], rinv_s[64];
    const int tid = threadIdx.x;
    if (tid < 64) {
        rmax_s[tid] = g_rmax[b*NPIX + n0 + tid];
        rinv_s[tid] = g_rinv[b*NPIX + n0 + tid];
    }
    __syncthreads();
    const int tn = (tid & 15)*4, tm = (tid >> 4)*8;
    const int kc = tid & 15, orow = tid >> 4;
    float acc[8][4] = {};
    for (int k0 = 0; k0 < NPIX; k0 += 16) {
#pragma unroll
        for (int ps = 0; ps < 8; ++ps) {
            int o = orow + ps*16;
            As[kc*132 + o] = vs[(size_t)o*NPIX + k0 + kc];
        }
#pragma unroll
        for (int ps = 0; ps < 4; ++ps) {
            int nl = orow + ps*16;
            Bs[kc*68 + nl] = __expf(Ab[(size_t)(n0+nl)*NPIX + k0 + kc] - rmax_s[nl]);
        }
        __syncthreads();
        mma16<132,68>(As, Bs, tm, tn, acc);
        __syncthreads();
    }
#pragma unroll
    for (int i = 0; i < 8; ++i) {
        int o = tm + i;
        float gt = g_gs[b*CC + o];
        const float* sr = &st[(size_t)o*NPIX + n0 + tn];
        float4 r;
        r.x = gt*acc[i][0]*rinv_s[tn+0] + sr[0];
        r.y = gt*acc[i][1]*rinv_s[tn+1] + sr[1];
        r.z = gt*acc[i][2]*rinv_s[tn+2] + sr[2];
        r.w = gt*acc[i][3]*rinv_s[tn+3] + sr[3];
        *(float4*)&Eb[(size_t)o*NPIX + n0 + tn] = r;
    }
}

// ---------------- E_q = gate_q * (colSoftmax(A) @ v_q) + q' --------------------
// out[co][m] = gq[co] * (sum_n exp(A[n][m]-cmax[m]) * vq[co][n]) * cinv[m] + qt[co][m]
__global__ __launch_bounds__(256) void attn_q_kernel(float* __restrict__ Eq)
{
    const int b  = blockIdx.y;
    const int m0 = blockIdx.x * 64;
    const float* Ab = g_A  + (size_t)b*NPIX*NPIX;
    const float* vq = g_vq + (size_t)b*CC*NPIX;
    const float* qt = g_qt + (size_t)b*CC*NPIX;
    float* Eb = Eq + (size_t)b*CC*NPIX;
    __shared__ __align__(16) float As[16*132];
    __shared__ __align__(16) float Bs[16*64];
    __shared__ float cmax_s[64], cinv_s[64];
    const int tid = threadIdx.x;
    if (tid < 64) {
        cmax_s[tid] = g_cmax[b*NPIX + m0 + tid];
        cinv_s[tid] = g_cinv[b*NPIX + m0 + tid];
    }
    __syncthreads();
    const int tn = (tid & 15)*4, tm = (tid >> 4)*8;
    const int kc = tid & 15, orow = tid >> 4;
    const int pc = tid & 63, kr4 = tid >> 6;
    float acc[8][4] = {};
    for (int k0 = 0; k0 < NPIX; k0 += 16) {
#pragma unroll
        for (int ps = 0; ps < 8; ++ps) {
            int o = orow + ps*16;
            As[kc*132 + o] = vq[(size_t)o*NPIX + k0 + kc];
        }
#pragma unroll
        for (int ps = 0; ps < 4; ++ps) {
            int k = kr4 + ps*4;
            Bs[k*64 + pc] = __expf(Ab[(size_t)(k0+k)*NPIX + m0 + pc] - cmax_s[pc]);
        }
        __syncthreads();
        mma16<132,64>(As, Bs, tm, tn, acc);
        __syncthreads();
    }
#pragma unroll
    for (int i = 0; i < 8; ++i) {
        int o = tm + i;
        float gt = g_gq[b*CC + o];
        const float* qr = &qt[(size_t)o*NPIX + m0 + tn];
        float4 r;
        r.x = gt*acc[i][0]*cinv_s[tn+0] + qr[0];
        r.y = gt*acc[i][1]*cinv_s[tn+1] + qr[1];
        r.z = gt*acc[i][2]*cinv_s[tn+2] + qr[2];
        r.w = gt*acc[i][3]*cinv_s[tn+3] + qr[3];
        *(float4*)&Eb[(size_t)o*NPIX + m0 + tn] = r;
    }
}

// ---------------- 3x3 conv (implicit GEMM, K = 256*9 = 2304) + BN + ReLU -------
__global__ __launch_bounds__(256) void conv_kernel(
    const float* __restrict__ cw, const float* __restrict__ cg,
    const float* __restrict__ cb, const float* __restrict__ cm,
    const float* __restrict__ cv,
    const float* __restrict__ Eq, const float* __restrict__ Es,
    float* __restrict__ feat)
{
    const int b  = blockIdx.y;
    const int p0 = blockIdx.x * 64;
    const float* Eqb = Eq + (size_t)b*CC*NPIX;
    const float* Esb = Es + (size_t)b*CC*NPIX;
    float* fb = feat + (size_t)b*CC*NPIX;
    __shared__ __align__(16) float As[16*132];
    __shared__ __align__(16) float Bs[16*64];
    const int tid = threadIdx.x;
    const int tn = (tid & 15)*4, tm = (tid >> 4)*8;
    const int kc = tid & 15, orow = tid >> 4;
    const int pc = tid & 63, kr4 = tid >> 6;
    const int p = p0 + pc;
    const int hh = p / 48, ww = p - hh*48;
    float acc[8][4] = {};
    for (int k0 = 0; k0 < 2304; k0 += 16) {
#pragma unroll
        for (int ps = 0; ps < 8; ++ps) {
            int o = orow + ps*16;
            As[kc*132 + o] = cw[o*2304 + k0 + kc];
        }
#pragma unroll
        for (int ps = 0; ps < 4; ++ps) {
            int k   = kr4 + ps*4;
            int kap = k0 + k;
            int ic  = kap / 9;
            int kk  = kap - ic*9;
            int dh  = kk/3 - 1, dw = kk - (kk/3)*3 - 1;
            int ih  = hh + dh, iw = ww + dw;
            float val = 0.f;
            if ((unsigned)ih < 48u && (unsigned)iw < 48u) {
                const float* src = (ic < CC) ? Eqb : Esb;
                val = src[(size_t)(ic & (CC-1))*NPIX + ih*48 + iw];
            }
            Bs[k*64 + pc] = val;
        }
        __syncthreads();
        mma16<132,64>(As, Bs, tm, tn, acc);
        __syncthreads();
    }
#pragma unroll
    for (int i = 0; i < 8; ++i) {
        int o = tm + i;
        float sc  = cg[o] * rsqrtf(cv[o] + EPSB);
        float cbv = cb[o] - cm[o]*sc;
        float4 r;
        r.x = fmaxf(acc[i][0]*sc + cbv, 0.f);
        r.y = fmaxf(acc[i][1]*sc + cbv, 0.f);
        r.z = fmaxf(acc[i][2]*sc + cbv, 0.f);
        r.w = fmaxf(acc[i][3]*sc + cbv, 0.f);
        *(float4*)&fb[(size_t)o*NPIX + p0 + tn] = r;
    }
}

// ---------------- host ---------------------------------------------------------
extern "C" void kernel_launch(void* const* d_in, const int* in_sizes, int n_in,
                              void* d_out, int out_size)
{
    (void)in_sizes; (void)n_in; (void)out_size;
    const float* q    = (const float*)d_in[0];
    const float* s    = (const float*)d_in[1];
    const float* tsw  = (const float*)d_in[2];
    const float* tsb  = (const float*)d_in[3];
    const float* bsg  = (const float*)d_in[4];
    const float* bsb  = (const float*)d_in[5];
    const float* bsm  = (const float*)d_in[6];
    const float* bsv  = (const float*)d_in[7];
    const float* tqw  = (const float*)d_in[8];
    const float* tqb  = (const float*)d_in[9];
    const float* bqg  = (const float*)d_in[10];
    const float* bqb  = (const float*)d_in[11];
    const float* bqm  = (const float*)d_in[12];
    const float* bqv  = (const float*)d_in[13];
    const float* vqw  = (const float*)d_in[14];
    const float* vqb  = (const float*)d_in[15];
    const float* vsw  = (const float*)d_in[16];
    const float* vsb  = (const float*)d_in[17];
    const float* keyw = (const float*)d_in[18];
    const float* keyb = (const float*)d_in[19];
    const float* qryw = (const float*)d_in[20];
    const float* qryb = (const float*)d_in[21];
    const float* gw1  = (const float*)d_in[22];
    const float* gb1  = (const float*)d_in[23];
    const float* gw2  = (const float*)d_in[24];
    const float* gb2  = (const float*)d_in[25];
    const float* cw   = (const float*)d_in[26];
    const float* cg   = (const float*)d_in[27];
    const float* cb   = (const float*)d_in[28];
    const float* cm   = (const float*)d_in[29];
    const float* cv   = (const float*)d_in[30];

    float *p_qt, *p_st, *p_vq, *p_vs, *p_kx, *p_qx;
    cudaGetSymbolAddress((void**)&p_qt, g_qt);
    cudaGetSymbolAddress((void**)&p_st, g_st);
    cudaGetSymbolAddress((void**)&p_vq, g_vq);
    cudaGetSymbolAddress((void**)&p_vs, g_vs);
    cudaGetSymbolAddress((void**)&p_kx, g_kx);
    cudaGetSymbolAddress((void**)&p_qx, g_qx);

    float* feat = (float*)d_out;
    float* Eq   = feat + (size_t)BATCH*CC*NPIX;
    float* Es   = Eq   + (size_t)BATCH*CC*NPIX;

    dim3 g36(36, BATCH);

    // trans (1x1 conv + BN)
    gemm_wx<<<g36, 256>>>(q, tqw, tqb, bqg, bqb, bqm, bqv, p_qt, CIN);
    gemm_wx<<<g36, 256>>>(s, tsw, tsb, bsg, bsb, bsm, bsv, p_st, CIN);
    // projections (1x1 conv, no BN)
    gemm_wx<<<g36, 256>>>(p_qt, vqw,  vqb,  0, 0, 0, 0, p_vq, CC);
    gemm_wx<<<g36, 256>>>(p_qt, qryw, qryb, 0, 0, 0, 0, p_qx, CC);
    gemm_wx<<<g36, 256>>>(p_st, vsw,  vsb,  0, 0, 0, 0, p_vs, CC);
    gemm_wx<<<g36, 256>>>(p_st, keyw, keyb, 0, 0, 0, 0, p_kx, CC);
    // attention score A = kx^T @ qx
    score_kernel<<<dim3(36, 18, BATCH), 256>>>();
    // softmax statistics (rows over m; columns over n)
    row_stats_kernel<<<dim3(NPIX, BATCH), 256>>>();
    col_stats_kernel<<<dim3(9, BATCH), 256>>>();
    // channel gates (on q', s')
    gate_kernel<<<dim3(2, BATCH), 256>>>(gw1, gb1, gw2, gb2);
    // attention apply + gate + residual, written straight into d_out
    attn_s_kernel<<<g36, 256>>>(Es);
    attn_q_kernel<<<g36, 256>>>(Eq);
    // 3x3 conv on concat(E_q, E_s) + BN + ReLU
    conv_kernel<<<g36, 256>>>(cw, cg, cb, cm, cv, Eq, Es, feat);
}

// round 2
// speedup vs baseline: 1.4382x; 1.4382x over previous
#include <cuda_runtime.h>

#define BATCH 8
#define CIN   256
#define CC    128
#define NPIX  2304
#define EPSB  1e-5f

// ---------------- scratch ------------------------------------------------------
__device__ __align__(16) float g_qt[BATCH*CC*NPIX];
__device__ __align__(16) float g_st[BATCH*CC*NPIX];
__device__ __align__(16) float g_vq[BATCH*CC*NPIX];
__device__ __align__(16) float g_vs[BATCH*CC*NPIX];
__device__ __align__(16) float g_kx[BATCH*CC*NPIX];
__device__ __align__(16) float g_qx[BATCH*CC*NPIX];
__device__ __align__(16) float g_A[(size_t)BATCH*NPIX*NPIX];
__device__ float g_rmax[BATCH*NPIX];
__device__ float g_rinv[BATCH*NPIX];
__device__ float g_cmax[BATCH*NPIX];
__device__ float g_cinv[BATCH*NPIX];
__device__ float g_gq[BATCH*CC];
__device__ float g_gs[BATCH*CC];

// ---------------- tf32 helpers -------------------------------------------------
__device__ __forceinline__ float tf(float x) {
    unsigned u;
    asm("cvt.rna.tf32.f32 %0, %1;" : "=r"(u) : "f"(x));
    return __uint_as_float(u);
}
__device__ __forceinline__ float4 tf4(float4 v) {
    v.x = tf(v.x); v.y = tf(v.y); v.z = tf(v.z); v.w = tf(v.w); return v;
}

__device__ __forceinline__ void mma_tf32(float* c,
    unsigned a0, unsigned a1, unsigned a2, unsigned a3,
    unsigned b0, unsigned b1)
{
    asm volatile(
        "mma.sync.aligned.m16n8k8.row.col.f32.tf32.tf32.f32 "
        "{%0,%1,%2,%3}, {%4,%5,%6,%7}, {%8,%9}, {%0,%1,%2,%3};"
        : "+f"(c[0]), "+f"(c[1]), "+f"(c[2]), "+f"(c[3])
        : "r"(a0), "r"(a1), "r"(a2), "r"(a3), "r"(b0), "r"(b1));
}

// block: 256 thr = 8 warps as 2(M) x 4(N); block tile 128(M) x 64(N) x 16(K)
// warp tile 64(M) x 16(N): 4 m-frags x 2 n-frags of m16n8k8.
// AKM: A stored [k][m] (stride AS); else [m][k]. BKN: B stored [k][n]; else [n][k].
template<int AS, bool AKM, int BS, bool BKN>
__device__ __forceinline__ void mma_k16(float acc[4][2][4],
    const float* As, const float* Bs, int warp_m, int warp_n, int lane)
{
    const int gid = lane >> 2, t4 = lane & 3;
#pragma unroll
    for (int ko = 0; ko < 16; ko += 8) {
        unsigned a[4][4];
#pragma unroll
        for (int mf = 0; mf < 4; ++mf) {
            int rb = warp_m*64 + mf*16 + gid;
            if (AKM) {
                a[mf][0] = __float_as_uint(As[(ko+t4  )*AS + rb  ]);
                a[mf][1] = __float_as_uint(As[(ko+t4  )*AS + rb+8]);
                a[mf][2] = __float_as_uint(As[(ko+t4+4)*AS + rb  ]);
                a[mf][3] = __float_as_uint(As[(ko+t4+4)*AS + rb+8]);
            } else {
                a[mf][0] = __float_as_uint(As[(rb  )*AS + ko+t4  ]);
                a[mf][1] = __float_as_uint(As[(rb+8)*AS + ko+t4  ]);
                a[mf][2] = __float_as_uint(As[(rb  )*AS + ko+t4+4]);
                a[mf][3] = __float_as_uint(As[(rb+8)*AS + ko+t4+4]);
            }
        }
        unsigned bf[2][2];
#pragma unroll
        for (int nf = 0; nf < 2; ++nf) {
            int nb = warp_n*16 + nf*8 + gid;
            if (BKN) {
                bf[nf][0] = __float_as_uint(Bs[(ko+t4  )*BS + nb]);
                bf[nf][1] = __float_as_uint(Bs[(ko+t4+4)*BS + nb]);
            } else {
                bf[nf][0] = __float_as_uint(Bs[nb*BS + ko+t4  ]);
                bf[nf][1] = __float_as_uint(Bs[nb*BS + ko+t4+4]);
            }
        }
#pragma unroll
        for (int mf = 0; mf < 4; ++mf)
#pragma unroll
            for (int nf = 0; nf < 2; ++nf)
                mma_tf32(acc[mf][nf], a[mf][0], a[mf][1], a[mf][2], a[mf][3],
                         bf[nf][0], bf[nf][1]);
    }
}

// ---------------- 1x1 conv GEMM (tensor): out[o][p] = sum_k w[o][k] x[k][p] ----
__global__ __launch_bounds__(256) void gemm_wx_t(
    const float* __restrict__ x, const float* __restrict__ w,
    const float* __restrict__ bias,
    const float* __restrict__ bng, const float* __restrict__ bnb,
    const float* __restrict__ bnm, const float* __restrict__ bnv,
    float* __restrict__ out, int K)
{
    const int b  = blockIdx.y;
    const int p0 = blockIdx.x * 64;
    const float* xb = x + (size_t)b*K*NPIX;
    float* ob = out + (size_t)b*CC*NPIX;
    __shared__ __align__(16) float As[128*20];   // w tile [o][k16]
    __shared__ __align__(16) float Bs[16*72];    // x tile [k16][p]
    const int tid = threadIdx.x, lane = tid & 31, wid = tid >> 5;
    const int warp_m = wid & 1, warp_n = wid >> 1;
    const int gid = lane >> 2, t4 = lane & 3;
    float acc[4][2][4] = {};
    float4 ra[2], rb;
    const int ar0 = (2*tid) >> 2,  aq0 = (2*tid) & 3;
    const int ar1 = (2*tid+1) >> 2, aq1 = (2*tid+1) & 3;
    const int bk = tid >> 4, bq = tid & 15;
    // prefetch k0 = 0
    ra[0] = *(const float4*)&w[ar0*K + aq0*4];
    ra[1] = *(const float4*)&w[ar1*K + aq1*4];
    rb    = *(const float4*)&xb[(size_t)bk*NPIX + p0 + bq*4];
    for (int k0 = 0; k0 < K; k0 += 16) {
        *(float4*)&As[ar0*20 + aq0*4] = tf4(ra[0]);
        *(float4*)&As[ar1*20 + aq1*4] = tf4(ra[1]);
        *(float4*)&Bs[bk*72 + bq*4]   = tf4(rb);
        __syncthreads();
        if (k0 + 16 < K) {
            ra[0] = *(const float4*)&w[ar0*K + k0+16 + aq0*4];
            ra[1] = *(const float4*)&w[ar1*K + k0+16 + aq1*4];
            rb    = *(const float4*)&xb[(size_t)(k0+16+bk)*NPIX + p0 + bq*4];
        }
        mma_k16<20,false,72,true>(acc, As, Bs, warp_m, warp_n, lane);
        __syncthreads();
    }
#pragma unroll
    for (int mf = 0; mf < 4; ++mf) {
#pragma unroll
        for (int h = 0; h < 2; ++h) {
            int o = warp_m*64 + mf*16 + gid + h*8;
            float sc = 1.0f, cb = bias[o];
            if (bng) {
                sc = bng[o] * rsqrtf(bnv[o] + EPSB);
                cb = (bias[o] - bnm[o]) * sc + bnb[o];
            }
#pragma unroll
            for (int nf = 0; nf < 2; ++nf) {
                int col = warp_n*16 + nf*8 + t4*2;
                float2 r;
                r.x = acc[mf][nf][2*h+0]*sc + cb;
                r.y = acc[mf][nf][2*h+1]*sc + cb;
                *(float2*)&ob[(size_t)o*NPIX + p0 + col] = r;
            }
        }
    }
}

// ---------------- score (tensor): A[n][m] = sum_c kx[c][n] qx[c][m] ------------
__global__ __launch_bounds__(256) void score_t()
{
    const int b  = blockIdx.z;
    const int n0 = blockIdx.y * 128;
    const int m0 = blockIdx.x * 64;
    const float* kx = g_kx + (size_t)b*CC*NPIX;
    const float* qx = g_qx + (size_t)b*CC*NPIX;
    float* Ab = g_A + (size_t)b*NPIX*NPIX;
    __shared__ __align__(16) float As[16*136];  // kx tile [k16][n128]
    __shared__ __align__(16) float Bs[16*72];   // qx tile [k16][m64]
    const int tid = threadIdx.x, lane = tid & 31, wid = tid >> 5;
    const int warp_m = wid & 1, warp_n = wid >> 1;
    const int gid = lane >> 2, t4 = lane & 3;
    float acc[4][2][4] = {};
    float4 ra[2], rb;
    const int ak0 = (2*tid) >> 5,   aq0 = (2*tid) & 31;
    const int ak1 = (2*tid+1) >> 5, aq1 = (2*tid+1) & 31;
    const int bk = tid >> 4, bq = tid & 15;
    ra[0] = *(const float4*)&kx[(size_t)ak0*NPIX + n0 + aq0*4];
    ra[1] = *(const float4*)&kx[(size_t)ak1*NPIX + n0 + aq1*4];
    rb    = *(const float4*)&qx[(size_t)bk*NPIX + m0 + bq*4];
    for (int k0 = 0; k0 < CC; k0 += 16) {
        *(float4*)&As[ak0*136 + aq0*4] = tf4(ra[0]);
        *(float4*)&As[ak1*136 + aq1*4] = tf4(ra[1]);
        *(float4*)&Bs[bk*72 + bq*4]    = tf4(rb);
        __syncthreads();
        if (k0 + 16 < CC) {
            ra[0] = *(const float4*)&kx[(size_t)(k0+16+ak0)*NPIX + n0 + aq0*4];
            ra[1] = *(const float4*)&kx[(size_t)(k0+16+ak1)*NPIX + n0 + aq1*4];
            rb    = *(const float4*)&qx[(size_t)(k0+16+bk)*NPIX + m0 + bq*4];
        }
        mma_k16<136,true,72,true>(acc, As, Bs, warp_m, warp_n, lane);
        __syncthreads();
    }
#pragma unroll
    for (int mf = 0; mf < 4; ++mf)
#pragma unroll
        for (int h = 0; h < 2; ++h) {
            int n = n0 + warp_m*64 + mf*16 + gid + h*8;
#pragma unroll
            for (int nf = 0; nf < 2; ++nf) {
                int col = warp_n*16 + nf*8 + t4*2;
                float2 r; r.x = acc[mf][nf][2*h+0]; r.y = acc[mf][nf][2*h+1];
                *(float2*)&Ab[(size_t)n*NPIX + m0 + col] = r;
            }
        }
}

// ---------------- row softmax stats --------------------------------------------
__global__ __launch_bounds__(256) void row_stats_kernel()
{
    const int n = blockIdx.x, b = blockIdx.y;
    const float* row = g_A + ((size_t)b*NPIX + n)*NPIX;
    const int tid = threadIdx.x;
    float v[9];
    float mx = -1e30f;
#pragma unroll
    for (int i = 0; i < 9; ++i) { v[i] = row[tid + i*256]; mx = fmaxf(mx, v[i]); }
    __shared__ float s1[8], s2[8];
#pragma unroll
    for (int o = 16; o; o >>= 1) mx = fmaxf(mx, __shfl_xor_sync(~0u, mx, o));
    if ((tid & 31) == 0) s1[tid >> 5] = mx;
    __syncthreads();
    mx = s1[0];
#pragma unroll
    for (int j = 1; j < 8; ++j) mx = fmaxf(mx, s1[j]);
    float s = 0.f;
#pragma unroll
    for (int i = 0; i < 9; ++i) s += __expf(v[i] - mx);
#pragma unroll
    for (int o = 16; o; o >>= 1) s += __shfl_xor_sync(~0u, s, o);
    if ((tid & 31) == 0) s2[tid >> 5] = s;
    __syncthreads();
    if (tid == 0) {
        float t = 0.f;
#pragma unroll
        for (int j = 0; j < 8; ++j) t += s2[j];
        g_rmax[b*NPIX + n] = mx;
        g_rinv[b*NPIX + n] = 1.0f / t;
    }
}

// ---------------- column softmax stats -----------------------------------------
__global__ __launch_bounds__(256) void col_stats_kernel()
{
    const int m = blockIdx.x * 256 + threadIdx.x;
    const int b = blockIdx.y;
    const float* Ab = g_A + (size_t)b*NPIX*NPIX;
    float mx = -1e30f, s = 0.f;
    for (int n = 0; n < NPIX; ++n) {
        float x = Ab[(size_t)n*NPIX + m];
        if (x <= mx) s += __expf(x - mx);
        else { s = s * __expf(mx - x) + 1.0f; mx = x; }
    }
    g_cmax[b*NPIX + m] = mx;
    g_cinv[b*NPIX + m] = 1.0f / s;
}

// ---------------- channel gate -------------------------------------------------
__global__ __launch_bounds__(256) void gate_kernel(
    const float* __restrict__ w1, const float* __restrict__ b1,
    const float* __restrict__ w2, const float* __restrict__ b2)
{
    const int b = blockIdx.y;
    const float* t = (blockIdx.x == 0 ? g_qt : g_st) + (size_t)b*CC*NPIX;
    float* go = (blockIdx.x == 0 ? g_gq : g_gs) + b*CC;
    __shared__ float pool[CC];
    __shared__ float hsh[8];
    const int tid = threadIdx.x, lane = tid & 31, wid = tid >> 5;
    for (int ch = wid; ch < CC; ch += 8) {
        const float* row = t + (size_t)ch*NPIX;
        float s = 0.f;
        for (int i = lane; i < NPIX; i += 32) s += row[i];
#pragma unroll
        for (int o = 16; o; o >>= 1) s += __shfl_xor_sync(~0u, s, o);
        if (lane == 0) pool[ch] = s * (1.0f/NPIX);
    }
    __syncthreads();
    if (tid < 8) {
        float h = b1[tid];
        for (int i = 0; i < CC; ++i) h += pool[i] * w1[tid*CC + i];
        hsh[tid] = fmaxf(h, 0.f);
    }
    __syncthreads();
    if (tid < CC) {
        float z = b2[tid];
#pragma unroll
        for (int j = 0; j < 8; ++j) z += hsh[j] * w2[tid*8 + j];
        go[tid] = 1.0f / (1.0f + __expf(-z));
    }
}

// ---------------- E_s (tensor): M = n pixels, N = co channels, K = m -----------
// out[co][n] = gs[co] * (sum_m exp(A[n][m]-rmax[n]) * vs[co][m]) * rinv[n] + st[co][n]
__global__ __launch_bounds__(256) void attn_s_t(float* __restrict__ Es)
{
    const int b   = blockIdx.z;
    const int n0  = blockIdx.x * 128;
    const int co0 = blockIdx.y * 64;
    const float* Ab = g_A  + (size_t)b*NPIX*NPIX;
    const float* vs = g_vs + (size_t)b*CC*NPIX;
    const float* st = g_st + (size_t)b*CC*NPIX;
    const float* gt = g_gs + b*CC;
    float* Eb = Es + (size_t)b*CC*NPIX;
    __shared__ __align__(16) float As[128*20];  // exp(A) tile [n128][k16]
    __shared__ __align__(16) float Bs[64*20];   // vs tile [co64][k16]
    __shared__ float rmax_s[128], rinv_s[128];
    const int tid = threadIdx.x, lane = tid & 31, wid = tid >> 5;
    const int warp_m = wid & 1, warp_n = wid >> 1;
    const int gid = lane >> 2, t4 = lane & 3;
    if (tid < 128) {
        rmax_s[tid] = g_rmax[b*NPIX + n0 + tid];
        rinv_s[tid] = g_rinv[b*NPIX + n0 + tid];
    }
    __syncthreads();
    float acc[4][2][4] = {};
    float4 ra[2], rb;
    const int ar0 = (2*tid) >> 2,  aq0 = (2*tid) & 3;
    const int ar1 = (2*tid+1) >> 2, aq1 = (2*tid+1) & 3;
    const int br = tid >> 2, bq = tid & 3;
    float rm0 = rmax_s[ar0], rm1 = rmax_s[ar1];
    {
        float4 v0 = *(const float4*)&Ab[(size_t)(n0+ar0)*NPIX + aq0*4];
        float4 v1 = *(const float4*)&Ab[(size_t)(n0+ar1)*NPIX + aq1*4];
        ra[0].x = __expf(v0.x-rm0); ra[0].y = __expf(v0.y-rm0);
        ra[0].z = __expf(v0.z-rm0); ra[0].w = __expf(v0.w-rm0);
        ra[1].x = __expf(v1.x-rm1); ra[1].y = __expf(v1.y-rm1);
        ra[1].z = __expf(v1.z-rm1); ra[1].w = __expf(v1.w-rm1);
        rb = *(const float4*)&vs[(size_t)(co0+br)*NPIX + bq*4];
    }
    for (int k0 = 0; k0 < NPIX; k0 += 16) {
        *(float4*)&As[ar0*20 + aq0*4] = tf4(ra[0]);
        *(float4*)&As[ar1*20 + aq1*4] = tf4(ra[1]);
        *(float4*)&Bs[br*20 + bq*4]   = tf4(rb);
        __syncthreads();
        if (k0 + 16 < NPIX) {
            float4 v0 = *(const float4*)&Ab[(size_t)(n0+ar0)*NPIX + k0+16 + aq0*4];
            float4 v1 = *(const float4*)&Ab[(size_t)(n0+ar1)*NPIX + k0+16 + aq1*4];
            ra[0].x = __expf(v0.x-rm0); ra[0].y = __expf(v0.y-rm0);
            ra[0].z = __expf(v0.z-rm0); ra[0].w = __expf(v0.w-rm0);
            ra[1].x = __expf(v1.x-rm1); ra[1].y = __expf(v1.y-rm1);
            ra[1].z = __expf(v1.z-rm1); ra[1].w = __expf(v1.w-rm1);
            rb = *(const float4*)&vs[(size_t)(co0+br)*NPIX + k0+16 + bq*4];
        }
        mma_k16<20,false,20,false>(acc, As, Bs, warp_m, warp_n, lane);
        __syncthreads();
    }
#pragma unroll
    for (int mf = 0; mf < 4; ++mf)
#pragma unroll
        for (int nf = 0; nf < 2; ++nf) {
            int nl  = warp_m*64 + mf*16 + gid;
            int col = warp_n*16 + nf*8 + t4*2;
            int co  = co0 + col;
            float g0 = gt[co], g1 = gt[co+1];
#pragma unroll
            for (int h = 0; h < 2; ++h) {
                int nn = nl + h*8;
                float ri = rinv_s[nn];
                Eb[(size_t)co*NPIX + n0 + nn] =
                    g0*acc[mf][nf][2*h+0]*ri + st[(size_t)co*NPIX + n0 + nn];
                Eb[(size_t)(co+1)*NPIX + n0 + nn] =
                    g1*acc[mf][nf][2*h+1]*ri + st[(size_t)(co+1)*NPIX + n0 + nn];
            }
        }
}

// ---------------- E_q (tensor): M = co channels, N = m pixels, K = n -----------
// out[co][m] = gq[co] * (sum_n exp(A[n][m]-cmax[m]) * vq[co][n]) * cinv[m] + qt[co][m]
__global__ __launch_bounds__(256) void attn_q_t(float* __restrict__ Eq)
{
    const int b  = blockIdx.y;
    const int m0 = blockIdx.x * 64;
    const float* Ab = g_A  + (size_t)b*NPIX*NPIX;
    const float* vq = g_vq + (size_t)b*CC*NPIX;
    const float* qt = g_qt + (size_t)b*CC*NPIX;
    const float* gt = g_gq + b*CC;
    float* Eb = Eq + (size_t)b*CC*NPIX;
    __shared__ __align__(16) float As[128*20];  // vq tile [co128][k16]
    __shared__ __align__(16) float Bs[16*72];   // exp(A) tile [k16][m64]
    __shared__ float cmax_s[64], cinv_s[64];
    const int tid = threadIdx.x, lane = tid & 31, wid = tid >> 5;
    const int warp_m = wid & 1, warp_n = wid >> 1;
    const int gid = lane >> 2, t4 = lane & 3;
    if (tid < 64) {
        cmax_s[tid] = g_cmax[b*NPIX + m0 + tid];
        cinv_s[tid] = g_cinv[b*NPIX + m0 + tid];
    }
    __syncthreads();
    float acc[4][2][4] = {};
    float4 ra[2], rb;
    const int ar0 = (2*tid) >> 2,  aq0 = (2*tid) & 3;
    const int ar1 = (2*tid+1) >> 2, aq1 = (2*tid+1) & 3;
    const int bk = tid >> 4, bq = tid & 15;
    float cm0 = cmax_s[bq*4+0], cm1 = cmax_s[bq*4+1];
    float cm2 = cmax_s[bq*4+2], cm3 = cmax_s[bq*4+3];
    {
        ra[0] = *(const float4*)&vq[(size_t)ar0*NPIX + aq0*4];
        ra[1] = *(const float4*)&vq[(size_t)ar1*NPIX + aq1*4];
        float4 v = *(const float4*)&Ab[(size_t)bk*NPIX + m0 + bq*4];
        rb.x = __expf(v.x-cm0); rb.y = __expf(v.y-cm1);
        rb.z = __expf(v.z-cm2); rb.w = __expf(v.w-cm3);
    }
    for (int k0 = 0; k0 < NPIX; k0 += 16) {
        *(float4*)&As[ar0*20 + aq0*4] = tf4(ra[0]);
        *(float4*)&As[ar1*20 + aq1*4] = tf4(ra[1]);
        *(float4*)&Bs[bk*72 + bq*4]   = tf4(rb);
        __syncthreads();
        if (k0 + 16 < NPIX) {
            ra[0] = *(const float4*)&vq[(size_t)ar0*NPIX + k0+16 + aq0*4];
            ra[1] = *(const float4*)&vq[(size_t)ar1*NPIX + k0+16 + aq1*4];
            float4 v = *(const float4*)&Ab[(size_t)(k0+16+bk)*NPIX + m0 + bq*4];
            rb.x = __expf(v.x-cm0); rb.y = __expf(v.y-cm1);
            rb.z = __expf(v.z-cm2); rb.w = __expf(v.w-cm3);
        }
        mma_k16<20,false,72,true>(acc, As, Bs, warp_m, warp_n, lane);
        __syncthreads();
    }
#pragma unroll
    for (int mf = 0; mf < 4; ++mf)
#pragma unroll
        for (int h = 0; h < 2; ++h) {
            int co = warp_m*64 + mf*16 + gid + h*8;
            float g = gt[co];
#pragma unroll
            for (int nf = 0; nf < 2; ++nf) {
                int col = warp_n*16 + nf*8 + t4*2;
                float2 res = *(const float2*)&qt[(size_t)co*NPIX + m0 + col];
                float2 r;
                r.x = g*acc[mf][nf][2*h+0]*cinv_s[col]   + res.x;
                r.y = g*acc[mf][nf][2*h+1]*cinv_s[col+1] + res.y;
                *(float2*)&Eb[(size_t)co*NPIX + m0 + col] = r;
            }
        }
}

// ---------------- 3x3 conv (tensor implicit GEMM) + BN + ReLU ------------------
__global__ __launch_bounds__(256) void conv_t(
    const float* __restrict__ cw, const float* __restrict__ cg,
    const float* __restrict__ cb, const float* __restrict__ cm,
    const float* __restrict__ cv,
    const float* __restrict__ Eq, const float* __restrict__ Es,
    float* __restrict__ feat)
{
    const int b  = blockIdx.y;
    const int p0 = blockIdx.x * 64;
    const float* Eqb = Eq + (size_t)b*CC*NPIX;
    const float* Esb = Es + (size_t)b*CC*NPIX;
    float* fb = feat + (size_t)b*CC*NPIX;
    __shared__ __align__(16) float As[128*20];  // cw tile [o][k16]
    __shared__ __align__(16) float Bs[16*72];   // im2col tile [k16][p64]
    const int tid = threadIdx.x, lane = tid & 31, wid = tid >> 5;
    const int warp_m = wid & 1, warp_n = wid >> 1;
    const int gid = lane >> 2, t4 = lane & 3;
    float acc[4][2][4] = {};
    float4 ra[2];
    float rb[4];
    const int ar0 = (2*tid) >> 2,  aq0 = (2*tid) & 3;
    const int ar1 = (2*tid+1) >> 2, aq1 = (2*tid+1) & 3;
    const int bk = tid >> 4, bq = tid & 15;
    int hh[4], ww[4];
#pragma unroll
    for (int j = 0; j < 4; ++j) {
        int p = p0 + bq*4 + j;
        hh[j] = p / 48; ww[j] = p - hh[j]*48;
    }
    auto loadB = [&](int k0) {
        int kap = k0 + bk;
        int ic = kap / 9, kk = kap - ic*9;
        int dh = kk/3 - 1, dw = kk - (kk/3)*3 - 1;
        const float* src = (ic < CC) ? Eqb : Esb;
        int icl = ic & (CC-1);
#pragma unroll
        for (int j = 0; j < 4; ++j) {
            int ih = hh[j] + dh, iw = ww[j] + dw;
            rb[j] = ((unsigned)ih < 48u && (unsigned)iw < 48u)
                  ? src[(size_t)icl*NPIX + ih*48 + iw] : 0.f;
        }
    };
    ra[0] = *(const float4*)&cw[ar0*2304 + aq0*4];
    ra[1] = *(const float4*)&cw[ar1*2304 + aq1*4];
    loadB(0);
    for (int k0 = 0; k0 < 2304; k0 += 16) {
        *(float4*)&As[ar0*20 + aq0*4] = tf4(ra[0]);
        *(float4*)&As[ar1*20 + aq1*4] = tf4(ra[1]);
        Bs[bk*72 + bq*4+0] = tf(rb[0]);
        Bs[bk*72 + bq*4+1] = tf(rb[1]);
        Bs[bk*72 + bq*4+2] = tf(rb[2]);
        Bs[bk*72 + bq*4+3] = tf(rb[3]);
        __syncthreads();
        if (k0 + 16 < 2304) {
            ra[0] = *(const float4*)&cw[ar0*2304 + k0+16 + aq0*4];
            ra[1] = *(const float4*)&cw[ar1*2304 + k0+16 + aq1*4];
            loadB(k0 + 16);
        }
        mma_k16<20,false,72,true>(acc, As, Bs, warp_m, warp_n, lane);
        __syncthreads();
    }
#pragma unroll
    for (int mf = 0; mf < 4; ++mf)
#pragma unroll
        for (int h = 0; h < 2; ++h) {
            int o = warp_m*64 + mf*16 + gid + h*8;
            float sc  = cg[o] * rsqrtf(cv[o] + EPSB);
            float cbv = cb[o] - cm[o]*sc;
#pragma unroll
            for (int nf = 0; nf < 2; ++nf) {
                int col = warp_n*16 + nf*8 + t4*2;
                float2 r;
                r.x = fmaxf(acc[mf][nf][2*h+0]*sc + cbv, 0.f);
                r.y = fmaxf(acc[mf][nf][2*h+1]*sc + cbv, 0.f);
                *(float2*)&fb[(size_t)o*NPIX + p0 + col] = r;
            }
        }
}

// ---------------- host ---------------------------------------------------------
extern "C" void kernel_launch(void* const* d_in, const int* in_sizes, int n_in,
                              void* d_out, int out_size)
{
    (void)in_sizes; (void)n_in; (void)out_size;
    const float* q    = (const float*)d_in[0];
    const float* s    = (const float*)d_in[1];
    const float* tsw  = (const float*)d_in[2];
    const float* tsb  = (const float*)d_in[3];
    const float* bsg  = (const float*)d_in[4];
    const float* bsb  = (const float*)d_in[5];
    const float* bsm  = (const float*)d_in[6];
    const float* bsv  = (const float*)d_in[7];
    const float* tqw  = (const float*)d_in[8];
    const float* tqb  = (const float*)d_in[9];
    const float* bqg  = (const float*)d_in[10];
    const float* bqb  = (const float*)d_in[11];
    const float* bqm  = (const float*)d_in[12];
    const float* bqv  = (const float*)d_in[13];
    const float* vqw  = (const float*)d_in[14];
    const float* vqb  = (const float*)d_in[15];
    const float* vsw  = (const float*)d_in[16];
    const float* vsb  = (const float*)d_in[17];
    const float* keyw = (const float*)d_in[18];
    const float* keyb = (const float*)d_in[19];
    const float* qryw = (const float*)d_in[20];
    const float* qryb = (const float*)d_in[21];
    const float* gw1  = (const float*)d_in[22];
    const float* gb1  = (const float*)d_in[23];
    const float* gw2  = (const float*)d_in[24];
    const float* gb2  = (const float*)d_in[25];
    const float* cw   = (const float*)d_in[26];
    const float* cg   = (const float*)d_in[27];
    const float* cb   = (const float*)d_in[28];
    const float* cm   = (const float*)d_in[29];
    const float* cv   = (const float*)d_in[30];

    float *p_qt, *p_st, *p_vq, *p_vs, *p_kx, *p_qx;
    cudaGetSymbolAddress((void**)&p_qt, g_qt);
    cudaGetSymbolAddress((void**)&p_st, g_st);
    cudaGetSymbolAddress((void**)&p_vq, g_vq);
    cudaGetSymbolAddress((void**)&p_vs, g_vs);
    cudaGetSymbolAddress((void**)&p_kx, g_kx);
    cudaGetSymbolAddress((void**)&p_qx, g_qx);

    float* feat = (float*)d_out;
    float* Eq   = feat + (size_t)BATCH*CC*NPIX;
    float* Es   = Eq   + (size_t)BATCH*CC*NPIX;

    dim3 g36(36, BATCH);

    gemm_wx_t<<<g36, 256>>>(q, tqw, tqb, bqg, bqb, bqm, bqv, p_qt, CIN);
    gemm_wx_t<<<g36, 256>>>(s, tsw, tsb, bsg, bsb, bsm, bsv, p_st, CIN);
    gemm_wx_t<<<g36, 256>>>(p_qt, vqw,  vqb,  0, 0, 0, 0, p_vq, CC);
    gemm_wx_t<<<g36, 256>>>(p_qt, qryw, qryb, 0, 0, 0, 0, p_qx, CC);
    gemm_wx_t<<<g36, 256>>>(p_st, vsw,  vsb,  0, 0, 0, 0, p_vs, CC);
    gemm_wx_t<<<g36, 256>>>(p_st, keyw, keyb, 0, 0, 0, 0, p_kx, CC);

    score_t<<<dim3(36, 18, BATCH), 256>>>();

    row_stats_kernel<<<dim3(NPIX, BATCH), 256>>>();
    col_stats_kernel<<<dim3(9, BATCH), 256>>>();
    gate_kernel<<<dim3(2, BATCH), 256>>>(gw1, gb1, gw2, gb2);

    attn_s_t<<<dim3(18, 2, BATCH), 256>>>(Es);
    attn_q_t<<<g36, 256>>>(Eq);

    conv_t<<<g36, 256>>>(cw, cg, cb, cm, cv, Eq, Es, feat);
}

// round 3
// speedup vs baseline: 1.8604x; 1.2936x over previous
#include <cuda_runtime.h>

#define BATCH 8
#define CIN   256
#define CC    128
#define NPIX  2304
#define EPSB  1e-5f

// ---------------- scratch ------------------------------------------------------
__device__ __align__(16) float g_qt[BATCH*CC*NPIX];
__device__ __align__(16) float g_st[BATCH*CC*NPIX];
__device__ __align__(16) float g_vq[BATCH*CC*NPIX];
__device__ __align__(16) float g_vs[BATCH*CC*NPIX];
__device__ __align__(16) float g_kx[BATCH*CC*NPIX];
__device__ __align__(16) float g_qx[BATCH*CC*NPIX];
__device__ __align__(16) float g_A[(size_t)BATCH*NPIX*NPIX];
__device__ unsigned g_bmaxk[BATCH];     // per-batch max of A, monotone-key encoded
__device__ float g_gq[BATCH*CC];
__device__ float g_gs[BATCH*CC];

// ---------------- tf32 + maxkey helpers ----------------------------------------
__device__ __forceinline__ float tf(float x) {
    unsigned u;
    asm("cvt.rna.tf32.f32 %0, %1;" : "=r"(u) : "f"(x));
    return __uint_as_float(u);
}
__device__ __forceinline__ float4 tf4(float4 v) {
    v.x = tf(v.x); v.y = tf(v.y); v.z = tf(v.z); v.w = tf(v.w); return v;
}
__device__ __forceinline__ unsigned fkey(float x) {
    int i = __float_as_int(x);
    return (i >= 0) ? ((unsigned)i | 0x80000000u) : ~(unsigned)i;
}
__device__ __forceinline__ float fdekey(unsigned u) {
    int i = (u & 0x80000000u) ? (int)(u & 0x7fffffffu) : ~(int)u;
    return __int_as_float(i);
}

__device__ __forceinline__ void mma_tf32(float* c,
    unsigned a0, unsigned a1, unsigned a2, unsigned a3,
    unsigned b0, unsigned b1)
{
    asm volatile(
        "mma.sync.aligned.m16n8k8.row.col.f32.tf32.tf32.f32 "
        "{%0,%1,%2,%3}, {%4,%5,%6,%7}, {%8,%9}, {%0,%1,%2,%3};"
        : "+f"(c[0]), "+f"(c[1]), "+f"(c[2]), "+f"(c[3])
        : "r"(a0), "r"(a1), "r"(a2), "r"(a3), "r"(b0), "r"(b1));
}

// Block: 256 thr = 8 warps (wm=wid&1, wn=wid>>1). Block tile 128(M) x 64(N) x 16(K).
// Warp tile 64(M) x 16(N): 4 m-frags x 2 n-frags.
//
// A in "crosswise" smem: element (m,k) at As[m*20 + (k&3)*4 + (k>>2)], so one
// LDS.128 at As4[m*5 + t4] yields k = {t4, t4+4, t4+8, t4+12} for row m.
// B in [k16][BS] (n-fast), conflict-free scalar fragment reads.
template<int BS>
__device__ __forceinline__ void mma_cross(float acc[4][2][4],
    const float* As, const float* Bs, int wm, int wn, int lane)
{
    const int gid = lane >> 2, t4 = lane & 3;
    const float4* As4 = (const float4*)As;
    float4 va[4][2];
#pragma unroll
    for (int mf = 0; mf < 4; ++mf) {
        int rb = wm*64 + mf*16 + gid;
        va[mf][0] = As4[rb*5 + t4];
        va[mf][1] = As4[(rb+8)*5 + t4];
    }
#pragma unroll
    for (int ko = 0; ko < 2; ++ko) {
        unsigned bf[2][2];
#pragma unroll
        for (int nf = 0; nf < 2; ++nf) {
            int nb = wn*16 + nf*8 + gid;
            bf[nf][0] = __float_as_uint(Bs[(ko*8+t4  )*BS + nb]);
            bf[nf][1] = __float_as_uint(Bs[(ko*8+t4+4)*BS + nb]);
        }
#pragma unroll
        for (int mf = 0; mf < 4; ++mf) {
            unsigned a0, a1, a2, a3;
            if (ko == 0) {
                a0 = __float_as_uint(va[mf][0].x); a1 = __float_as_uint(va[mf][1].x);
                a2 = __float_as_uint(va[mf][0].y); a3 = __float_as_uint(va[mf][1].y);
            } else {
                a0 = __float_as_uint(va[mf][0].z); a1 = __float_as_uint(va[mf][1].z);
                a2 = __float_as_uint(va[mf][0].w); a3 = __float_as_uint(va[mf][1].w);
            }
#pragma unroll
            for (int nf = 0; nf < 2; ++nf)
                mma_tf32(acc[mf][nf], a0, a1, a2, a3, bf[nf][0], bf[nf][1]);
        }
    }
}

// store one k-quad (k = aq*4 .. aq*4+3 within the k16 window) of row m, crosswise
__device__ __forceinline__ void stA(float* As, int m, int aq, float4 v) {
    float* p = &As[m*20 + aq];
    p[0] = tf(v.x); p[4] = tf(v.y); p[8] = tf(v.z); p[12] = tf(v.w);
}

// ---------------- init ----------------------------------------------------------
__global__ void init_bmax() { if (threadIdx.x < BATCH) g_bmaxk[threadIdx.x] = 0u; }

// ---------------- 1x1 conv GEMM: out[o][p] = sum_k w[o][k] x[k][p] (+BN) --------
__global__ __launch_bounds__(256, 2) void gemm_wx_t(
    const float* __restrict__ x, const float* __restrict__ w,
    const float* __restrict__ bias,
    const float* __restrict__ bng, const float* __restrict__ bnb,
    const float* __restrict__ bnm, const float* __restrict__ bnv,
    float* __restrict__ out, int K)
{
    const int b  = blockIdx.y;
    const int p0 = blockIdx.x * 64;
    const float* xb = x + (size_t)b*K*NPIX;
    float* ob = out + (size_t)b*CC*NPIX;
    __shared__ __align__(16) float As[2][128*20];
    __shared__ __align__(16) float Bs[2][16*68];
    const int tid = threadIdx.x, lane = tid & 31, wid = tid >> 5;
    const int wm = wid & 1, wn = wid >> 1;
    const int gid = lane >> 2, t4 = lane & 3;
    const int am = tid >> 1, aq0 = 2*(tid & 1), aq1 = aq0 + 1;
    const int bk = tid >> 4, bq = tid & 15;
    float acc[4][2][4] = {};
    float4 pa0, pa1, pb;
    pa0 = *(const float4*)&w[am*K + aq0*4];
    pa1 = *(const float4*)&w[am*K + aq1*4];
    pb  = *(const float4*)&xb[(size_t)bk*NPIX + p0 + bq*4];
    stA(As[0], am, aq0, pa0); stA(As[0], am, aq1, pa1);
    *(float4*)&Bs[0][bk*68 + bq*4] = tf4(pb);
    __syncthreads();
    const int iters = K / 16;
    for (int it = 0; it < iters; ++it) {
        if (it + 1 < iters) {
            int k0 = (it+1)*16;
            pa0 = *(const float4*)&w[am*K + k0 + aq0*4];
            pa1 = *(const float4*)&w[am*K + k0 + aq1*4];
            pb  = *(const float4*)&xb[(size_t)(k0+bk)*NPIX + p0 + bq*4];
        }
        mma_cross<68>(acc, As[it & 1], Bs[it & 1], wm, wn, lane);
        if (it + 1 < iters) {
            int nb = (it+1) & 1;
            stA(As[nb], am, aq0, pa0); stA(As[nb], am, aq1, pa1);
            *(float4*)&Bs[nb][bk*68 + bq*4] = tf4(pb);
        }
        __syncthreads();
    }
#pragma unroll
    for (int mf = 0; mf < 4; ++mf)
#pragma unroll
        for (int h = 0; h < 2; ++h) {
            int o = wm*64 + mf*16 + gid + h*8;
            float sc = 1.0f, cb = bias[o];
            if (bng) {
                sc = bng[o] * rsqrtf(bnv[o] + EPSB);
                cb = (bias[o] - bnm[o]) * sc + bnb[o];
            }
#pragma unroll
            for (int nf = 0; nf < 2; ++nf) {
                int cl = wn*16 + nf*8 + t4*2;
                float2 r;
                r.x = acc[mf][nf][2*h+0]*sc + cb;
                r.y = acc[mf][nf][2*h+1]*sc + cb;
                *(float2*)&ob[(size_t)o*NPIX + p0 + cl] = r;
            }
        }
}

// ---------------- score: A[n][m] = sum_c kx[c][n] qx[c][m]; track batch max ----
__global__ __launch_bounds__(256, 2) void score_t()
{
    const int b  = blockIdx.z;
    const int n0 = blockIdx.y * 128;
    const int m0 = blockIdx.x * 64;
    const float* kx = g_kx + (size_t)b*CC*NPIX;
    const float* qx = g_qx + (size_t)b*CC*NPIX;
    float* Ab = g_A + (size_t)b*NPIX*NPIX;
    __shared__ __align__(16) float As[2][16*132];   // kx tile [k16][n128]
    __shared__ __align__(16) float Bs[2][16*68];    // qx tile [k16][m64]
    __shared__ float smax[8];
    const int tid = threadIdx.x, lane = tid & 31, wid = tid >> 5;
    const int wm = wid & 1, wn = wid >> 1;
    const int gid = lane >> 2, t4 = lane & 3;
    const int ak = tid >> 4, anq0 = (tid & 15)*2, anq1 = anq0 + 1;
    const int bk = tid >> 4, bq = tid & 15;
    float acc[4][2][4] = {};
    float4 pa0, pa1, pb;
    pa0 = *(const float4*)&kx[(size_t)ak*NPIX + n0 + anq0*4];
    pa1 = *(const float4*)&kx[(size_t)ak*NPIX + n0 + anq1*4];
    pb  = *(const float4*)&qx[(size_t)bk*NPIX + m0 + bq*4];
    *(float4*)&As[0][ak*132 + anq0*4] = tf4(pa0);
    *(float4*)&As[0][ak*132 + anq1*4] = tf4(pa1);
    *(float4*)&Bs[0][bk*68 + bq*4]    = tf4(pb);
    __syncthreads();
    for (int it = 0; it < CC/16; ++it) {
        if (it + 1 < CC/16) {
            int k0 = (it+1)*16;
            pa0 = *(const float4*)&kx[(size_t)(k0+ak)*NPIX + n0 + anq0*4];
            pa1 = *(const float4*)&kx[(size_t)(k0+ak)*NPIX + n0 + anq1*4];
            pb  = *(const float4*)&qx[(size_t)(k0+bk)*NPIX + m0 + bq*4];
        }
        {   // mma with A in [k][n] layout (scalar a-frag loads, conflict-free)
            const float* Asb = As[it & 1];
            const float* Bsb = Bs[it & 1];
#pragma unroll
            for (int ko = 0; ko < 2; ++ko) {
                unsigned bf[2][2];
#pragma unroll
                for (int nf = 0; nf < 2; ++nf) {
                    int nb = wn*16 + nf*8 + gid;
                    bf[nf][0] = __float_as_uint(Bsb[(ko*8+t4  )*68 + nb]);
                    bf[nf][1] = __float_as_uint(Bsb[(ko*8+t4+4)*68 + nb]);
                }
#pragma unroll
                for (int mf = 0; mf < 4; ++mf) {
                    int rb = wm*64 + mf*16 + gid;
                    unsigned a0 = __float_as_uint(Asb[(ko*8+t4  )*132 + rb]);
                    unsigned a1 = __float_as_uint(Asb[(ko*8+t4  )*132 + rb+8]);
                    unsigned a2 = __float_as_uint(Asb[(ko*8+t4+4)*132 + rb]);
                    unsigned a3 = __float_as_uint(Asb[(ko*8+t4+4)*132 + rb+8]);
#pragma unroll
                    for (int nf = 0; nf < 2; ++nf)
                        mma_tf32(acc[mf][nf], a0, a1, a2, a3, bf[nf][0], bf[nf][1]);
                }
            }
        }
        if (it + 1 < CC/16) {
            int nb = (it+1) & 1;
            *(float4*)&As[nb][ak*132 + anq0*4] = tf4(pa0);
            *(float4*)&As[nb][ak*132 + anq1*4] = tf4(pa1);
            *(float4*)&Bs[nb][bk*68 + bq*4]    = tf4(pb);
        }
        __syncthreads();
    }
    float mx = -1e30f;
#pragma unroll
    for (int mf = 0; mf < 4; ++mf)
#pragma unroll
        for (int h = 0; h < 2; ++h) {
            int n = n0 + wm*64 + mf*16 + gid + h*8;
#pragma unroll
            for (int nf = 0; nf < 2; ++nf) {
                int cl = wn*16 + nf*8 + t4*2;
                float2 r;
                r.x = acc[mf][nf][2*h+0]; r.y = acc[mf][nf][2*h+1];
                mx = fmaxf(mx, fmaxf(r.x, r.y));
                *(float2*)&Ab[(size_t)n*NPIX + m0 + cl] = r;
            }
        }
#pragma unroll
    for (int o = 16; o; o >>= 1) mx = fmaxf(mx, __shfl_xor_sync(~0u, mx, o));
    if (lane == 0) smax[wid] = mx;
    __syncthreads();
    if (tid == 0) {
        float m2 = smax[0];
#pragma unroll
        for (int j = 1; j < 8; ++j) m2 = fmaxf(m2, smax[j]);
        atomicMax(&g_bmaxk[b], fkey(m2));
    }
}

// ---------------- channel gate --------------------------------------------------
__global__ __launch_bounds__(256) void gate_kernel(
    const float* __restrict__ w1, const float* __restrict__ b1,
    const float* __restrict__ w2, const float* __restrict__ b2)
{
    const int b = blockIdx.y;
    const float* t = (blockIdx.x == 0 ? g_qt : g_st) + (size_t)b*CC*NPIX;
    float* go = (blockIdx.x == 0 ? g_gq : g_gs) + b*CC;
    __shared__ float pool[CC];
    __shared__ float hsh[8];
    const int tid = threadIdx.x, lane = tid & 31, wid = tid >> 5;
    for (int ch = wid; ch < CC; ch += 8) {
        const float* row = t + (size_t)ch*NPIX;
        float s = 0.f;
        for (int i = lane; i < NPIX; i += 32) s += row[i];
#pragma unroll
        for (int o = 16; o; o >>= 1) s += __shfl_xor_sync(~0u, s, o);
        if (lane == 0) pool[ch] = s * (1.0f/NPIX);
    }
    __syncthreads();
    if (tid < 8) {
        float h = b1[tid];
        for (int i = 0; i < CC; ++i) h += pool[i] * w1[tid*CC + i];
        hsh[tid] = fmaxf(h, 0.f);
    }
    __syncthreads();
    if (tid < CC) {
        float z = b2[tid];
#pragma unroll
        for (int j = 0; j < 8; ++j) z += hsh[j] * w2[tid*8 + j];
        go[tid] = 1.0f / (1.0f + __expf(-z));
    }
}

// ---------------- E_s: M = co, N = n(64), K = m. Inline row sums. ---------------
// out[co][n] = gs[co]*(sum_m exp(A[n][m]-gm) vs[co][m]) / rowsum(n) + st[co][n]
__global__ __launch_bounds__(256, 2) void attn_s_t(float* __restrict__ Es)
{
    const int b  = blockIdx.y;
    const int n0 = blockIdx.x * 64;
    const float* Ab = g_A  + (size_t)b*NPIX*NPIX;
    const float* vs = g_vs + (size_t)b*CC*NPIX;
    const float* st = g_st + (size_t)b*CC*NPIX;
    const float* gt = g_gs + b*CC;
    float* Eb = Es + (size_t)b*CC*NPIX;
    const float gm = fdekey(g_bmaxk[b]);
    __shared__ __align__(16) float As[2][128*20];   // vs crosswise
    __shared__ __align__(16) float Bs[2][16*68];    // exp(A) tile [k16][n64]
    __shared__ float rinv_s[64];
    const int tid = threadIdx.x, lane = tid & 31, wid = tid >> 5;
    const int wm = wid & 1, wn = wid >> 1;
    const int gid = lane >> 2, t4 = lane & 3;
    const int am = tid >> 1, aq0 = 2*(tid & 1), aq1 = aq0 + 1;
    const int bn = tid >> 2, bkq = tid & 3;      // B: row bn of A, k-quad bkq
    float acc[4][2][4] = {};
    float rs = 0.f;
    float4 pa0, pa1, pb;
    pa0 = *(const float4*)&vs[(size_t)am*NPIX + aq0*4];
    pa1 = *(const float4*)&vs[(size_t)am*NPIX + aq1*4];
    pb  = *(const float4*)&Ab[(size_t)(n0+bn)*NPIX + bkq*4];
    {
        stA(As[0], am, aq0, pa0); stA(As[0], am, aq1, pa1);
        float e0 = __expf(pb.x-gm), e1 = __expf(pb.y-gm);
        float e2 = __expf(pb.z-gm), e3 = __expf(pb.w-gm);
        rs += e0+e1+e2+e3;
        float* p = &Bs[0][bkq*4*68 + bn];
        p[0] = tf(e0); p[68] = tf(e1); p[136] = tf(e2); p[204] = tf(e3);
    }
    __syncthreads();
    const int iters = NPIX/16;
    for (int it = 0; it < iters; ++it) {
        if (it + 1 < iters) {
            int k0 = (it+1)*16;
            pa0 = *(const float4*)&vs[(size_t)am*NPIX + k0 + aq0*4];
            pa1 = *(const float4*)&vs[(size_t)am*NPIX + k0 + aq1*4];
            pb  = *(const float4*)&Ab[(size_t)(n0+bn)*NPIX + k0 + bkq*4];
        }
        mma_cross<68>(acc, As[it & 1], Bs[it & 1], wm, wn, lane);
        if (it + 1 < iters) {
            int nb = (it+1) & 1;
            stA(As[nb], am, aq0, pa0); stA(As[nb], am, aq1, pa1);
            float e0 = __expf(pb.x-gm), e1 = __expf(pb.y-gm);
            float e2 = __expf(pb.z-gm), e3 = __expf(pb.w-gm);
            rs += e0+e1+e2+e3;
            float* p = &Bs[nb][bkq*4*68 + bn];
            p[0] = tf(e0); p[68] = tf(e1); p[136] = tf(e2); p[204] = tf(e3);
        }
        __syncthreads();
    }
    rs += __shfl_xor_sync(~0u, rs, 1);
    rs += __shfl_xor_sync(~0u, rs, 2);
    if ((tid & 3) == 0) rinv_s[bn] = 1.0f / rs;
    __syncthreads();
#pragma unroll
    for (int mf = 0; mf < 4; ++mf)
#pragma unroll
        for (int h = 0; h < 2; ++h) {
            int co = wm*64 + mf*16 + gid + h*8;
            float g = gt[co];
#pragma unroll
            for (int nf = 0; nf < 2; ++nf) {
                int cl = wn*16 + nf*8 + t4*2;
                float2 res = *(const float2*)&st[(size_t)co*NPIX + n0 + cl];
                float2 r;
                r.x = g*acc[mf][nf][2*h+0]*rinv_s[cl]   + res.x;
                r.y = g*acc[mf][nf][2*h+1]*rinv_s[cl+1] + res.y;
                *(float2*)&Eb[(size_t)co*NPIX + n0 + cl] = r;
            }
        }
}

// ---------------- E_q: M = co, N = m(64), K = n. Inline col sums. ---------------
// out[co][m] = gq[co]*(sum_n exp(A[n][m]-gm) vq[co][n]) / colsum(m) + qt[co][m]
__global__ __launch_bounds__(256, 2) void attn_q_t(float* __restrict__ Eq)
{
    const int b  = blockIdx.y;
    const int m0 = blockIdx.x * 64;
    const float* Ab = g_A  + (size_t)b*NPIX*NPIX;
    const float* vq = g_vq + (size_t)b*CC*NPIX;
    const float* qt = g_qt + (size_t)b*CC*NPIX;
    const float* gt = g_gq + b*CC;
    float* Eb = Eq + (size_t)b*CC*NPIX;
    const float gm = fdekey(g_bmaxk[b]);
    __shared__ __align__(16) float As[2][128*20];   // vq crosswise
    __shared__ __align__(16) float Bs[2][16*68];    // exp(A) tile [k16][m64]
    __shared__ float red[16*68];
    __shared__ float cinv_s[64];
    const int tid = threadIdx.x, lane = tid & 31, wid = tid >> 5;
    const int wm = wid & 1, wn = wid >> 1;
    const int gid = lane >> 2, t4 = lane & 3;
    const int am = tid >> 1, aq0 = 2*(tid & 1), aq1 = aq0 + 1;
    const int bk = tid >> 4, bq = tid & 15;
    float acc[4][2][4] = {};
    float cs0 = 0.f, cs1 = 0.f, cs2 = 0.f, cs3 = 0.f;
    float4 pa0, pa1, pb;
    pa0 = *(const float4*)&vq[(size_t)am*NPIX + aq0*4];
    pa1 = *(const float4*)&vq[(size_t)am*NPIX + aq1*4];
    pb  = *(const float4*)&Ab[(size_t)bk*NPIX + m0 + bq*4];
    {
        stA(As[0], am, aq0, pa0); stA(As[0], am, aq1, pa1);
        float4 e;
        e.x = __expf(pb.x-gm); e.y = __expf(pb.y-gm);
        e.z = __expf(pb.z-gm); e.w = __expf(pb.w-gm);
        cs0 += e.x; cs1 += e.y; cs2 += e.z; cs3 += e.w;
        *(float4*)&Bs[0][bk*68 + bq*4] = tf4(e);
    }
    __syncthreads();
    const int iters = NPIX/16;
    for (int it = 0; it < iters; ++it) {
        if (it + 1 < iters) {
            int k0 = (it+1)*16;
            pa0 = *(const float4*)&vq[(size_t)am*NPIX + k0 + aq0*4];
            pa1 = *(const float4*)&vq[(size_t)am*NPIX + k0 + aq1*4];
            pb  = *(const float4*)&Ab[(size_t)(k0+bk)*NPIX + m0 + bq*4];
        }
        mma_cross<68>(acc, As[it & 1], Bs[it & 1], wm, wn, lane);
        if (it + 1 < iters) {
            int nb = (it+1) & 1;
            stA(As[nb], am, aq0, pa0); stA(As[nb], am, aq1, pa1);
            float4 e;
            e.x = __expf(pb.x-gm); e.y = __expf(pb.y-gm);
            e.z = __expf(pb.z-gm); e.w = __expf(pb.w-gm);
            cs0 += e.x; cs1 += e.y; cs2 += e.z; cs3 += e.w;
            *(float4*)&Bs[nb][bk*68 + bq*4] = tf4(e);
        }
        __syncthreads();
    }
    red[bk*68 + bq*4+0] = cs0; red[bk*68 + bq*4+1] = cs1;
    red[bk*68 + bq*4+2] = cs2; red[bk*68 + bq*4+3] = cs3;
    __syncthreads();
    if (tid < 64) {
        float s = 0.f;
#pragma unroll
        for (int i = 0; i < 16; ++i) s += red[i*68 + tid];
        cinv_s[tid] = 1.0f / s;
    }
    __syncthreads();
#pragma unroll
    for (int mf = 0; mf < 4; ++mf)
#pragma unroll
        for (int h = 0; h < 2; ++h) {
            int co = wm*64 + mf*16 + gid + h*8;
            float g = gt[co];
#pragma unroll
            for (int nf = 0; nf < 2; ++nf) {
                int cl = wn*16 + nf*8 + t4*2;
                float2 res = *(const float2*)&qt[(size_t)co*NPIX + m0 + cl];
                float2 r;
                r.x = g*acc[mf][nf][2*h+0]*cinv_s[cl]   + res.x;
                r.y = g*acc[mf][nf][2*h+1]*cinv_s[cl+1] + res.y;
                *(float2*)&Eb[(size_t)co*NPIX + m0 + cl] = r;
            }
        }
}

// ---------------- 3x3 conv (implicit GEMM) + BN + ReLU --------------------------
__global__ __launch_bounds__(256, 2) void conv_t(
    const float* __restrict__ cw, const float* __restrict__ cg,
    const float* __restrict__ cb, const float* __restrict__ cm,
    const float* __restrict__ cv,
    const float* __restrict__ Eq, const float* __restrict__ Es,
    float* __restrict__ feat)
{
    const int b  = blockIdx.y;
    const int p0 = blockIdx.x * 64;
    const float* Eqb = Eq + (size_t)b*CC*NPIX;
    const float* Esb = Es + (size_t)b*CC*NPIX;
    float* fb = feat + (size_t)b*CC*NPIX;
    __shared__ __align__(16) float As[2][128*20];   // cw crosswise
    __shared__ __align__(16) float Bs[2][16*68];    // im2col tile
    const int tid = threadIdx.x, lane = tid & 31, wid = tid >> 5;
    const int wm = wid & 1, wn = wid >> 1;
    const int gid = lane >> 2, t4 = lane & 3;
    const int am = tid >> 1, aq0 = 2*(tid & 1), aq1 = aq0 + 1;
    const int bk = tid >> 4, bq = tid & 15;
    int hh[4], ww[4];
#pragma unroll
    for (int j = 0; j < 4; ++j) {
        int p = p0 + bq*4 + j;
        hh[j] = p / 48; ww[j] = p - hh[j]*48;
    }
    auto loadB = [&](int k0) -> float4 {
        int kap = k0 + bk;
        int ic = kap / 9, kk = kap - ic*9;
        int dh = kk/3 - 1, dw = kk - (kk/3)*3 - 1;
        const float* src = (ic < CC) ? Eqb : Esb;
        int icl = ic & (CC-1);
        float4 v;
        float* vp = (float*)&v;
#pragma unroll
        for (int j = 0; j < 4; ++j) {
            int ih = hh[j] + dh, iw = ww[j] + dw;
            vp[j] = ((unsigned)ih < 48u && (unsigned)iw < 48u)
                  ? src[(size_t)icl*NPIX + ih*48 + iw] : 0.f;
        }
        return v;
    };
    float acc[4][2][4] = {};
    float4 pa0, pa1, pb;
    pa0 = *(const float4*)&cw[am*2304 + aq0*4];
    pa1 = *(const float4*)&cw[am*2304 + aq1*4];
    pb  = loadB(0);
    stA(As[0], am, aq0, pa0); stA(As[0], am, aq1, pa1);
    *(float4*)&Bs[0][bk*68 + bq*4] = tf4(pb);
    __syncthreads();
    for (int it = 0; it < 144; ++it) {
        if (it + 1 < 144) {
            int k0 = (it+1)*16;
            pa0 = *(const float4*)&cw[am*2304 + k0 + aq0*4];
            pa1 = *(const float4*)&cw[am*2304 + k0 + aq1*4];
            pb  = loadB(k0);
        }
        mma_cross<68>(acc, As[it & 1], Bs[it & 1], wm, wn, lane);
        if (it + 1 < 144) {
            int nb = (it+1) & 1;
            stA(As[nb], am, aq0, pa0); stA(As[nb], am, aq1, pa1);
            *(float4*)&Bs[nb][bk*68 + bq*4] = tf4(pb);
        }
        __syncthreads();
    }
#pragma unroll
    for (int mf = 0; mf < 4; ++mf)
#pragma unroll
        for (int h = 0; h < 2; ++h) {
            int o = wm*64 + mf*16 + gid + h*8;
            float sc  = cg[o] * rsqrtf(cv[o] + EPSB);
            float cbv = cb[o] - cm[o]*sc;
#pragma unroll
            for (int nf = 0; nf < 2; ++nf) {
                int cl = wn*16 + nf*8 + t4*2;
                float2 r;
                r.x = fmaxf(acc[mf][nf][2*h+0]*sc + cbv, 0.f);
                r.y = fmaxf(acc[mf][nf][2*h+1]*sc + cbv, 0.f);
                *(float2*)&fb[(size_t)o*NPIX + p0 + cl] = r;
            }
        }
}

// ---------------- host ----------------------------------------------------------
extern "C" void kernel_launch(void* const* d_in, const int* in_sizes, int n_in,
                              void* d_out, int out_size)
{
    (void)in_sizes; (void)n_in; (void)out_size;
    const float* q    = (const float*)d_in[0];
    const float* s    = (const float*)d_in[1];
    const float* tsw  = (const float*)d_in[2];
    const float* tsb  = (const float*)d_in[3];
    const float* bsg  = (const float*)d_in[4];
    const float* bsb  = (const float*)d_in[5];
    const float* bsm  = (const float*)d_in[6];
    const float* bsv  = (const float*)d_in[7];
    const float* tqw  = (const float*)d_in[8];
    const float* tqb  = (const float*)d_in[9];
    const float* bqg  = (const float*)d_in[10];
    const float* bqb  = (const float*)d_in[11];
    const float* bqm  = (const float*)d_in[12];
    const float* bqv  = (const float*)d_in[13];
    const float* vqw  = (const float*)d_in[14];
    const float* vqb  = (const float*)d_in[15];
    const float* vsw  = (const float*)d_in[16];
    const float* vsb  = (const float*)d_in[17];
    const float* keyw = (const float*)d_in[18];
    const float* keyb = (const float*)d_in[19];
    const float* qryw = (const float*)d_in[20];
    const float* qryb = (const float*)d_in[21];
    const float* gw1  = (const float*)d_in[22];
    const float* gb1  = (const float*)d_in[23];
    const float* gw2  = (const float*)d_in[24];
    const float* gb2  = (const float*)d_in[25];
    const float* cw   = (const float*)d_in[26];
    const float* cg   = (const float*)d_in[27];
    const float* cb   = (const float*)d_in[28];
    const float* cm   = (const float*)d_in[29];
    const float* cv   = (const float*)d_in[30];

    float *p_qt, *p_st, *p_vq, *p_vs, *p_kx, *p_qx;
    cudaGetSymbolAddress((void**)&p_qt, g_qt);
    cudaGetSymbolAddress((void**)&p_st, g_st);
    cudaGetSymbolAddress((void**)&p_vq, g_vq);
    cudaGetSymbolAddress((void**)&p_vs, g_vs);
    cudaGetSymbolAddress((void**)&p_kx, g_kx);
    cudaGetSymbolAddress((void**)&p_qx, g_qx);

    float* feat = (float*)d_out;
    float* Eq   = feat + (size_t)BATCH*CC*NPIX;
    float* Es   = Eq   + (size_t)BATCH*CC*NPIX;

    dim3 g36(36, BATCH);

    init_bmax<<<1, 32>>>();
    gemm_wx_t<<<g36, 256>>>(q, tqw, tqb, bqg, bqb, bqm, bqv, p_qt, CIN);
    gemm_wx_t<<<g36, 256>>>(s, tsw, tsb, bsg, bsb, bsm, bsv, p_st, CIN);
    gemm_wx_t<<<g36, 256>>>(p_qt, vqw,  vqb,  0, 0, 0, 0, p_vq, CC);
    gemm_wx_t<<<g36, 256>>>(p_qt, qryw, qryb, 0, 0, 0, 0, p_qx, CC);
    gemm_wx_t<<<g36, 256>>>(p_st, vsw,  vsb,  0, 0, 0, 0, p_vs, CC);
    gemm_wx_t<<<g36, 256>>>(p_st, keyw, keyb, 0, 0, 0, 0, p_kx, CC);

    score_t<<<dim3(36, 18, BATCH), 256>>>();
    gate_kernel<<<dim3(2, BATCH), 256>>>(gw1, gb1, gw2, gb2);

    attn_s_t<<<g36, 256>>>(Es);
    attn_q_t<<<g36, 256>>>(Eq);

    conv_t<<<g36, 256>>>(cw, cg, cb, cm, cv, Eq, Es, feat);
}

// round 4
// speedup vs baseline: 2.2510x; 1.2100x over previous
#include <cuda_runtime.h>

#define BATCH 8
#define CIN   256
#define CC    128
#define NPIX  2304
#define EPSB  1e-5f

// ---------------- scratch ------------------------------------------------------
__device__ __align__(16) float g_qt[BATCH*CC*NPIX];
__device__ __align__(16) float g_st[BATCH*CC*NPIX];
__device__ __align__(16) float g_vq[BATCH*CC*NPIX];
__device__ __align__(16) float g_vs[BATCH*CC*NPIX];
__device__ __align__(16) float g_kx[BATCH*CC*NPIX];
__device__ __align__(16) float g_qx[BATCH*CC*NPIX];
__device__ __align__(16) float g_A[(size_t)BATCH*NPIX*NPIX];
__device__ unsigned g_bmaxk[BATCH];
__device__ float g_gq[BATCH*CC];
__device__ float g_gs[BATCH*CC];

// ---------------- helpers ------------------------------------------------------
__device__ __forceinline__ float tf(float x) {
    unsigned u;
    asm("cvt.rna.tf32.f32 %0, %1;" : "=r"(u) : "f"(x));
    return __uint_as_float(u);
}
__device__ __forceinline__ float4 tf4(float4 v) {
    v.x = tf(v.x); v.y = tf(v.y); v.z = tf(v.z); v.w = tf(v.w); return v;
}
__device__ __forceinline__ unsigned fkey(float x) {
    int i = __float_as_int(x);
    return (i >= 0) ? ((unsigned)i | 0x80000000u) : ~(unsigned)i;
}
__device__ __forceinline__ float fdekey(unsigned u) {
    int i = (u & 0x80000000u) ? (int)(u & 0x7fffffffu) : ~(int)u;
    return __int_as_float(i);
}
__device__ __forceinline__ void mma_tf32(float* c,
    unsigned a0, unsigned a1, unsigned a2, unsigned a3,
    unsigned b0, unsigned b1)
{
    asm volatile(
        "mma.sync.aligned.m16n8k8.row.col.f32.tf32.tf32.f32 "
        "{%0,%1,%2,%3}, {%4,%5,%6,%7}, {%8,%9}, {%0,%1,%2,%3};"
        : "+f"(c[0]), "+f"(c[1]), "+f"(c[2]), "+f"(c[3])
        : "r"(a0), "r"(a1), "r"(a2), "r"(a3), "r"(b0), "r"(b1));
}

// Block tile 128(M) x 128(N) x 16(K); 8 warps: wm = wid&1, wn = wid>>2? No:
// wm = wid&1 (2 in M), wn = wid>>1 (4 in N); warp tile 64 x 32.
// A crosswise: (m,k) at As[m*20 + (k&3)*4 + (k>>2)] -> LDS.128 at As4[m*5+t4]
// gives k = {t4, t4+4, t4+8, t4+12}.
// B row layout: (k,n) at Bs[k*136 + n] (pad 8 -> conflict-free scalar frags).
__device__ __forceinline__ void mma_AB(float acc[4][4][4],
    const float* As, const float* Bs, int wm, int wn, int lane)
{
    const int gid = lane >> 2, t4 = lane & 3;
    const float4* As4 = (const float4*)As;
    float4 va[4][2];
#pragma unroll
    for (int mf = 0; mf < 4; ++mf) {
        int rb = wm*64 + mf*16 + gid;
        va[mf][0] = As4[rb*5 + t4];
        va[mf][1] = As4[(rb+8)*5 + t4];
    }
#pragma unroll
    for (int ko = 0; ko < 2; ++ko) {
        unsigned bf[4][2];
#pragma unroll
        for (int nf = 0; nf < 4; ++nf) {
            int nb = wn*32 + nf*8 + gid;
            bf[nf][0] = __float_as_uint(Bs[(ko*8+t4  )*136 + nb]);
            bf[nf][1] = __float_as_uint(Bs[(ko*8+t4+4)*136 + nb]);
        }
#pragma unroll
        for (int mf = 0; mf < 4; ++mf) {
            unsigned a0, a1, a2, a3;
            if (ko == 0) {
                a0 = __float_as_uint(va[mf][0].x); a1 = __float_as_uint(va[mf][1].x);
                a2 = __float_as_uint(va[mf][0].y); a3 = __float_as_uint(va[mf][1].y);
            } else {
                a0 = __float_as_uint(va[mf][0].z); a1 = __float_as_uint(va[mf][1].z);
                a2 = __float_as_uint(va[mf][0].w); a3 = __float_as_uint(va[mf][1].w);
            }
#pragma unroll
            for (int nf = 0; nf < 4; ++nf)
                mma_tf32(acc[mf][nf], a0, a1, a2, a3, bf[nf][0], bf[nf][1]);
        }
    }
}

// store a k-quad (k = aq*4..aq*4+3) of row m into crosswise A
__device__ __forceinline__ void stA(float* As, int m, int aq, float4 v) {
    float* p = &As[m*20 + aq];
    p[0] = tf(v.x); p[4] = tf(v.y); p[8] = tf(v.z); p[12] = tf(v.w);
}

#define ASZ (128*20)
#define BSZ (16*136)

__global__ void init_bmax() { if (threadIdx.x < BATCH) g_bmaxk[threadIdx.x] = 0u; }

// ---------------- 1x1 conv GEMM: out[o][p] = sum_k w[o][k] x[k][p] (+BN) --------
__global__ __launch_bounds__(256, 2) void gemm_wx_t(
    const float* __restrict__ x, const float* __restrict__ w,
    const float* __restrict__ bias,
    const float* __restrict__ bng, const float* __restrict__ bnb,
    const float* __restrict__ bnm, const float* __restrict__ bnv,
    float* __restrict__ out, int K)
{
    const int b  = blockIdx.y;
    const int p0 = blockIdx.x * 128;
    const float* xb = x + (size_t)b*K*NPIX;
    float* ob = out + (size_t)b*CC*NPIX;
    __shared__ __align__(16) float As[2][ASZ];
    __shared__ __align__(16) float Bs[2][BSZ];
    const int tid = threadIdx.x, lane = tid & 31, wid = tid >> 5;
    const int wm = wid & 1, wn = wid >> 1;
    const int gid = lane >> 2, t4 = lane & 3;
    const int am = tid >> 1, aq0 = 2*(tid & 1), aq1 = aq0 + 1;
    const int bk = tid >> 4, bq = tid & 15;
    float acc[4][4][4] = {};
    float4 pa0, pa1, pb0, pb1;
    pa0 = *(const float4*)&w[am*K + aq0*4];
    pa1 = *(const float4*)&w[am*K + aq1*4];
    pb0 = *(const float4*)&xb[(size_t)bk*NPIX + p0 + bq*4];
    pb1 = *(const float4*)&xb[(size_t)bk*NPIX + p0 + 64 + bq*4];
    stA(As[0], am, aq0, pa0); stA(As[0], am, aq1, pa1);
    *(float4*)&Bs[0][bk*136 + bq*4]      = tf4(pb0);
    *(float4*)&Bs[0][bk*136 + 64 + bq*4] = tf4(pb1);
    __syncthreads();
    const int iters = K / 16;
    for (int it = 0; it < iters; ++it) {
        if (it + 1 < iters) {
            int k0 = (it+1)*16;
            pa0 = *(const float4*)&w[am*K + k0 + aq0*4];
            pa1 = *(const float4*)&w[am*K + k0 + aq1*4];
            pb0 = *(const float4*)&xb[(size_t)(k0+bk)*NPIX + p0 + bq*4];
            pb1 = *(const float4*)&xb[(size_t)(k0+bk)*NPIX + p0 + 64 + bq*4];
        }
        mma_AB(acc, As[it & 1], Bs[it & 1], wm, wn, lane);
        if (it + 1 < iters) {
            int nb = (it+1) & 1;
            stA(As[nb], am, aq0, pa0); stA(As[nb], am, aq1, pa1);
            *(float4*)&Bs[nb][bk*136 + bq*4]      = tf4(pb0);
            *(float4*)&Bs[nb][bk*136 + 64 + bq*4] = tf4(pb1);
        }
        __syncthreads();
    }
#pragma unroll
    for (int mf = 0; mf < 4; ++mf)
#pragma unroll
        for (int h = 0; h < 2; ++h) {
            int o = wm*64 + mf*16 + gid + h*8;
            float sc = 1.0f, cb = bias[o];
            if (bng) {
                sc = bng[o] * rsqrtf(bnv[o] + EPSB);
                cb = (bias[o] - bnm[o]) * sc + bnb[o];
            }
#pragma unroll
            for (int nf = 0; nf < 4; ++nf) {
                int cl = wn*32 + nf*8 + t4*2;
                float2 r;
                r.x = acc[mf][nf][2*h+0]*sc + cb;
                r.y = acc[mf][nf][2*h+1]*sc + cb;
                *(float2*)&ob[(size_t)o*NPIX + p0 + cl] = r;
            }
        }
}

// ---------------- score: A[n][m] = sum_c kx[c][n] qx[c][m]; track batch max ----
__global__ __launch_bounds__(256, 2) void score_t()
{
    const int b  = blockIdx.z;
    const int n0 = blockIdx.y * 128;
    const int m0 = blockIdx.x * 128;
    const float* kx = g_kx + (size_t)b*CC*NPIX;
    const float* qx = g_qx + (size_t)b*CC*NPIX;
    float* Ab = g_A + (size_t)b*NPIX*NPIX;
    __shared__ __align__(16) float As[2][BSZ];   // kx tile [k16][n128+pad]
    __shared__ __align__(16) float Bs[2][BSZ];   // qx tile [k16][m128+pad]
    __shared__ float smax[8];
    const int tid = threadIdx.x, lane = tid & 31, wid = tid >> 5;
    const int wm = wid & 1, wn = wid >> 1;
    const int gid = lane >> 2, t4 = lane & 3;
    const int ak = tid >> 4, aq = tid & 15;
    float acc[4][4][4] = {};
    float4 pa0, pa1, pb0, pb1;
    pa0 = *(const float4*)&kx[(size_t)ak*NPIX + n0 + aq*4];
    pa1 = *(const float4*)&kx[(size_t)ak*NPIX + n0 + 64 + aq*4];
    pb0 = *(const float4*)&qx[(size_t)ak*NPIX + m0 + aq*4];
    pb1 = *(const float4*)&qx[(size_t)ak*NPIX + m0 + 64 + aq*4];
    *(float4*)&As[0][ak*136 + aq*4]      = tf4(pa0);
    *(float4*)&As[0][ak*136 + 64 + aq*4] = tf4(pa1);
    *(float4*)&Bs[0][ak*136 + aq*4]      = tf4(pb0);
    *(float4*)&Bs[0][ak*136 + 64 + aq*4] = tf4(pb1);
    __syncthreads();
    for (int it = 0; it < CC/16; ++it) {
        if (it + 1 < CC/16) {
            int k0 = (it+1)*16;
            pa0 = *(const float4*)&kx[(size_t)(k0+ak)*NPIX + n0 + aq*4];
            pa1 = *(const float4*)&kx[(size_t)(k0+ak)*NPIX + n0 + 64 + aq*4];
            pb0 = *(const float4*)&qx[(size_t)(k0+ak)*NPIX + m0 + aq*4];
            pb1 = *(const float4*)&qx[(size_t)(k0+ak)*NPIX + m0 + 64 + aq*4];
        }
        {   // A-frags via scalar reads from [k][n+pad8] (conflict-free)
            const float* Asb = As[it & 1];
            const float* Bsb = Bs[it & 1];
#pragma unroll
            for (int ko = 0; ko < 2; ++ko) {
                unsigned bf[4][2];
#pragma unroll
                for (int nf = 0; nf < 4; ++nf) {
                    int nb = wn*32 + nf*8 + gid;
                    bf[nf][0] = __float_as_uint(Bsb[(ko*8+t4  )*136 + nb]);
                    bf[nf][1] = __float_as_uint(Bsb[(ko*8+t4+4)*136 + nb]);
                }
#pragma unroll
                for (int mf = 0; mf < 4; ++mf) {
                    int rb = wm*64 + mf*16 + gid;
                    unsigned a0 = __float_as_uint(Asb[(ko*8+t4  )*136 + rb]);
                    unsigned a1 = __float_as_uint(Asb[(ko*8+t4  )*136 + rb+8]);
                    unsigned a2 = __float_as_uint(Asb[(ko*8+t4+4)*136 + rb]);
                    unsigned a3 = __float_as_uint(Asb[(ko*8+t4+4)*136 + rb+8]);
#pragma unroll
                    for (int nf = 0; nf < 4; ++nf)
                        mma_tf32(acc[mf][nf], a0, a1, a2, a3, bf[nf][0], bf[nf][1]);
                }
            }
        }
        if (it + 1 < CC/16) {
            int nb = (it+1) & 1;
            *(float4*)&As[nb][ak*136 + aq*4]      = tf4(pa0);
            *(float4*)&As[nb][ak*136 + 64 + aq*4] = tf4(pa1);
            *(float4*)&Bs[nb][ak*136 + aq*4]      = tf4(pb0);
            *(float4*)&Bs[nb][ak*136 + 64 + aq*4] = tf4(pb1);
        }
        __syncthreads();
    }
    float mx = -1e30f;
#pragma unroll
    for (int mf = 0; mf < 4; ++mf)
#pragma unroll
        for (int h = 0; h < 2; ++h) {
            int n = n0 + wm*64 + mf*16 + gid + h*8;
#pragma unroll
            for (int nf = 0; nf < 4; ++nf) {
                int cl = wn*32 + nf*8 + t4*2;
                float2 r;
                r.x = acc[mf][nf][2*h+0]; r.y = acc[mf][nf][2*h+1];
                mx = fmaxf(mx, fmaxf(r.x, r.y));
                *(float2*)&Ab[(size_t)n*NPIX + m0 + cl] = r;
            }
        }
#pragma unroll
    for (int o = 16; o; o >>= 1) mx = fmaxf(mx, __shfl_xor_sync(~0u, mx, o));
    if (lane == 0) smax[wid] = mx;
    __syncthreads();
    if (tid == 0) {
        float m2 = smax[0];
#pragma unroll
        for (int j = 1; j < 8; ++j) m2 = fmaxf(m2, smax[j]);
        atomicMax(&g_bmaxk[b], fkey(m2));
    }
}

// ---------------- channel gate --------------------------------------------------
__global__ __launch_bounds__(256) void gate_kernel(
    const float* __restrict__ w1, const float* __restrict__ b1,
    const float* __restrict__ w2, const float* __restrict__ b2)
{
    const int b = blockIdx.y;
    const float* t = (blockIdx.x == 0 ? g_qt : g_st) + (size_t)b*CC*NPIX;
    float* go = (blockIdx.x == 0 ? g_gq : g_gs) + b*CC;
    __shared__ float pool[CC];
    __shared__ float hsh[8];
    const int tid = threadIdx.x, lane = tid & 31, wid = tid >> 5;
    for (int ch = wid; ch < CC; ch += 8) {
        const float* row = t + (size_t)ch*NPIX;
        float s = 0.f;
        for (int i = lane; i < NPIX; i += 32) s += row[i];
#pragma unroll
        for (int o = 16; o; o >>= 1) s += __shfl_xor_sync(~0u, s, o);
        if (lane == 0) pool[ch] = s * (1.0f/NPIX);
    }
    __syncthreads();
    if (tid < 8) {
        float h = b1[tid];
        for (int i = 0; i < CC; ++i) h += pool[i] * w1[tid*CC + i];
        hsh[tid] = fmaxf(h, 0.f);
    }
    __syncthreads();
    if (tid < CC) {
        float z = b2[tid];
#pragma unroll
        for (int j = 0; j < 8; ++j) z += hsh[j] * w2[tid*8 + j];
        go[tid] = 1.0f / (1.0f + __expf(-z));
    }
}

// ---------------- E_s: M = co(128), N = n(128), K = m. Inline row sums. ---------
__global__ __launch_bounds__(256, 2) void attn_s_t(float* __restrict__ Es)
{
    const int b  = blockIdx.y;
    const int n0 = blockIdx.x * 128;
    const float* Ab = g_A  + (size_t)b*NPIX*NPIX;
    const float* vs = g_vs + (size_t)b*CC*NPIX;
    const float* st = g_st + (size_t)b*CC*NPIX;
    const float* gt = g_gs + b*CC;
    float* Eb = Es + (size_t)b*CC*NPIX;
    const float gm = fdekey(g_bmaxk[b]);
    __shared__ __align__(16) float As[2][ASZ];     // vs crosswise
    __shared__ __align__(16) float Bs[2][BSZ];     // exp(A) [k16][n128+pad]
    __shared__ float red2[2][128];
    __shared__ float rinv_s[128];
    const int tid = threadIdx.x, lane = tid & 31, wid = tid >> 5;
    const int wm = wid & 1, wn = wid >> 1;
    const int gid = lane >> 2, t4 = lane & 3;
    const int am = tid >> 1, aq0 = 2*(tid & 1), aq1 = aq0 + 1;
    const int bn = tid >> 1, bj = tid & 1;         // B: row bn, k-half bj*8
    float acc[4][4][4] = {};
    float rs = 0.f;
    float4 pa0, pa1, pb0, pb1;
    pa0 = *(const float4*)&vs[(size_t)am*NPIX + aq0*4];
    pa1 = *(const float4*)&vs[(size_t)am*NPIX + aq1*4];
    pb0 = *(const float4*)&Ab[(size_t)(n0+bn)*NPIX + bj*8];
    pb1 = *(const float4*)&Ab[(size_t)(n0+bn)*NPIX + bj*8 + 4];
    {
        stA(As[0], am, aq0, pa0); stA(As[0], am, aq1, pa1);
        float e[8];
        e[0]=__expf(pb0.x-gm); e[1]=__expf(pb0.y-gm); e[2]=__expf(pb0.z-gm); e[3]=__expf(pb0.w-gm);
        e[4]=__expf(pb1.x-gm); e[5]=__expf(pb1.y-gm); e[6]=__expf(pb1.z-gm); e[7]=__expf(pb1.w-gm);
#pragma unroll
        for (int j = 0; j < 8; ++j) { rs += e[j]; Bs[0][(bj*8+j)*136 + bn] = tf(e[j]); }
    }
    __syncthreads();
    const int iters = NPIX/16;
    for (int it = 0; it < iters; ++it) {
        if (it + 1 < iters) {
            int k0 = (it+1)*16;
            pa0 = *(const float4*)&vs[(size_t)am*NPIX + k0 + aq0*4];
            pa1 = *(const float4*)&vs[(size_t)am*NPIX + k0 + aq1*4];
            pb0 = *(const float4*)&Ab[(size_t)(n0+bn)*NPIX + k0 + bj*8];
            pb1 = *(const float4*)&Ab[(size_t)(n0+bn)*NPIX + k0 + bj*8 + 4];
        }
        mma_AB(acc, As[it & 1], Bs[it & 1], wm, wn, lane);
        if (it + 1 < iters) {
            int nb = (it+1) & 1;
            stA(As[nb], am, aq0, pa0); stA(As[nb], am, aq1, pa1);
            float e[8];
            e[0]=__expf(pb0.x-gm); e[1]=__expf(pb0.y-gm); e[2]=__expf(pb0.z-gm); e[3]=__expf(pb0.w-gm);
            e[4]=__expf(pb1.x-gm); e[5]=__expf(pb1.y-gm); e[6]=__expf(pb1.z-gm); e[7]=__expf(pb1.w-gm);
#pragma unroll
            for (int j = 0; j < 8; ++j) { rs += e[j]; Bs[nb][(bj*8+j)*136 + bn] = tf(e[j]); }
        }
        __syncthreads();
    }
    red2[bj][bn] = rs;
    __syncthreads();
    if (tid < 128) rinv_s[tid] = 1.0f / (red2[0][tid] + red2[1][tid]);
    __syncthreads();
#pragma unroll
    for (int mf = 0; mf < 4; ++mf)
#pragma unroll
        for (int h = 0; h < 2; ++h) {
            int co = wm*64 + mf*16 + gid + h*8;
            float g = gt[co];
#pragma unroll
            for (int nf = 0; nf < 4; ++nf) {
                int cl = wn*32 + nf*8 + t4*2;
                float2 res = *(const float2*)&st[(size_t)co*NPIX + n0 + cl];
                float2 r;
                r.x = g*acc[mf][nf][2*h+0]*rinv_s[cl]   + res.x;
                r.y = g*acc[mf][nf][2*h+1]*rinv_s[cl+1] + res.y;
                *(float2*)&Eb[(size_t)co*NPIX + n0 + cl] = r;
            }
        }
}

// ---------------- E_q: M = co(128), N = m(128), K = n. Inline col sums. ---------
__global__ __launch_bounds__(256, 2) void attn_q_t(float* __restrict__ Eq)
{
    const int b  = blockIdx.y;
    const int m0 = blockIdx.x * 128;
    const float* Ab = g_A  + (size_t)b*NPIX*NPIX;
    const float* vq = g_vq + (size_t)b*CC*NPIX;
    const float* qt = g_qt + (size_t)b*CC*NPIX;
    const float* gt = g_gq + b*CC;
    float* Eb = Eq + (size_t)b*CC*NPIX;
    const float gm = fdekey(g_bmaxk[b]);
    __shared__ __align__(16) float As[2][ASZ];     // vq crosswise
    __shared__ __align__(16) float Bs[2][BSZ];     // exp(A) [k16][m128+pad]
    __shared__ float red[16*132];
    __shared__ float cinv_s[128];
    const int tid = threadIdx.x, lane = tid & 31, wid = tid >> 5;
    const int wm = wid & 1, wn = wid >> 1;
    const int gid = lane >> 2, t4 = lane & 3;
    const int am = tid >> 1, aq0 = 2*(tid & 1), aq1 = aq0 + 1;
    const int bk = tid >> 4, mq = tid & 15;
    float acc[4][4][4] = {};
    float cs[2][4] = {};
    float4 pa0, pa1, pb0, pb1;
    pa0 = *(const float4*)&vq[(size_t)am*NPIX + aq0*4];
    pa1 = *(const float4*)&vq[(size_t)am*NPIX + aq1*4];
    pb0 = *(const float4*)&Ab[(size_t)bk*NPIX + m0 + mq*4];
    pb1 = *(const float4*)&Ab[(size_t)bk*NPIX + m0 + 64 + mq*4];
    {
        stA(As[0], am, aq0, pa0); stA(As[0], am, aq1, pa1);
        float4 e0, e1;
        e0.x=__expf(pb0.x-gm); e0.y=__expf(pb0.y-gm); e0.z=__expf(pb0.z-gm); e0.w=__expf(pb0.w-gm);
        e1.x=__expf(pb1.x-gm); e1.y=__expf(pb1.y-gm); e1.z=__expf(pb1.z-gm); e1.w=__expf(pb1.w-gm);
        cs[0][0]+=e0.x; cs[0][1]+=e0.y; cs[0][2]+=e0.z; cs[0][3]+=e0.w;
        cs[1][0]+=e1.x; cs[1][1]+=e1.y; cs[1][2]+=e1.z; cs[1][3]+=e1.w;
        *(float4*)&Bs[0][bk*136 + mq*4]      = tf4(e0);
        *(float4*)&Bs[0][bk*136 + 64 + mq*4] = tf4(e1);
    }
    __syncthreads();
    const int iters = NPIX/16;
    for (int it = 0; it < iters; ++it) {
        if (it + 1 < iters) {
            int k0 = (it+1)*16;
            pa0 = *(const float4*)&vq[(size_t)am*NPIX + k0 + aq0*4];
            pa1 = *(const float4*)&vq[(size_t)am*NPIX + k0 + aq1*4];
            pb0 = *(const float4*)&Ab[(size_t)(k0+bk)*NPIX + m0 + mq*4];
            pb1 = *(const float4*)&Ab[(size_t)(k0+bk)*NPIX + m0 + 64 + mq*4];
        }
        mma_AB(acc, As[it & 1], Bs[it & 1], wm, wn, lane);
        if (it + 1 < iters) {
            int nb = (it+1) & 1;
            stA(As[nb], am, aq0, pa0); stA(As[nb], am, aq1, pa1);
            float4 e0, e1;
            e0.x=__expf(pb0.x-gm); e0.y=__expf(pb0.y-gm); e0.z=__expf(pb0.z-gm); e0.w=__expf(pb0.w-gm);
            e1.x=__expf(pb1.x-gm); e1.y=__expf(pb1.y-gm); e1.z=__expf(pb1.z-gm); e1.w=__expf(pb1.w-gm);
            cs[0][0]+=e0.x; cs[0][1]+=e0.y; cs[0][2]+=e0.z; cs[0][3]+=e0.w;
            cs[1][0]+=e1.x; cs[1][1]+=e1.y; cs[1][2]+=e1.z; cs[1][3]+=e1.w;
            *(float4*)&Bs[nb][bk*136 + mq*4]      = tf4(e0);
            *(float4*)&Bs[nb][bk*136 + 64 + mq*4] = tf4(e1);
        }
        __syncthreads();
    }
#pragma unroll
    for (int j = 0; j < 4; ++j) {
        red[bk*132 + mq*4 + j]      = cs[0][j];
        red[bk*132 + 64 + mq*4 + j] = cs[1][j];
    }
    __syncthreads();
    if (tid < 128) {
        float s = 0.f;
#pragma unroll
        for (int i = 0; i < 16; ++i) s += red[i*132 + tid];
        cinv_s[tid] = 1.0f / s;
    }
    __syncthreads();
#pragma unroll
    for (int mf = 0; mf < 4; ++mf)
#pragma unroll
        for (int h = 0; h < 2; ++h) {
            int co = wm*64 + mf*16 + gid + h*8;
            float g = gt[co];
#pragma unroll
            for (int nf = 0; nf < 4; ++nf) {
                int cl = wn*32 + nf*8 + t4*2;
                float2 res = *(const float2*)&qt[(size_t)co*NPIX + m0 + cl];
                float2 r;
                r.x = g*acc[mf][nf][2*h+0]*cinv_s[cl]   + res.x;
                r.y = g*acc[mf][nf][2*h+1]*cinv_s[cl+1] + res.y;
                *(float2*)&Eb[(size_t)co*NPIX + m0 + cl] = r;
            }
        }
}

// ---------------- 3x3 conv (implicit GEMM) + BN + ReLU --------------------------
__global__ __launch_bounds__(256, 2) void conv_t(
    const float* __restrict__ cw, const float* __restrict__ cg,
    const float* __restrict__ cb, const float* __restrict__ cm,
    const float* __restrict__ cv,
    const float* __restrict__ Eq, const float* __restrict__ Es,
    float* __restrict__ feat)
{
    const int b  = blockIdx.y;
    const int p0 = blockIdx.x * 128;
    const float* Eqb = Eq + (size_t)b*CC*NPIX;
    const float* Esb = Es + (size_t)b*CC*NPIX;
    float* fb = feat + (size_t)b*CC*NPIX;
    __shared__ __align__(16) float As[2][ASZ];
    __shared__ __align__(16) float Bs[2][BSZ];
    const int tid = threadIdx.x, lane = tid & 31, wid = tid >> 5;
    const int wm = wid & 1, wn = wid >> 1;
    const int gid = lane >> 2, t4 = lane & 3;
    const int am = tid >> 1, aq0 = 2*(tid & 1), aq1 = aq0 + 1;
    const int bk = tid >> 4, mq = tid & 15;
    int hh[8], ww[8];
#pragma unroll
    for (int j = 0; j < 8; ++j) {
        int p = p0 + mq*4 + (j & 3) + (j >> 2)*64;
        hh[j] = p / 48; ww[j] = p - hh[j]*48;
    }
    auto loadB = [&](int k0, float4& v0, float4& v1) {
        int kap = k0 + bk;
        int ic = kap / 9, kk = kap - ic*9;
        int dh = kk/3 - 1, dw = kk - (kk/3)*3 - 1;
        const float* src = (ic < CC) ? Eqb : Esb;
        const float* sp = src + (size_t)(ic & (CC-1))*NPIX;
        float* v = (float*)&v0;
#pragma unroll
        for (int j = 0; j < 8; ++j) {
            int ih = hh[j] + dh, iw = ww[j] + dw;
            float val = ((unsigned)ih < 48u && (unsigned)iw < 48u)
                      ? sp[ih*48 + iw] : 0.f;
            if (j < 4) v[j] = val; else ((float*)&v1)[j-4] = val;
        }
    };
    float acc[4][4][4] = {};
    float4 pa0, pa1, pb0, pb1;
    pa0 = *(const float4*)&cw[am*2304 + aq0*4];
    pa1 = *(const float4*)&cw[am*2304 + aq1*4];
    loadB(0, pb0, pb1);
    stA(As[0], am, aq0, pa0); stA(As[0], am, aq1, pa1);
    *(float4*)&Bs[0][bk*136 + mq*4]      = tf4(pb0);
    *(float4*)&Bs[0][bk*136 + 64 + mq*4] = tf4(pb1);
    __syncthreads();
    for (int it = 0; it < 144; ++it) {
        if (it + 1 < 144) {
            int k0 = (it+1)*16;
            pa0 = *(const float4*)&cw[am*2304 + k0 + aq0*4];
            pa1 = *(const float4*)&cw[am*2304 + k0 + aq1*4];
            loadB(k0, pb0, pb1);
        }
        mma_AB(acc, As[it & 1], Bs[it & 1], wm, wn, lane);
        if (it + 1 < 144) {
            int nb = (it+1) & 1;
            stA(As[nb], am, aq0, pa0); stA(As[nb], am, aq1, pa1);
            *(float4*)&Bs[nb][bk*136 + mq*4]      = tf4(pb0);
            *(float4*)&Bs[nb][bk*136 + 64 + mq*4] = tf4(pb1);
        }
        __syncthreads();
    }
#pragma unroll
    for (int mf = 0; mf < 4; ++mf)
#pragma unroll
        for (int h = 0; h < 2; ++h) {
            int o = wm*64 + mf*16 + gid + h*8;
            float sc  = cg[o] * rsqrtf(cv[o] + EPSB);
            float cbv = cb[o] - cm[o]*sc;
#pragma unroll
            for (int nf = 0; nf < 4; ++nf) {
                int cl = wn*32 + nf*8 + t4*2;
                float2 r;
                r.x = fmaxf(acc[mf][nf][2*h+0]*sc + cbv, 0.f);
                r.y = fmaxf(acc[mf][nf][2*h+1]*sc + cbv, 0.f);
                *(float2*)&fb[(size_t)o*NPIX + p0 + cl] = r;
            }
        }
}

// ---------------- host ----------------------------------------------------------
extern "C" void kernel_launch(void* const* d_in, const int* in_sizes, int n_in,
                              void* d_out, int out_size)
{
    (void)in_sizes; (void)n_in; (void)out_size;
    const float* q    = (const float*)d_in[0];
    const float* s    = (const float*)d_in[1];
    const float* tsw  = (const float*)d_in[2];
    const float* tsb  = (const float*)d_in[3];
    const float* bsg  = (const float*)d_in[4];
    const float* bsb  = (const float*)d_in[5];
    const float* bsm  = (const float*)d_in[6];
    const float* bsv  = (const float*)d_in[7];
    const float* tqw  = (const float*)d_in[8];
    const float* tqb  = (const float*)d_in[9];
    const float* bqg  = (const float*)d_in[10];
    const float* bqb  = (const float*)d_in[11];
    const float* bqm  = (const float*)d_in[12];
    const float* bqv  = (const float*)d_in[13];
    const float* vqw  = (const float*)d_in[14];
    const float* vqb  = (const float*)d_in[15];
    const float* vsw  = (const float*)d_in[16];
    const float* vsb  = (const float*)d_in[17];
    const float* keyw = (const float*)d_in[18];
    const float* keyb = (const float*)d_in[19];
    const float* qryw = (const float*)d_in[20];
    const float* qryb = (const float*)d_in[21];
    const float* gw1  = (const float*)d_in[22];
    const float* gb1  = (const float*)d_in[23];
    const float* gw2  = (const float*)d_in[24];
    const float* gb2  = (const float*)d_in[25];
    const float* cw   = (const float*)d_in[26];
    const float* cg   = (const float*)d_in[27];
    const float* cb   = (const float*)d_in[28];
    const float* cm   = (const float*)d_in[29];
    const float* cv   = (const float*)d_in[30];

    float *p_qt, *p_st, *p_vq, *p_vs, *p_kx, *p_qx;
    cudaGetSymbolAddress((void**)&p_qt, g_qt);
    cudaGetSymbolAddress((void**)&p_st, g_st);
    cudaGetSymbolAddress((void**)&p_vq, g_vq);
    cudaGetSymbolAddress((void**)&p_vs, g_vs);
    cudaGetSymbolAddress((void**)&p_kx, g_kx);
    cudaGetSymbolAddress((void**)&p_qx, g_qx);

    float* feat = (float*)d_out;
    float* Eq   = feat + (size_t)BATCH*CC*NPIX;
    float* Es   = Eq   + (size_t)BATCH*CC*NPIX;

    dim3 g18(18, BATCH);

    init_bmax<<<1, 32>>>();
    gemm_wx_t<<<g18, 256>>>(q, tqw, tqb, bqg, bqb, bqm, bqv, p_qt, CIN);
    gemm_wx_t<<<g18, 256>>>(s, tsw, tsb, bsg, bsb, bsm, bsv, p_st, CIN);
    gemm_wx_t<<<g18, 256>>>(p_qt, vqw,  vqb,  0, 0, 0, 0, p_vq, CC);
    gemm_wx_t<<<g18, 256>>>(p_qt, qryw, qryb, 0, 0, 0, 0, p_qx, CC);
    gemm_wx_t<<<g18, 256>>>(p_st, vsw,  vsb,  0, 0, 0, 0, p_vs, CC);
    gemm_wx_t<<<g18, 256>>>(p_st, keyw, keyb, 0, 0, 0, 0, p_kx, CC);

    score_t<<<dim3(18, 18, BATCH), 256>>>();
    gate_kernel<<<dim3(2, BATCH), 256>>>(gw1, gb1, gw2, gb2);

    attn_s_t<<<g18, 256>>>(Es);
    attn_q_t<<<g18, 256>>>(Eq);

    conv_t<<<g18, 256>>>(cw, cg, cb, cm, cv, Eq, Es, feat);
}

// round 6
// speedup vs baseline: 2.8132x; 1.2497x over previous
#include <cuda_runtime.h>
#include <cuda_bf16.h>

#define BATCH 8
#define CIN   256
#define CC    128
#define NPIX  2304
#define EPSB  1e-5f

// ---------------- scratch ------------------------------------------------------
__device__ __align__(16) float g_qt[BATCH*CC*NPIX];
__device__ __align__(16) float g_st[BATCH*CC*NPIX];
__device__ __align__(16) float g_vq[BATCH*CC*NPIX];
__device__ __align__(16) float g_vs[BATCH*CC*NPIX];
__device__ __align__(16) float g_kx[BATCH*CC*NPIX];
__device__ __align__(16) float g_qx[BATCH*CC*NPIX];
__device__ __align__(16) unsigned short g_e[(size_t)BATCH*NPIX*NPIX]; // bf16 exp(A-lm)
__device__ float g_tmax[BATCH*18*18];
__device__ unsigned g_bmaxk[BATCH];
__device__ float g_poolq[BATCH*18*CC];
__device__ float g_pools[BATCH*18*CC];
__device__ float g_gq[BATCH*CC];
__device__ float g_gs[BATCH*CC];

// ---------------- helpers ------------------------------------------------------
__device__ __forceinline__ float tf(float x) {
    unsigned u;
    asm("cvt.rna.tf32.f32 %0, %1;" : "=r"(u) : "f"(x));
    return __uint_as_float(u);
}
__device__ __forceinline__ float4 tf4(float4 v) {
    v.x = tf(v.x); v.y = tf(v.y); v.z = tf(v.z); v.w = tf(v.w); return v;
}
__device__ __forceinline__ unsigned fkey(float x) {
    int i = __float_as_int(x);
    return (i >= 0) ? ((unsigned)i | 0x80000000u) : ~(unsigned)i;
}
__device__ __forceinline__ float fdekey(unsigned u) {
    int i = (u & 0x80000000u) ? (int)(u & 0x7fffffffu) : ~(int)u;
    return __int_as_float(i);
}
__device__ __forceinline__ unsigned packbf(float a, float b) {
    __nv_bfloat162 h = __floats2bfloat162_rn(a, b);   // .x = a (low), .y = b (high)
    return *(unsigned*)&h;
}
__device__ __forceinline__ float2 unpackbf(unsigned u) {
    return __bfloat1622float2(*(__nv_bfloat162*)&u);
}
__device__ __forceinline__ int cpos(int j) { return ((j & 3) << 2) | (j >> 2); }

__device__ __forceinline__ void mma_tf32(float* c,
    unsigned a0, unsigned a1, unsigned a2, unsigned a3, unsigned b0, unsigned b1)
{
    asm volatile(
        "mma.sync.aligned.m16n8k8.row.col.f32.tf32.tf32.f32 "
        "{%0,%1,%2,%3}, {%4,%5,%6,%7}, {%8,%9}, {%0,%1,%2,%3};"
        : "+f"(c[0]), "+f"(c[1]), "+f"(c[2]), "+f"(c[3])
        : "r"(a0), "r"(a1), "r"(a2), "r"(a3), "r"(b0), "r"(b1));
}
__device__ __forceinline__ void mma_bf16(float* c,
    unsigned a0, unsigned a1, unsigned a2, unsigned a3, unsigned b0, unsigned b1)
{
    asm volatile(
        "mma.sync.aligned.m16n8k16.row.col.f32.bf16.bf16.f32 "
        "{%0,%1,%2,%3}, {%4,%5,%6,%7}, {%8,%9}, {%0,%1,%2,%3};"
        : "+f"(c[0]), "+f"(c[1]), "+f"(c[2]), "+f"(c[3])
        : "r"(a0), "r"(a1), "r"(a2), "r"(a3), "r"(b0), "r"(b1));
}

// ---- fp32/tf32 path (gemm, score, conv): block 128x128x16, warp 64x32 ---------
__device__ __forceinline__ void mma_AB(float acc[4][4][4],
    const float* As, const float* Bs, int wm, int wn, int lane)
{
    const int gid = lane >> 2, t4 = lane & 3;
    const float4* As4 = (const float4*)As;
    float4 va[4][2];
#pragma unroll
    for (int mf = 0; mf < 4; ++mf) {
        int rb = wm*64 + mf*16 + gid;
        va[mf][0] = As4[rb*5 + t4];
        va[mf][1] = As4[(rb+8)*5 + t4];
    }
#pragma unroll
    for (int ko = 0; ko < 2; ++ko) {
        unsigned bf[4][2];
#pragma unroll
        for (int nf = 0; nf < 4; ++nf) {
            int nb = wn*32 + nf*8 + gid;
            bf[nf][0] = __float_as_uint(Bs[(ko*8+t4  )*136 + nb]);
            bf[nf][1] = __float_as_uint(Bs[(ko*8+t4+4)*136 + nb]);
        }
#pragma unroll
        for (int mf = 0; mf < 4; ++mf) {
            unsigned a0, a1, a2, a3;
            if (ko == 0) {
                a0 = __float_as_uint(va[mf][0].x); a1 = __float_as_uint(va[mf][1].x);
                a2 = __float_as_uint(va[mf][0].y); a3 = __float_as_uint(va[mf][1].y);
            } else {
                a0 = __float_as_uint(va[mf][0].z); a1 = __float_as_uint(va[mf][1].z);
                a2 = __float_as_uint(va[mf][0].w); a3 = __float_as_uint(va[mf][1].w);
            }
#pragma unroll
            for (int nf = 0; nf < 4; ++nf)
                mma_tf32(acc[mf][nf], a0, a1, a2, a3, bf[nf][0], bf[nf][1]);
        }
    }
}
__device__ __forceinline__ void stA(float* As, int m, int aq, float4 v) {
    float* p = &As[m*20 + aq];
    p[0] = tf(v.x); p[4] = tf(v.y); p[8] = tf(v.z); p[12] = tf(v.w);
}

// ---- bf16 path (attention apply): block 128x128x32, warp 64x32 ----------------
// A and B both crosswise-uint [row][16 kpairs], stride 20 uints.
__device__ __forceinline__ void mma_AB16(float acc[4][4][4],
    const unsigned* As, const unsigned* Bs, int wm, int wn, int lane)
{
    const int gid = lane >> 2, t4 = lane & 3;
    const uint4* A4 = (const uint4*)As;
    const uint4* B4 = (const uint4*)Bs;
    uint4 va[4][2], vb[4];
#pragma unroll
    for (int mf = 0; mf < 4; ++mf) {
        int rb = wm*64 + mf*16 + gid;
        va[mf][0] = A4[rb*5 + t4];
        va[mf][1] = A4[(rb+8)*5 + t4];
    }
#pragma unroll
    for (int nf = 0; nf < 4; ++nf) {
        int nb = wn*32 + nf*8 + gid;
        vb[nf] = B4[nb*5 + t4];
    }
#pragma unroll
    for (int mf = 0; mf < 4; ++mf)
#pragma unroll
        for (int nf = 0; nf < 4; ++nf)
            mma_bf16(acc[mf][nf], va[mf][0].x, va[mf][1].x, va[mf][0].y, va[mf][1].y,
                     vb[nf].x, vb[nf].y);
#pragma unroll
    for (int mf = 0; mf < 4; ++mf)
#pragma unroll
        for (int nf = 0; nf < 4; ++nf)
            mma_bf16(acc[mf][nf], va[mf][0].z, va[mf][1].z, va[mf][0].w, va[mf][1].w,
                     vb[nf].z, vb[nf].w);
}

#define ASZ (128*20)
#define BSZ (16*136)

__global__ void init_bmax() { if (threadIdx.x < BATCH) g_bmaxk[threadIdx.x] = 0u; }

// ---------------- 1x1 conv GEMM (+BN, + optional pool partials) -----------------
__global__ __launch_bounds__(256, 2) void gemm_wx_t(
    const float* __restrict__ x, const float* __restrict__ w,
    const float* __restrict__ bias,
    const float* __restrict__ bng, const float* __restrict__ bnb,
    const float* __restrict__ bnm, const float* __restrict__ bnv,
    float* __restrict__ out, int K, float* __restrict__ poolpart)
{
    const int b  = blockIdx.y;
    const int p0 = blockIdx.x * 128;
    const float* xb = x + (size_t)b*K*NPIX;
    float* ob = out + (size_t)b*CC*NPIX;
    __shared__ __align__(16) float As[2][ASZ];
    __shared__ __align__(16) float Bs[2][BSZ];
    const int tid = threadIdx.x, lane = tid & 31, wid = tid >> 5;
    const int wm = wid & 1, wn = wid >> 1;
    const int gid = lane >> 2, t4 = lane & 3;
    const int am = tid >> 1, aq0 = 2*(tid & 1), aq1 = aq0 + 1;
    const int bk = tid >> 4, bq = tid & 15;
    float acc[4][4][4] = {};
    float4 pa0, pa1, pb0, pb1;
    pa0 = *(const float4*)&w[am*K + aq0*4];
    pa1 = *(const float4*)&w[am*K + aq1*4];
    pb0 = *(const float4*)&xb[(size_t)bk*NPIX + p0 + bq*4];
    pb1 = *(const float4*)&xb[(size_t)bk*NPIX + p0 + 64 + bq*4];
    stA(As[0], am, aq0, pa0); stA(As[0], am, aq1, pa1);
    *(float4*)&Bs[0][bk*136 + bq*4]      = tf4(pb0);
    *(float4*)&Bs[0][bk*136 + 64 + bq*4] = tf4(pb1);
    __syncthreads();
    const int iters = K / 16;
    for (int it = 0; it < iters; ++it) {
        if (it + 1 < iters) {
            int k0 = (it+1)*16;
            pa0 = *(const float4*)&w[am*K + k0 + aq0*4];
            pa1 = *(const float4*)&w[am*K + k0 + aq1*4];
            pb0 = *(const float4*)&xb[(size_t)(k0+bk)*NPIX + p0 + bq*4];
            pb1 = *(const float4*)&xb[(size_t)(k0+bk)*NPIX + p0 + 64 + bq*4];
        }
        mma_AB(acc, As[it & 1], Bs[it & 1], wm, wn, lane);
        if (it + 1 < iters) {
            int nb = (it+1) & 1;
            stA(As[nb], am, aq0, pa0); stA(As[nb], am, aq1, pa1);
            *(float4*)&Bs[nb][bk*136 + bq*4]      = tf4(pb0);
            *(float4*)&Bs[nb][bk*136 + 64 + bq*4] = tf4(pb1);
        }
        __syncthreads();
    }
    float rsum[8];
#pragma unroll
    for (int mf = 0; mf < 4; ++mf)
#pragma unroll
        for (int h = 0; h < 2; ++h) {
            int o = wm*64 + mf*16 + gid + h*8;
            float sc = 1.0f, cb = bias[o];
            if (bng) {
                sc = bng[o] * rsqrtf(bnv[o] + EPSB);
                cb = (bias[o] - bnm[o]) * sc + bnb[o];
            }
            float sm = 0.f;
#pragma unroll
            for (int nf = 0; nf < 4; ++nf) {
                int cl = wn*32 + nf*8 + t4*2;
                float2 r;
                r.x = acc[mf][nf][2*h+0]*sc + cb;
                r.y = acc[mf][nf][2*h+1]*sc + cb;
                sm += r.x + r.y;
                *(float2*)&ob[(size_t)o*NPIX + p0 + cl] = r;
            }
            rsum[mf*2+h] = sm;
        }
    if (poolpart) {
        float* redp = (float*)As;   // 512 floats, reuse smem
        __syncthreads();
#pragma unroll
        for (int j = 0; j < 8; ++j) {
            float v = rsum[j];
            v += __shfl_xor_sync(~0u, v, 1);
            v += __shfl_xor_sync(~0u, v, 2);
            if (t4 == 0) {
                int row = wm*64 + (j>>1)*16 + gid + (j&1)*8;
                redp[wn*128 + row] = v;
            }
        }
        __syncthreads();
        if (tid < 128)
            poolpart[((size_t)b*18 + blockIdx.x)*CC + tid] =
                redp[tid] + redp[128+tid] + redp[256+tid] + redp[384+tid];
    }
}

// ---------------- score: e[n][m] = bf16(exp(A - blkmax)); track maxima ----------
__global__ __launch_bounds__(256, 2) void score_t()
{
    const int b  = blockIdx.z;
    const int n0 = blockIdx.y * 128;
    const int m0 = blockIdx.x * 128;
    const float* kx = g_kx + (size_t)b*CC*NPIX;
    const float* qx = g_qx + (size_t)b*CC*NPIX;
    unsigned short* eb = g_e + (size_t)b*NPIX*NPIX;
    __shared__ __align__(16) float As[2][BSZ];   // kx [k16][n128+pad]
    __shared__ __align__(16) float Bs[2][BSZ];   // qx [k16][m128+pad]
    __shared__ float smax[8];
    const int tid = threadIdx.x, lane = tid & 31, wid = tid >> 5;
    const int wm = wid & 1, wn = wid >> 1;
    const int gid = lane >> 2, t4 = lane & 3;
    const int ak = tid >> 4, aq = tid & 15;
    float acc[4][4][4] = {};
    float4 pa0, pa1, pb0, pb1;
    pa0 = *(const float4*)&kx[(size_t)ak*NPIX + n0 + aq*4];
    pa1 = *(const float4*)&kx[(size_t)ak*NPIX + n0 + 64 + aq*4];
    pb0 = *(const float4*)&qx[(size_t)ak*NPIX + m0 + aq*4];
    pb1 = *(const float4*)&qx[(size_t)ak*NPIX + m0 + 64 + aq*4];
    *(float4*)&As[0][ak*136 + aq*4]      = tf4(pa0);
    *(float4*)&As[0][ak*136 + 64 + aq*4] = tf4(pa1);
    *(float4*)&Bs[0][ak*136 + aq*4]      = tf4(pb0);
    *(float4*)&Bs[0][ak*136 + 64 + aq*4] = tf4(pb1);
    __syncthreads();
    for (int it = 0; it < CC/16; ++it) {
        if (it + 1 < CC/16) {
            int k0 = (it+1)*16;
            pa0 = *(const float4*)&kx[(size_t)(k0+ak)*NPIX + n0 + aq*4];
            pa1 = *(const float4*)&kx[(size_t)(k0+ak)*NPIX + n0 + 64 + aq*4];
            pb0 = *(const float4*)&qx[(size_t)(k0+ak)*NPIX + m0 + aq*4];
            pb1 = *(const float4*)&qx[(size_t)(k0+ak)*NPIX + m0 + 64 + aq*4];
        }
        {
            const float* Asb = As[it & 1];
            const float* Bsb = Bs[it & 1];
#pragma unroll
            for (int ko = 0; ko < 2; ++ko) {
                unsigned bf[4][2];
#pragma unroll
                for (int nf = 0; nf < 4; ++nf) {
                    int nb = wn*32 + nf*8 + gid;
                    bf[nf][0] = __float_as_uint(Bsb[(ko*8+t4  )*136 + nb]);
                    bf[nf][1] = __float_as_uint(Bsb[(ko*8+t4+4)*136 + nb]);
                }
#pragma unroll
                for (int mf = 0; mf < 4; ++mf) {
                    int rb = wm*64 + mf*16 + gid;
                    unsigned a0 = __float_as_uint(Asb[(ko*8+t4  )*136 + rb]);
                    unsigned a1 = __float_as_uint(Asb[(ko*8+t4  )*136 + rb+8]);
                    unsigned a2 = __float_as_uint(Asb[(ko*8+t4+4)*136 + rb]);
                    unsigned a3 = __float_as_uint(Asb[(ko*8+t4+4)*136 + rb+8]);
#pragma unroll
                    for (int nf = 0; nf < 4; ++nf)
                        mma_tf32(acc[mf][nf], a0, a1, a2, a3, bf[nf][0], bf[nf][1]);
                }
            }
        }
        if (it + 1 < CC/16) {
            int nb = (it+1) & 1;
            *(float4*)&As[nb][ak*136 + aq*4]      = tf4(pa0);
            *(float4*)&As[nb][ak*136 + 64 + aq*4] = tf4(pa1);
            *(float4*)&Bs[nb][ak*136 + aq*4]      = tf4(pb0);
            *(float4*)&Bs[nb][ak*136 + 64 + aq*4] = tf4(pb1);
        }
        __syncthreads();
    }
    float mx = -1e30f;
#pragma unroll
    for (int mf = 0; mf < 4; ++mf)
#pragma unroll
        for (int nf = 0; nf < 4; ++nf)
#pragma unroll
            for (int v = 0; v < 4; ++v) mx = fmaxf(mx, acc[mf][nf][v]);
#pragma unroll
    for (int o = 16; o; o >>= 1) mx = fmaxf(mx, __shfl_xor_sync(~0u, mx, o));
    if (lane == 0) smax[wid] = mx;
    __syncthreads();
    float lm = smax[0];
#pragma unroll
    for (int j = 1; j < 8; ++j) lm = fmaxf(lm, smax[j]);
#pragma unroll
    for (int mf = 0; mf < 4; ++mf)
#pragma unroll
        for (int h = 0; h < 2; ++h) {
            int n = n0 + wm*64 + mf*16 + gid + h*8;
#pragma unroll
            for (int nf = 0; nf < 4; ++nf) {
                int cl = wn*32 + nf*8 + t4*2;
                unsigned u = packbf(__expf(acc[mf][nf][2*h+0] - lm),
                                    __expf(acc[mf][nf][2*h+1] - lm));
                *(unsigned*)(eb + (size_t)n*NPIX + m0 + cl) = u;
            }
        }
    if (tid == 0) {
        g_tmax[(b*18 + blockIdx.y)*18 + blockIdx.x] = lm;
        atomicMax(&g_bmaxk[b], fkey(lm));
    }
}

// ---------------- channel gate (from pooled partials) ---------------------------
__global__ __launch_bounds__(128) void gate_kernel(
    const float* __restrict__ w1, const float* __restrict__ b1,
    const float* __restrict__ w2, const float* __restrict__ b2)
{
    const int b = blockIdx.y;
    const float* pp = (blockIdx.x == 0 ? g_poolq : g_pools) + (size_t)b*18*CC;
    float* go = (blockIdx.x == 0 ? g_gq : g_gs) + b*CC;
    __shared__ float pool[CC];
    __shared__ float hsh[8];
    const int tid = threadIdx.x;
    {
        float s = 0.f;
#pragma unroll
        for (int j = 0; j < 18; ++j) s += pp[j*CC + tid];
        pool[tid] = s * (1.0f/NPIX);
    }
    __syncthreads();
    if (tid < 8) {
        float h = b1[tid];
        for (int i = 0; i < CC; ++i) h += pool[i] * w1[tid*CC + i];
        hsh[tid] = fmaxf(h, 0.f);
    }
    __syncthreads();
    float z = b2[tid];
#pragma unroll
    for (int j = 0; j < 8; ++j) z += hsh[j] * w2[tid*8 + j];
    go[tid] = 1.0f / (1.0f + __expf(-z));
}

// ---------------- E_s (bf16): M=co, N=n(128), K=m. Inline row sums. -------------
__global__ __launch_bounds__(256) void attn_s_t(float* __restrict__ Es)
{
    const int b  = blockIdx.y;
    const int n0 = blockIdx.x * 128;
    const unsigned short* eb = g_e + (size_t)b*NPIX*NPIX;
    const float* vs = g_vs + (size_t)b*CC*NPIX;
    const float* st = g_st + (size_t)b*CC*NPIX;
    const float* gt = g_gs + b*CC;
    float* Eb = Es + (size_t)b*CC*NPIX;
    __shared__ unsigned As[2][ASZ];
    __shared__ unsigned Bs[2][ASZ];
    __shared__ float corr_sh[18];
    __shared__ float red2[2][128];
    __shared__ float rinv_s[128];
    const int tid = threadIdx.x, lane = tid & 31, wid = tid >> 5;
    const int wm = wid & 1, wn = wid >> 1;
    const int gid = lane >> 2, t4 = lane & 3;
    const int am = tid >> 1, half = tid & 1;
    const float bmax = fdekey(g_bmaxk[b]);
    if (tid < 18)
        corr_sh[tid] = __expf(g_tmax[(b*18 + blockIdx.x)*18 + tid] - bmax);
    __syncthreads();
    const float* arow = vs + (size_t)am*NPIX + half*16;
    const unsigned* erow = (const unsigned*)(eb + (size_t)(n0+am)*NPIX) + half*8;
    float acc[4][4][4] = {};
    float rs = 0.f;
    float4 pa[4]; uint4 pb[2];
#pragma unroll
    for (int i = 0; i < 4; ++i) pa[i] = *(const float4*)&arow[i*4];
    pb[0] = *(const uint4*)&erow[0]; pb[1] = *(const uint4*)&erow[4];

    auto store = [&](int buf, float corr) {
#pragma unroll
        for (int i = 0; i < 4; ++i) {
            int j = half*8 + i*2;
            As[buf][am*20 + cpos(j)]   = packbf(pa[i].x*corr, pa[i].y*corr);
            As[buf][am*20 + cpos(j+1)] = packbf(pa[i].z*corr, pa[i].w*corr);
        }
        float rst = 0.f;
#pragma unroll
        for (int i = 0; i < 2; ++i) {
            unsigned uu[4] = {pb[i].x, pb[i].y, pb[i].z, pb[i].w};
#pragma unroll
            for (int c = 0; c < 4; ++c) {
                int j = half*8 + i*4 + c;
                Bs[buf][am*20 + cpos(j)] = uu[c];
                float2 f = unpackbf(uu[c]);
                rst += f.x + f.y;
            }
        }
        rs += corr * rst;
    };
    store(0, corr_sh[0]);
    __syncthreads();
    const int iters = NPIX/32;
    for (int it = 0; it < iters; ++it) {
        if (it + 1 < iters) {
            int k0 = (it+1)*32;
#pragma unroll
            for (int i = 0; i < 4; ++i) pa[i] = *(const float4*)&arow[k0 + i*4];
            pb[0] = *(const uint4*)&erow[k0/2];
            pb[1] = *(const uint4*)&erow[k0/2 + 4];
        }
        mma_AB16(acc, As[it & 1], Bs[it & 1], wm, wn, lane);
        if (it + 1 < iters) store((it+1) & 1, corr_sh[(it+1) >> 2]);
        __syncthreads();
    }
    red2[half][am] = rs;
    __syncthreads();
    if (tid < 128) rinv_s[tid] = 1.0f / (red2[0][tid] + red2[1][tid]);
    __syncthreads();
#pragma unroll
    for (int mf = 0; mf < 4; ++mf)
#pragma unroll
        for (int h = 0; h < 2; ++h) {
            int co = wm*64 + mf*16 + gid + h*8;
            float g = gt[co];
#pragma unroll
            for (int nf = 0; nf < 4; ++nf) {
                int cl = wn*32 + nf*8 + t4*2;
                float2 res = *(const float2*)&st[(size_t)co*NPIX + n0 + cl];
                float2 r;
                r.x = g*acc[mf][nf][2*h+0]*rinv_s[cl]   + res.x;
                r.y = g*acc[mf][nf][2*h+1]*rinv_s[cl+1] + res.y;
                *(float2*)&Eb[(size_t)co*NPIX + n0 + cl] = r;
            }
        }
}

// ---------------- E_q (bf16): M=co, N=m(128), K=n. Inline col sums. -------------
__global__ __launch_bounds__(256) void attn_q_t(float* __restrict__ Eq)
{
    const int b  = blockIdx.y;
    const int m0 = blockIdx.x * 128;
    const unsigned short* eb = g_e + (size_t)b*NPIX*NPIX;
    const float* vq = g_vq + (size_t)b*CC*NPIX;
    const float* qt = g_qt + (size_t)b*CC*NPIX;
    const float* gt = g_gq + b*CC;
    float* Eb = Eq + (size_t)b*CC*NPIX;
    __shared__ unsigned As[2][ASZ];
    __shared__ unsigned Bs[2][ASZ];
    __shared__ float corr_sh[18];
    __shared__ float cinv_s[128];
    const int tid = threadIdx.x, lane = tid & 31, wid = tid >> 5;
    const int wm = wid & 1, wn = wid >> 1;
    const int gid = lane >> 2, t4 = lane & 3;
    const int am = tid >> 1, half = tid & 1;
    const int np = tid >> 4, mseg = tid & 15;
    const float bmax = fdekey(g_bmaxk[b]);
    if (tid < 18)
        corr_sh[tid] = __expf(g_tmax[(b*18 + tid)*18 + blockIdx.x] - bmax);
    __syncthreads();
    const float* arow = vq + (size_t)am*NPIX + half*16;
    const int ppos = cpos(np);
    float acc[4][4][4] = {};
    float cs[8] = {};
    float4 pa[4]; uint4 pb0, pb1;
#pragma unroll
    for (int i = 0; i < 4; ++i) pa[i] = *(const float4*)&arow[i*4];
    {
        const unsigned* r0 = (const unsigned*)(eb + (size_t)(2*np  )*NPIX + m0);
        const unsigned* r1 = (const unsigned*)(eb + (size_t)(2*np+1)*NPIX + m0);
        pb0 = *(const uint4*)&r0[mseg*4];
        pb1 = *(const uint4*)&r1[mseg*4];
    }
    auto store = [&](int buf, float corr) {
#pragma unroll
        for (int i = 0; i < 4; ++i) {
            int j = half*8 + i*2;
            As[buf][am*20 + cpos(j)]   = packbf(pa[i].x*corr, pa[i].y*corr);
            As[buf][am*20 + cpos(j+1)] = packbf(pa[i].z*corr, pa[i].w*corr);
        }
        unsigned u0[4] = {pb0.x, pb0.y, pb0.z, pb0.w};
        unsigned u1[4] = {pb1.x, pb1.y, pb1.z, pb1.w};
#pragma unroll
        for (int jj = 0; jj < 4; ++jj) {
            unsigned q0 = __byte_perm(u0[jj], u1[jj], 0x5410);
            unsigned q1 = __byte_perm(u0[jj], u1[jj], 0x7632);
            int ml = mseg*8 + 2*jj;
            Bs[buf][ml*20 + ppos]     = q0;
            Bs[buf][(ml+1)*20 + ppos] = q1;
            float2 f0 = unpackbf(q0), f1 = unpackbf(q1);
            cs[2*jj]   += corr * (f0.x + f0.y);
            cs[2*jj+1] += corr * (f1.x + f1.y);
        }
    };
    store(0, corr_sh[0]);
    __syncthreads();
    const int iters = NPIX/32;
    for (int it = 0; it < iters; ++it) {
        if (it + 1 < iters) {
            int k0 = (it+1)*32;
#pragma unroll
            for (int i = 0; i < 4; ++i) pa[i] = *(const float4*)&arow[k0 + i*4];
            const unsigned* r0 = (const unsigned*)(eb + (size_t)(k0+2*np  )*NPIX + m0);
            const unsigned* r1 = (const unsigned*)(eb + (size_t)(k0+2*np+1)*NPIX + m0);
            pb0 = *(const uint4*)&r0[mseg*4];
            pb1 = *(const uint4*)&r1[mseg*4];
        }
        mma_AB16(acc, As[it & 1], Bs[it & 1], wm, wn, lane);
        if (it + 1 < iters) store((it+1) & 1, corr_sh[(it+1) >> 2]);
        __syncthreads();
    }
    float* red = (float*)Bs[0];   // reuse, 16x128
#pragma unroll
    for (int j = 0; j < 8; ++j) red[np*128 + mseg*8 + j] = cs[j];
    __syncthreads();
    if (tid < 128) {
        float s = 0.f;
#pragma unroll
        for (int i = 0; i < 16; ++i) s += red[i*128 + tid];
        cinv_s[tid] = 1.0f / s;
    }
    __syncthreads();
#pragma unroll
    for (int mf = 0; mf < 4; ++mf)
#pragma unroll
        for (int h = 0; h < 2; ++h) {
            int co = wm*64 + mf*16 + gid + h*8;
            float g = gt[co];
#pragma unroll
            for (int nf = 0; nf < 4; ++nf) {
                int cl = wn*32 + nf*8 + t4*2;
                float2 res = *(const float2*)&qt[(size_t)co*NPIX + m0 + cl];
                float2 r;
                r.x = g*acc[mf][nf][2*h+0]*cinv_s[cl]   + res.x;
                r.y = g*acc[mf][nf][2*h+1]*cinv_s[cl+1] + res.y;
                *(float2*)&Eb[(size_t)co*NPIX + m0 + cl] = r;
            }
        }
}

// ---------------- 3x3 conv (tf32 implicit GEMM) + BN + ReLU ---------------------
__global__ __launch_bounds__(256) void conv_t(
    const float* __restrict__ cw, const float* __restrict__ cg,
    const float* __restrict__ cb, const float* __restrict__ cm,
    const float* __restrict__ cv,
    const float* __restrict__ Eq, const float* __restrict__ Es,
    float* __restrict__ feat)
{
    const int b  = blockIdx.y;
    const int p0 = blockIdx.x * 128;
    const float* Eqb = Eq + (size_t)b*CC*NPIX;
    const float* Esb = Es + (size_t)b*CC*NPIX;
    float* fb = feat + (size_t)b*CC*NPIX;
    __shared__ __align__(16) float As[2][ASZ];
    __shared__ __align__(16) float Bs[2][BSZ];
    const int tid = threadIdx.x, lane = tid & 31, wid = tid >> 5;
    const int wm = wid & 1, wn = wid >> 1;
    const int gid = lane >> 2, t4 = lane & 3;
    const int am = tid >> 1, aq0 = 2*(tid & 1), aq1 = aq0 + 1;
    const int bk = tid >> 4, mq = tid & 15;
    int hh[8], ww[8];
#pragma unroll
    for (int j = 0; j < 8; ++j) {
        int p = p0 + mq*4 + (j & 3) + (j >> 2)*64;
        hh[j] = p / 48; ww[j] = p - hh[j]*48;
    }
    auto loadB = [&](int k0, float4& v0, float4& v1) {
        int kap = k0 + bk;
        int ic = kap / 9, kk = kap - ic*9;
        int dh = kk/3 - 1, dw = kk - (kk/3)*3 - 1;
        const float* src = (ic < CC) ? Eqb : Esb;
        const float* sp = src + (size_t)(ic & (CC-1))*NPIX;
        float* v = (float*)&v0;
#pragma unroll
        for (int j = 0; j < 8; ++j) {
            int ih = hh[j] + dh, iw = ww[j] + dw;
            float val = ((unsigned)ih < 48u && (unsigned)iw < 48u)
                      ? sp[ih*48 + iw] : 0.f;
            if (j < 4) v[j] = val; else ((float*)&v1)[j-4] = val;
        }
    };
    float acc[4][4][4] = {};
    float4 pa0, pa1, pb0, pb1;
    pa0 = *(const float4*)&cw[am*2304 + aq0*4];
    pa1 = *(const float4*)&cw[am*2304 + aq1*4];
    loadB(0, pb0, pb1);
    stA(As[0], am, aq0, pa0); stA(As[0], am, aq1, pa1);
    *(float4*)&Bs[0][bk*136 + mq*4]      = tf4(pb0);
    *(float4*)&Bs[0][bk*136 + 64 + mq*4] = tf4(pb1);
    __syncthreads();
    for (int it = 0; it < 144; ++it) {
        if (it + 1 < 144) {
            int k0 = (it+1)*16;
            pa0 = *(const float4*)&cw[am*2304 + k0 + aq0*4];
            pa1 = *(const float4*)&cw[am*2304 + k0 + aq1*4];
            loadB(k0, pb0, pb1);
        }
        mma_AB(acc, As[it & 1], Bs[it & 1], wm, wn, lane);
        if (it + 1 < 144) {
            int nb = (it+1) & 1;
            stA(As[nb], am, aq0, pa0); stA(As[nb], am, aq1, pa1);
            *(float4*)&Bs[nb][bk*136 + mq*4]      = tf4(pb0);
            *(float4*)&Bs[nb][bk*136 + 64 + mq*4] = tf4(pb1);
        }
        __syncthreads();
    }
#pragma unroll
    for (int mf = 0; mf < 4; ++mf)
#pragma unroll
        for (int h = 0; h < 2; ++h) {
            int o = wm*64 + mf*16 + gid + h*8;
            float sc  = cg[o] * rsqrtf(cv[o] + EPSB);
            float cbv = cb[o] - cm[o]*sc;
#pragma unroll
            for (int nf = 0; nf < 4; ++nf) {
                int cl = wn*32 + nf*8 + t4*2;
                float2 r;
                r.x = fmaxf(acc[mf][nf][2*h+0]*sc + cbv, 0.f);
                r.y = fmaxf(acc[mf][nf][2*h+1]*sc + cbv, 0.f);
                *(float2*)&fb[(size_t)o*NPIX + p0 + cl] = r;
            }
        }
}

// ---------------- host ----------------------------------------------------------
extern "C" void kernel_launch(void* const* d_in, const int* in_sizes, int n_in,
                              void* d_out, int out_size)
{
    (void)in_sizes; (void)n_in; (void)out_size;
    const float* q    = (const float*)d_in[0];
    const float* s    = (const float*)d_in[1];
    const float* tsw  = (const float*)d_in[2];
    const float* tsb  = (const float*)d_in[3];
    const float* bsg  = (const float*)d_in[4];
    const float* bsb  = (const float*)d_in[5];
    const float* bsm  = (const float*)d_in[6];
    const float* bsv  = (const float*)d_in[7];
    const float* tqw  = (const float*)d_in[8];
    const float* tqb  = (const float*)d_in[9];
    const float* bqg  = (const float*)d_in[10];
    const float* bqb  = (const float*)d_in[11];
    const float* bqm  = (const float*)d_in[12];
    const float* bqv  = (const float*)d_in[13];
    const float* vqw  = (const float*)d_in[14];
    const float* vqb  = (const float*)d_in[15];
    const float* vsw  = (const float*)d_in[16];
    const float* vsb  = (const float*)d_in[17];
    const float* keyw = (const float*)d_in[18];
    const float* keyb = (const float*)d_in[19];
    const float* qryw = (const float*)d_in[20];
    const float* qryb = (const float*)d_in[21];
    const float* gw1  = (const float*)d_in[22];
    const float* gb1  = (const float*)d_in[23];
    const float* gw2  = (const float*)d_in[24];
    const float* gb2  = (const float*)d_in[25];
    const float* cw   = (const float*)d_in[26];
    const float* cg   = (const float*)d_in[27];
    const float* cb   = (const float*)d_in[28];
    const float* cm   = (const float*)d_in[29];
    const float* cv   = (const float*)d_in[30];

    float *p_qt, *p_st, *p_vq, *p_vs, *p_kx, *p_qx, *p_pq, *p_ps;
    cudaGetSymbolAddress((void**)&p_qt, g_qt);
    cudaGetSymbolAddress((void**)&p_st, g_st);
    cudaGetSymbolAddress((void**)&p_vq, g_vq);
    cudaGetSymbolAddress((void**)&p_vs, g_vs);
    cudaGetSymbolAddress((void**)&p_kx, g_kx);
    cudaGetSymbolAddress((void**)&p_qx, g_qx);
    cudaGetSymbolAddress((void**)&p_pq, g_poolq);
    cudaGetSymbolAddress((void**)&p_ps, g_pools);

    float* feat = (float*)d_out;
    float* Eq   = feat + (size_t)BATCH*CC*NPIX;
    float* Es   = Eq   + (size_t)BATCH*CC*NPIX;

    dim3 g18(18, BATCH);

    init_bmax<<<1, 32>>>();
    gemm_wx_t<<<g18, 256>>>(q, tqw, tqb, bqg, bqb, bqm, bqv, p_qt, CIN, p_pq);
    gemm_wx_t<<<g18, 256>>>(s, tsw, tsb, bsg, bsb, bsm, bsv, p_st, CIN, p_ps);
    gemm_wx_t<<<g18, 256>>>(p_qt, vqw,  vqb,  0, 0, 0, 0, p_vq, CC, 0);
    gemm_wx_t<<<g18, 256>>>(p_qt, qryw, qryb, 0, 0, 0, 0, p_qx, CC, 0);
    gemm_wx_t<<<g18, 256>>>(p_st, vsw,  vsb,  0, 0, 0, 0, p_vs, CC, 0);
    gemm_wx_t<<<g18, 256>>>(p_st, keyw, keyb, 0, 0, 0, 0, p_kx, CC, 0);

    score_t<<<dim3(18, 18, BATCH), 256>>>();
    gate_kernel<<<dim3(2, BATCH), 128>>>(gw1, gb1, gw2, gb2);

    attn_s_t<<<g18, 256>>>(Es);
    attn_q_t<<<g18, 256>>>(Eq);

    conv_t<<<g18, 256>>>(cw, cg, cb, cm, cv, Eq, Es, feat);
}

// round 7
// speedup vs baseline: 2.9110x; 1.0348x over previous
#include <cuda_runtime.h>
#include <cuda_bf16.h>

#define BATCH 8
#define CIN   256
#define CC    128
#define NPIX  2304
#define EPSB  1e-5f

// ---------------- scratch ------------------------------------------------------
__device__ __align__(16) float g_qt[BATCH*CC*NPIX];
__device__ __align__(16) float g_st[BATCH*CC*NPIX];
__device__ __align__(16) float g_kx[BATCH*CC*NPIX];
__device__ __align__(16) float g_qx[BATCH*CC*NPIX];
__device__ __align__(16) unsigned short g_vqh[BATCH*CC*NPIX];   // bf16 v_q
__device__ __align__(16) unsigned short g_vsh[BATCH*CC*NPIX];   // bf16 v_s
__device__ __align__(16) unsigned short g_e[(size_t)BATCH*NPIX*NPIX]; // bf16 exp(A-lm)
__device__ __align__(16) float g_cwr[CC*2304];                  // tf32-rounded conv w
__device__ float g_tmax[BATCH*18*18];
__device__ float g_rpart[BATCH*18*NPIX];   // [b][mblock][n] row partial sums
__device__ float g_cpart[BATCH*18*NPIX];   // [b][nblock][m] col partial sums
__device__ unsigned g_bmaxk[BATCH];
__device__ float g_poolq[BATCH*18*CC];
__device__ float g_pools[BATCH*18*CC];
__device__ float g_gq[BATCH*CC];
__device__ float g_gs[BATCH*CC];

// ---------------- helpers ------------------------------------------------------
__device__ __forceinline__ float tf(float x) {
    unsigned u;
    asm("cvt.rna.tf32.f32 %0, %1;" : "=r"(u) : "f"(x));
    return __uint_as_float(u);
}
__device__ __forceinline__ float4 tf4(float4 v) {
    v.x = tf(v.x); v.y = tf(v.y); v.z = tf(v.z); v.w = tf(v.w); return v;
}
__device__ __forceinline__ unsigned fkey(float x) {
    int i = __float_as_int(x);
    return (i >= 0) ? ((unsigned)i | 0x80000000u) : ~(unsigned)i;
}
__device__ __forceinline__ float fdekey(unsigned u) {
    int i = (u & 0x80000000u) ? (int)(u & 0x7fffffffu) : ~(int)u;
    return __int_as_float(i);
}
__device__ __forceinline__ unsigned packbf(float a, float b) {
    __nv_bfloat162 h = __floats2bfloat162_rn(a, b);   // .x = a (low), .y = b (high)
    return *(unsigned*)&h;
}
__device__ __forceinline__ int cpos(int j) { return ((j & 3) << 2) | (j >> 2); }

__device__ __forceinline__ void mma_tf32(float* c,
    unsigned a0, unsigned a1, unsigned a2, unsigned a3, unsigned b0, unsigned b1)
{
    asm volatile(
        "mma.sync.aligned.m16n8k8.row.col.f32.tf32.tf32.f32 "
        "{%0,%1,%2,%3}, {%4,%5,%6,%7}, {%8,%9}, {%0,%1,%2,%3};"
        : "+f"(c[0]), "+f"(c[1]), "+f"(c[2]), "+f"(c[3])
        : "r"(a0), "r"(a1), "r"(a2), "r"(a3), "r"(b0), "r"(b1));
}
__device__ __forceinline__ void mma_bf16(float* c,
    unsigned a0, unsigned a1, unsigned a2, unsigned a3, unsigned b0, unsigned b1)
{
    asm volatile(
        "mma.sync.aligned.m16n8k16.row.col.f32.bf16.bf16.f32 "
        "{%0,%1,%2,%3}, {%4,%5,%6,%7}, {%8,%9}, {%0,%1,%2,%3};"
        : "+f"(c[0]), "+f"(c[1]), "+f"(c[2]), "+f"(c[3])
        : "r"(a0), "r"(a1), "r"(a2), "r"(a3), "r"(b0), "r"(b1));
}

// ---- fp32/tf32 path: block 128x128x16, warp 64x32 -----------------------------
__device__ __forceinline__ void mma_AB(float acc[4][4][4],
    const float* As, const float* Bs, int wm, int wn, int lane)
{
    const int gid = lane >> 2, t4 = lane & 3;
    const float4* As4 = (const float4*)As;
    float4 va[4][2];
#pragma unroll
    for (int mf = 0; mf < 4; ++mf) {
        int rb = wm*64 + mf*16 + gid;
        va[mf][0] = As4[rb*5 + t4];
        va[mf][1] = As4[(rb+8)*5 + t4];
    }
#pragma unroll
    for (int ko = 0; ko < 2; ++ko) {
        unsigned bf[4][2];
#pragma unroll
        for (int nf = 0; nf < 4; ++nf) {
            int nb = wn*32 + nf*8 + gid;
            bf[nf][0] = __float_as_uint(Bs[(ko*8+t4  )*136 + nb]);
            bf[nf][1] = __float_as_uint(Bs[(ko*8+t4+4)*136 + nb]);
        }
#pragma unroll
        for (int mf = 0; mf < 4; ++mf) {
            unsigned a0, a1, a2, a3;
            if (ko == 0) {
                a0 = __float_as_uint(va[mf][0].x); a1 = __float_as_uint(va[mf][1].x);
                a2 = __float_as_uint(va[mf][0].y); a3 = __float_as_uint(va[mf][1].y);
            } else {
                a0 = __float_as_uint(va[mf][0].z); a1 = __float_as_uint(va[mf][1].z);
                a2 = __float_as_uint(va[mf][0].w); a3 = __float_as_uint(va[mf][1].w);
            }
#pragma unroll
            for (int nf = 0; nf < 4; ++nf)
                mma_tf32(acc[mf][nf], a0, a1, a2, a3, bf[nf][0], bf[nf][1]);
        }
    }
}
__device__ __forceinline__ void stA(float* As, int m, int aq, float4 v) {
    float* p = &As[m*20 + aq];
    p[0] = tf(v.x); p[4] = tf(v.y); p[8] = tf(v.z); p[12] = tf(v.w);
}
__device__ __forceinline__ void stAraw(float* As, int m, int aq, float4 v) {
    float* p = &As[m*20 + aq];
    p[0] = v.x; p[4] = v.y; p[8] = v.z; p[12] = v.w;
}

// ---- bf16 path: block 128x128x32, warp 64x32; A,B crosswise-uint stride 20 ----
__device__ __forceinline__ void mma_AB16(float acc[4][4][4],
    const unsigned* As, const unsigned* Bs, int wm, int wn, int lane)
{
    const int gid = lane >> 2, t4 = lane & 3;
    const uint4* A4 = (const uint4*)As;
    const uint4* B4 = (const uint4*)Bs;
    uint4 va[4][2], vb[4];
#pragma unroll
    for (int mf = 0; mf < 4; ++mf) {
        int rb = wm*64 + mf*16 + gid;
        va[mf][0] = A4[rb*5 + t4];
        va[mf][1] = A4[(rb+8)*5 + t4];
    }
#pragma unroll
    for (int nf = 0; nf < 4; ++nf) {
        int nb = wn*32 + nf*8 + gid;
        vb[nf] = B4[nb*5 + t4];
    }
#pragma unroll
    for (int mf = 0; mf < 4; ++mf)
#pragma unroll
        for (int nf = 0; nf < 4; ++nf)
            mma_bf16(acc[mf][nf], va[mf][0].x, va[mf][1].x, va[mf][0].y, va[mf][1].y,
                     vb[nf].x, vb[nf].y);
#pragma unroll
    for (int mf = 0; mf < 4; ++mf)
#pragma unroll
        for (int nf = 0; nf < 4; ++nf)
            mma_bf16(acc[mf][nf], va[mf][0].z, va[mf][1].z, va[mf][0].w, va[mf][1].w,
                     vb[nf].z, vb[nf].w);
}

#define ASZ (128*20)
#define BSZ (16*136)

__global__ void init_bmax() { if (threadIdx.x < BATCH) g_bmaxk[threadIdx.x] = 0u; }

__global__ void prep_cw(const float* __restrict__ cw, float* __restrict__ cwr) {
    int i = blockIdx.x*256 + threadIdx.x;
    if (i < CC*2304) cwr[i] = tf(cw[i]);
}

// ---------------- 1x1 conv GEMM (+BN, +pool partials, + optional bf16 out) -----
__global__ __launch_bounds__(256, 2) void gemm_wx_t(
    const float* __restrict__ x, const float* __restrict__ w,
    const float* __restrict__ bias,
    const float* __restrict__ bng, const float* __restrict__ bnb,
    const float* __restrict__ bnm, const float* __restrict__ bnv,
    float* __restrict__ out, int K, float* __restrict__ poolpart,
    unsigned short* __restrict__ outh)
{
    const int b  = blockIdx.y;
    const int p0 = blockIdx.x * 128;
    const float* xb = x + (size_t)b*K*NPIX;
    float* ob = out ? out + (size_t)b*CC*NPIX : 0;
    unsigned short* ohb = outh ? outh + (size_t)b*CC*NPIX : 0;
    __shared__ __align__(16) float As[2][ASZ];
    __shared__ __align__(16) float Bs[2][BSZ];
    const int tid = threadIdx.x, lane = tid & 31, wid = tid >> 5;
    const int wm = wid & 1, wn = wid >> 1;
    const int gid = lane >> 2, t4 = lane & 3;
    const int am = tid >> 1, aq0 = 2*(tid & 1), aq1 = aq0 + 1;
    const int bk = tid >> 4, bq = tid & 15;
    float acc[4][4][4] = {};
    float4 pa0, pa1, pb0, pb1;
    pa0 = *(const float4*)&w[am*K + aq0*4];
    pa1 = *(const float4*)&w[am*K + aq1*4];
    pb0 = *(const float4*)&xb[(size_t)bk*NPIX + p0 + bq*4];
    pb1 = *(const float4*)&xb[(size_t)bk*NPIX + p0 + 64 + bq*4];
    stA(As[0], am, aq0, pa0); stA(As[0], am, aq1, pa1);
    *(float4*)&Bs[0][bk*136 + bq*4]      = tf4(pb0);
    *(float4*)&Bs[0][bk*136 + 64 + bq*4] = tf4(pb1);
    __syncthreads();
    const int iters = K / 16;
    for (int it = 0; it < iters; ++it) {
        if (it + 1 < iters) {
            int k0 = (it+1)*16;
            pa0 = *(const float4*)&w[am*K + k0 + aq0*4];
            pa1 = *(const float4*)&w[am*K + k0 + aq1*4];
            pb0 = *(const float4*)&xb[(size_t)(k0+bk)*NPIX + p0 + bq*4];
            pb1 = *(const float4*)&xb[(size_t)(k0+bk)*NPIX + p0 + 64 + bq*4];
        }
        mma_AB(acc, As[it & 1], Bs[it & 1], wm, wn, lane);
        if (it + 1 < iters) {
            int nb = (it+1) & 1;
            stA(As[nb], am, aq0, pa0); stA(As[nb], am, aq1, pa1);
            *(float4*)&Bs[nb][bk*136 + bq*4]      = tf4(pb0);
            *(float4*)&Bs[nb][bk*136 + 64 + bq*4] = tf4(pb1);
        }
        __syncthreads();
    }
    float rsum[8];
#pragma unroll
    for (int mf = 0; mf < 4; ++mf)
#pragma unroll
        for (int h = 0; h < 2; ++h) {
            int o = wm*64 + mf*16 + gid + h*8;
            float sc = 1.0f, cb = bias[o];
            if (bng) {
                sc = bng[o] * rsqrtf(bnv[o] + EPSB);
                cb = (bias[o] - bnm[o]) * sc + bnb[o];
            }
            float sm = 0.f;
#pragma unroll
            for (int nf = 0; nf < 4; ++nf) {
                int cl = wn*32 + nf*8 + t4*2;
                float2 r;
                r.x = acc[mf][nf][2*h+0]*sc + cb;
                r.y = acc[mf][nf][2*h+1]*sc + cb;
                sm += r.x + r.y;
                if (ohb)
                    *(unsigned*)&ohb[(size_t)o*NPIX + p0 + cl] = packbf(r.x, r.y);
                else
                    *(float2*)&ob[(size_t)o*NPIX + p0 + cl] = r;
            }
            rsum[mf*2+h] = sm;
        }
    if (poolpart) {
        float* redp = (float*)As;
        __syncthreads();
#pragma unroll
        for (int j = 0; j < 8; ++j) {
            float v = rsum[j];
            v += __shfl_xor_sync(~0u, v, 1);
            v += __shfl_xor_sync(~0u, v, 2);
            if (t4 == 0) {
                int row = wm*64 + (j>>1)*16 + gid + (j&1)*8;
                redp[wn*128 + row] = v;
            }
        }
        __syncthreads();
        if (tid < 128)
            poolpart[((size_t)b*18 + blockIdx.x)*CC + tid] =
                redp[tid] + redp[128+tid] + redp[256+tid] + redp[384+tid];
    }
}

// ---------------- score: e = bf16(exp(A - blkmax)); maxima + partial sums -------
__global__ __launch_bounds__(256, 2) void score_t()
{
    const int b  = blockIdx.z;
    const int n0 = blockIdx.y * 128;
    const int m0 = blockIdx.x * 128;
    const float* kx = g_kx + (size_t)b*CC*NPIX;
    const float* qx = g_qx + (size_t)b*CC*NPIX;
    unsigned short* eb = g_e + (size_t)b*NPIX*NPIX;
    __shared__ __align__(16) float As[2][BSZ];
    __shared__ __align__(16) float Bs[2][BSZ];
    __shared__ float smax[8];
    const int tid = threadIdx.x, lane = tid & 31, wid = tid >> 5;
    const int wm = wid & 1, wn = wid >> 1;
    const int gid = lane >> 2, t4 = lane & 3;
    const int ak = tid >> 4, aq = tid & 15;
    float acc[4][4][4] = {};
    float4 pa0, pa1, pb0, pb1;
    pa0 = *(const float4*)&kx[(size_t)ak*NPIX + n0 + aq*4];
    pa1 = *(const float4*)&kx[(size_t)ak*NPIX + n0 + 64 + aq*4];
    pb0 = *(const float4*)&qx[(size_t)ak*NPIX + m0 + aq*4];
    pb1 = *(const float4*)&qx[(size_t)ak*NPIX + m0 + 64 + aq*4];
    *(float4*)&As[0][ak*136 + aq*4]      = tf4(pa0);
    *(float4*)&As[0][ak*136 + 64 + aq*4] = tf4(pa1);
    *(float4*)&Bs[0][ak*136 + aq*4]      = tf4(pb0);
    *(float4*)&Bs[0][ak*136 + 64 + aq*4] = tf4(pb1);
    __syncthreads();
    for (int it = 0; it < CC/16; ++it) {
        if (it + 1 < CC/16) {
            int k0 = (it+1)*16;
            pa0 = *(const float4*)&kx[(size_t)(k0+ak)*NPIX + n0 + aq*4];
            pa1 = *(const float4*)&kx[(size_t)(k0+ak)*NPIX + n0 + 64 + aq*4];
            pb0 = *(const float4*)&qx[(size_t)(k0+ak)*NPIX + m0 + aq*4];
            pb1 = *(const float4*)&qx[(size_t)(k0+ak)*NPIX + m0 + 64 + aq*4];
        }
        {
            const float* Asb = As[it & 1];
            const float* Bsb = Bs[it & 1];
#pragma unroll
            for (int ko = 0; ko < 2; ++ko) {
                unsigned bf[4][2];
#pragma unroll
                for (int nf = 0; nf < 4; ++nf) {
                    int nb = wn*32 + nf*8 + gid;
                    bf[nf][0] = __float_as_uint(Bsb[(ko*8+t4  )*136 + nb]);
                    bf[nf][1] = __float_as_uint(Bsb[(ko*8+t4+4)*136 + nb]);
                }
#pragma unroll
                for (int mf = 0; mf < 4; ++mf) {
                    int rb = wm*64 + mf*16 + gid;
                    unsigned a0 = __float_as_uint(Asb[(ko*8+t4  )*136 + rb]);
                    unsigned a1 = __float_as_uint(Asb[(ko*8+t4  )*136 + rb+8]);
                    unsigned a2 = __float_as_uint(Asb[(ko*8+t4+4)*136 + rb]);
                    unsigned a3 = __float_as_uint(Asb[(ko*8+t4+4)*136 + rb+8]);
#pragma unroll
                    for (int nf = 0; nf < 4; ++nf)
                        mma_tf32(acc[mf][nf], a0, a1, a2, a3, bf[nf][0], bf[nf][1]);
                }
            }
        }
        if (it + 1 < CC/16) {
            int nb = (it+1) & 1;
            *(float4*)&As[nb][ak*136 + aq*4]      = tf4(pa0);
            *(float4*)&As[nb][ak*136 + 64 + aq*4] = tf4(pa1);
            *(float4*)&Bs[nb][ak*136 + aq*4]      = tf4(pb0);
            *(float4*)&Bs[nb][ak*136 + 64 + aq*4] = tf4(pb1);
        }
        __syncthreads();
    }
    float mx = -1e30f;
#pragma unroll
    for (int mf = 0; mf < 4; ++mf)
#pragma unroll
        for (int nf = 0; nf < 4; ++nf)
#pragma unroll
            for (int v = 0; v < 4; ++v) mx = fmaxf(mx, acc[mf][nf][v]);
#pragma unroll
    for (int o = 16; o; o >>= 1) mx = fmaxf(mx, __shfl_xor_sync(~0u, mx, o));
    if (lane == 0) smax[wid] = mx;
    __syncthreads();
    float lm = smax[0];
#pragma unroll
    for (int j = 1; j < 8; ++j) lm = fmaxf(lm, smax[j]);
    float rowp[8] = {};
    float colp[8] = {};
#pragma unroll
    for (int mf = 0; mf < 4; ++mf)
#pragma unroll
        for (int h = 0; h < 2; ++h) {
            int n = n0 + wm*64 + mf*16 + gid + h*8;
#pragma unroll
            for (int nf = 0; nf < 4; ++nf) {
                int cl = wn*32 + nf*8 + t4*2;
                float e0 = __expf(acc[mf][nf][2*h+0] - lm);
                float e1 = __expf(acc[mf][nf][2*h+1] - lm);
                *(unsigned*)(eb + (size_t)n*NPIX + m0 + cl) = packbf(e0, e1);
                rowp[mf*2+h] += e0 + e1;
                colp[nf*2+0] += e0;
                colp[nf*2+1] += e1;
            }
        }
    // reductions into reused smem
    float* rowred = (float*)As;           // 4 x 128
    float* colred = rowred + 512;         // 16 x 132
    __syncthreads();
#pragma unroll
    for (int j = 0; j < 8; ++j) {
        float v = rowp[j];
        v += __shfl_xor_sync(~0u, v, 1);
        v += __shfl_xor_sync(~0u, v, 2);
        if (t4 == 0)
            rowred[wn*128 + wm*64 + (j>>1)*16 + gid + (j&1)*8] = v;
    }
#pragma unroll
    for (int j = 0; j < 8; ++j) {
        int cl = wn*32 + (j>>1)*8 + t4*2 + (j&1);
        colred[(wm*8+gid)*132 + cl] = colp[j];
    }
    __syncthreads();
    if (tid < 128) {
        float r = rowred[tid] + rowred[128+tid] + rowred[256+tid] + rowred[384+tid];
        g_rpart[((size_t)b*18 + blockIdx.x)*NPIX + n0 + tid] = r;
        float c = 0.f;
#pragma unroll
        for (int i = 0; i < 16; ++i) c += colred[i*132 + tid];
        g_cpart[((size_t)b*18 + blockIdx.y)*NPIX + m0 + tid] = c;
    }
    if (tid == 0) {
        g_tmax[(b*18 + blockIdx.y)*18 + blockIdx.x] = lm;
        atomicMax(&g_bmaxk[b], fkey(lm));
    }
}

// ---------------- channel gate --------------------------------------------------
__global__ __launch_bounds__(128) void gate_kernel(
    const float* __restrict__ w1, const float* __restrict__ b1,
    const float* __restrict__ w2, const float* __restrict__ b2)
{
    const int b = blockIdx.y;
    const float* pp = (blockIdx.x == 0 ? g_poolq : g_pools) + (size_t)b*18*CC;
    float* go = (blockIdx.x == 0 ? g_gq : g_gs) + b*CC;
    __shared__ float pool[CC];
    __shared__ float hsh[8];
    const int tid = threadIdx.x;
    {
        float s = 0.f;
#pragma unroll
        for (int j = 0; j < 18; ++j) s += pp[j*CC + tid];
        pool[tid] = s * (1.0f/NPIX);
    }
    __syncthreads();
    if (tid < 8) {
        float h = b1[tid];
        for (int i = 0; i < CC; ++i) h += pool[i] * w1[tid*CC + i];
        hsh[tid] = fmaxf(h, 0.f);
    }
    __syncthreads();
    float z = b2[tid];
#pragma unroll
    for (int j = 0; j < 8; ++j) z += hsh[j] * w2[tid*8 + j];
    go[tid] = 1.0f / (1.0f + __expf(-z));
}

// ---------------- E_s (bf16): lean mainloop; sorted tiles + acc rescale ---------
__global__ __launch_bounds__(256) void attn_s_t(float* __restrict__ Es)
{
    const int b  = blockIdx.y;
    const int n0 = blockIdx.x * 128;
    const unsigned short* eb = g_e + (size_t)b*NPIX*NPIX;
    const unsigned* vsh = (const unsigned*)g_vsh + (size_t)b*CC*(NPIX/2);
    const float* st = g_st + (size_t)b*CC*NPIX;
    const float* gt = g_gs + b*CC;
    float* Eb = Es + (size_t)b*CC*NPIX;
    __shared__ unsigned As[2][ASZ];
    __shared__ unsigned Bs[2][ASZ];
    __shared__ float tmx[18];
    __shared__ int   ordsh[18];
    __shared__ float ratio[18];
    __shared__ float rinv_s[128];
    const int tid = threadIdx.x, lane = tid & 31, wid = tid >> 5;
    const int wm = wid & 1, wn = wid >> 1;
    const int gid = lane >> 2, t4 = lane & 3;
    const int am = tid >> 1, half = tid & 1;
    const float bmax = fdekey(g_bmaxk[b]);
    if (tid < 18) tmx[tid] = g_tmax[(b*18 + blockIdx.x)*18 + tid];
    __syncthreads();
    if (tid < 18) {
        float mine = tmx[tid];
        int rank = 0;
        for (int j = 0; j < 18; ++j) {
            float o = tmx[j];
            rank += (o < mine) || (o == mine && j < tid);
        }
        ordsh[rank] = tid;
    }
    __syncthreads();
    if (tid < 18)
        ratio[tid] = (tid == 0) ? 1.0f : __expf(tmx[ordsh[tid-1]] - tmx[ordsh[tid]]);
    if (tid >= 32 && tid < 160) {
        int n = tid - 32;
        float s = 0.f;
#pragma unroll
        for (int mb = 0; mb < 18; ++mb)
            s += __expf(tmx[mb] - bmax) * g_rpart[((size_t)b*18 + mb)*NPIX + n0 + n];
        rinv_s[n] = s;
    }
    __syncthreads();
    if (tid < 128) {
        float slast = __expf(tmx[ordsh[17]] - bmax);
        rinv_s[tid] = slast / rinv_s[tid];
    }
    // mainloop
    const unsigned* arow = vsh + (size_t)am*(NPIX/2) + half*8;
    const unsigned* erow = (const unsigned*)(eb + (size_t)(n0+am)*NPIX) + half*8;
    float acc[4][4][4] = {};
    uint4 pa0, pa1, pb0, pb1;
    {
        int ko2 = ordsh[0]*64;
        pa0 = *(const uint4*)&arow[ko2];  pa1 = *(const uint4*)&arow[ko2+4];
        pb0 = *(const uint4*)&erow[ko2];  pb1 = *(const uint4*)&erow[ko2+4];
    }
    auto store = [&](int buf) {
        unsigned* Ap = &As[buf][am*20];
        unsigned* Bp = &Bs[buf][am*20];
        unsigned ua[8] = {pa0.x,pa0.y,pa0.z,pa0.w, pa1.x,pa1.y,pa1.z,pa1.w};
        unsigned ub[8] = {pb0.x,pb0.y,pb0.z,pb0.w, pb1.x,pb1.y,pb1.z,pb1.w};
#pragma unroll
        for (int i = 0; i < 8; ++i) {
            int c = cpos(half*8 + i);
            Ap[c] = ua[i];
            Bp[c] = ub[i];
        }
    };
    store(0);
    __syncthreads();
    for (int it = 0; it < 72; ++it) {
        if (it + 1 < 72) {
            int nit = it + 1;
            int ko2 = ordsh[nit>>2]*64 + (nit&3)*16;
            pa0 = *(const uint4*)&arow[ko2];  pa1 = *(const uint4*)&arow[ko2+4];
            pb0 = *(const uint4*)&erow[ko2];  pb1 = *(const uint4*)&erow[ko2+4];
        }
        if ((it & 3) == 0 && it) {
            float r = ratio[it>>2];
#pragma unroll
            for (int mf = 0; mf < 4; ++mf)
#pragma unroll
                for (int nf = 0; nf < 4; ++nf)
#pragma unroll
                    for (int v = 0; v < 4; ++v) acc[mf][nf][v] *= r;
        }
        mma_AB16(acc, As[it & 1], Bs[it & 1], wm, wn, lane);
        if (it + 1 < 72) store((it+1) & 1);
        __syncthreads();
    }
#pragma unroll
    for (int mf = 0; mf < 4; ++mf)
#pragma unroll
        for (int h = 0; h < 2; ++h) {
            int co = wm*64 + mf*16 + gid + h*8;
            float g = gt[co];
#pragma unroll
            for (int nf = 0; nf < 4; ++nf) {
                int cl = wn*32 + nf*8 + t4*2;
                float2 res = *(const float2*)&st[(size_t)co*NPIX + n0 + cl];
                float2 r;
                r.x = g*acc[mf][nf][2*h+0]*rinv_s[cl]   + res.x;
                r.y = g*acc[mf][nf][2*h+1]*rinv_s[cl+1] + res.y;
                *(float2*)&Eb[(size_t)co*NPIX + n0 + cl] = r;
            }
        }
}

// ---------------- E_q (bf16): lean mainloop; sorted tiles + acc rescale ---------
__global__ __launch_bounds__(256) void attn_q_t(float* __restrict__ Eq)
{
    const int b  = blockIdx.y;
    const int m0 = blockIdx.x * 128;
    const unsigned short* eb = g_e + (size_t)b*NPIX*NPIX;
    const unsigned* vqh = (const unsigned*)g_vqh + (size_t)b*CC*(NPIX/2);
    const float* qt = g_qt + (size_t)b*CC*NPIX;
    const float* gt = g_gq + b*CC;
    float* Eb = Eq + (size_t)b*CC*NPIX;
    __shared__ unsigned As[2][ASZ];
    __shared__ unsigned Bs[2][ASZ];
    __shared__ float tmx[18];
    __shared__ int   ordsh[18];
    __shared__ float ratio[18];
    __shared__ float cinv_s[128];
    const int tid = threadIdx.x, lane = tid & 31, wid = tid >> 5;
    const int wm = wid & 1, wn = wid >> 1;
    const int gid = lane >> 2, t4 = lane & 3;
    const int am = tid >> 1, half = tid & 1;
    const int np = tid >> 4, mseg = tid & 15;
    const float bmax = fdekey(g_bmaxk[b]);
    if (tid < 18) tmx[tid] = g_tmax[(b*18 + tid)*18 + blockIdx.x];
    __syncthreads();
    if (tid < 18) {
        float mine = tmx[tid];
        int rank = 0;
        for (int j = 0; j < 18; ++j) {
            float o = tmx[j];
            rank += (o < mine) || (o == mine && j < tid);
        }
        ordsh[rank] = tid;
    }
    __syncthreads();
    if (tid < 18)
        ratio[tid] = (tid == 0) ? 1.0f : __expf(tmx[ordsh[tid-1]] - tmx[ordsh[tid]]);
    if (tid >= 32 && tid < 160) {
        int m = tid - 32;
        float s = 0.f;
#pragma unroll
        for (int nb = 0; nb < 18; ++nb)
            s += __expf(tmx[nb] - bmax) * g_cpart[((size_t)b*18 + nb)*NPIX + m0 + m];
        cinv_s[m] = s;
    }
    __syncthreads();
    if (tid < 128) {
        float slast = __expf(tmx[ordsh[17]] - bmax);
        cinv_s[tid] = slast / cinv_s[tid];
    }
    // mainloop
    const unsigned* arow = vqh + (size_t)am*(NPIX/2) + half*8;
    const unsigned* ebase = (const unsigned*)eb + m0/2 + mseg*4;
    const int ppos = cpos(np);
    float acc[4][4][4] = {};
    uint4 pa0, pa1, pb0, pb1;
    {
        int k0 = ordsh[0]*128;
        pa0 = *(const uint4*)&arow[ordsh[0]*64];
        pa1 = *(const uint4*)&arow[ordsh[0]*64 + 4];
        pb0 = *(const uint4*)&ebase[(size_t)(k0 + 2*np    )*(NPIX/2)];
        pb1 = *(const uint4*)&ebase[(size_t)(k0 + 2*np + 1)*(NPIX/2)];
    }
    auto store = [&](int buf) {
        unsigned* Ap = &As[buf][am*20];
        unsigned ua[8] = {pa0.x,pa0.y,pa0.z,pa0.w, pa1.x,pa1.y,pa1.z,pa1.w};
#pragma unroll
        for (int i = 0; i < 8; ++i) Ap[cpos(half*8 + i)] = ua[i];
        unsigned u0[4] = {pb0.x, pb0.y, pb0.z, pb0.w};
        unsigned u1[4] = {pb1.x, pb1.y, pb1.z, pb1.w};
#pragma unroll
        for (int jj = 0; jj < 4; ++jj) {
            unsigned q0 = __byte_perm(u0[jj], u1[jj], 0x5410);
            unsigned q1 = __byte_perm(u0[jj], u1[jj], 0x7632);
            int ml = mseg*8 + 2*jj;
            Bs[buf][ml*20 + ppos]     = q0;
            Bs[buf][(ml+1)*20 + ppos] = q1;
        }
    };
    store(0);
    __syncthreads();
    for (int it = 0; it < 72; ++it) {
        if (it + 1 < 72) {
            int nit = it + 1;
            int kt = ordsh[nit>>2];
            int k0 = kt*128 + (nit&3)*32;
            pa0 = *(const uint4*)&arow[kt*64 + (nit&3)*16];
            pa1 = *(const uint4*)&arow[kt*64 + (nit&3)*16 + 4];
            pb0 = *(const uint4*)&ebase[(size_t)(k0 + 2*np    )*(NPIX/2)];
            pb1 = *(const uint4*)&ebase[(size_t)(k0 + 2*np + 1)*(NPIX/2)];
        }
        if ((it & 3) == 0 && it) {
            float r = ratio[it>>2];
#pragma unroll
            for (int mf = 0; mf < 4; ++mf)
#pragma unroll
                for (int nf = 0; nf < 4; ++nf)
#pragma unroll
                    for (int v = 0; v < 4; ++v) acc[mf][nf][v] *= r;
        }
        mma_AB16(acc, As[it & 1], Bs[it & 1], wm, wn, lane);
        if (it + 1 < 72) store((it+1) & 1);
        __syncthreads();
    }
#pragma unroll
    for (int mf = 0; mf < 4; ++mf)
#pragma unroll
        for (int h = 0; h < 2; ++h) {
            int co = wm*64 + mf*16 + gid + h*8;
            float g = gt[co];
#pragma unroll
            for (int nf = 0; nf < 4; ++nf) {
                int cl = wn*32 + nf*8 + t4*2;
                float2 res = *(const float2*)&qt[(size_t)co*NPIX + m0 + cl];
                float2 r;
                r.x = g*acc[mf][nf][2*h+0]*cinv_s[cl]   + res.x;
                r.y = g*acc[mf][nf][2*h+1]*cinv_s[cl+1] + res.y;
                *(float2*)&Eb[(size_t)co*NPIX + m0 + cl] = r;
            }
        }
}

// ---------------- 3x3 conv (tf32 implicit GEMM) + BN + ReLU ---------------------
__global__ __launch_bounds__(256) void conv_t(
    const float* __restrict__ cwr, const float* __restrict__ cg,
    const float* __restrict__ cb, const float* __restrict__ cm,
    const float* __restrict__ cv,
    const float* __restrict__ Eq, const float* __restrict__ Es,
    float* __restrict__ feat)
{
    const int b  = blockIdx.y;
    const int p0 = blockIdx.x * 128;
    const float* Eqb = Eq + (size_t)b*CC*NPIX;
    const float* Esb = Es + (size_t)b*CC*NPIX;
    float* fb = feat + (size_t)b*CC*NPIX;
    __shared__ __align__(16) float As[2][ASZ];
    __shared__ __align__(16) float Bs[2][BSZ];
    const int tid = threadIdx.x, lane = tid & 31, wid = tid >> 5;
    const int wm = wid & 1, wn = wid >> 1;
    const int gid = lane >> 2, t4 = lane & 3;
    const int am = tid >> 1, aq0 = 2*(tid & 1), aq1 = aq0 + 1;
    const int bk = tid >> 4, mq = tid & 15;
    int hh[8], ww[8];
#pragma unroll
    for (int j = 0; j < 8; ++j) {
        int p = p0 + mq*4 + (j & 3) + (j >> 2)*64;
        hh[j] = p / 48; ww[j] = p - hh[j]*48;
    }
    auto loadB = [&](int k0, float4& v0, float4& v1) {
        int kap = k0 + bk;
        int ic = kap / 9, kk = kap - ic*9;
        int dh = kk/3 - 1, dw = kk - (kk/3)*3 - 1;
        const float* src = (ic < CC) ? Eqb : Esb;
        const float* sp = src + (size_t)(ic & (CC-1))*NPIX;
        float* v = (float*)&v0;
#pragma unroll
        for (int j = 0; j < 8; ++j) {
            int ih = hh[j] + dh, iw = ww[j] + dw;
            float val = ((unsigned)ih < 48u && (unsigned)iw < 48u)
                      ? sp[ih*48 + iw] : 0.f;
            if (j < 4) v[j] = val; else ((float*)&v1)[j-4] = val;
        }
    };
    float acc[4][4][4] = {};
    float4 pa0, pa1, pb0, pb1;
    pa0 = *(const float4*)&cwr[am*2304 + aq0*4];
    pa1 = *(const float4*)&cwr[am*2304 + aq1*4];
    loadB(0, pb0, pb1);
    stAraw(As[0], am, aq0, pa0); stAraw(As[0], am, aq1, pa1);
    *(float4*)&Bs[0][bk*136 + mq*4]      = tf4(pb0);
    *(float4*)&Bs[0][bk*136 + 64 + mq*4] = tf4(pb1);
    __syncthreads();
    for (int it = 0; it < 144; ++it) {
        if (it + 1 < 144) {
            int k0 = (it+1)*16;
            pa0 = *(const float4*)&cwr[am*2304 + k0 + aq0*4];
            pa1 = *(const float4*)&cwr[am*2304 + k0 + aq1*4];
            loadB(k0, pb0, pb1);
        }
        mma_AB(acc, As[it & 1], Bs[it & 1], wm, wn, lane);
        if (it + 1 < 144) {
            int nb = (it+1) & 1;
            stAraw(As[nb], am, aq0, pa0); stAraw(As[nb], am, aq1, pa1);
            *(float4*)&Bs[nb][bk*136 + mq*4]      = tf4(pb0);
            *(float4*)&Bs[nb][bk*136 + 64 + mq*4] = tf4(pb1);
        }
        __syncthreads();
    }
#pragma unroll
    for (int mf = 0; mf < 4; ++mf)
#pragma unroll
        for (int h = 0; h < 2; ++h) {
            int o = wm*64 + mf*16 + gid + h*8;
            float sc  = cg[o] * rsqrtf(cv[o] + EPSB);
            float cbv = cb[o] - cm[o]*sc;
#pragma unroll
            for (int nf = 0; nf < 4; ++nf) {
                int cl = wn*32 + nf*8 + t4*2;
                float2 r;
                r.x = fmaxf(acc[mf][nf][2*h+0]*sc + cbv, 0.f);
                r.y = fmaxf(acc[mf][nf][2*h+1]*sc + cbv, 0.f);
                *(float2*)&fb[(size_t)o*NPIX + p0 + cl] = r;
            }
        }
}

// ---------------- host ----------------------------------------------------------
extern "C" void kernel_launch(void* const* d_in, const int* in_sizes, int n_in,
                              void* d_out, int out_size)
{
    (void)in_sizes; (void)n_in; (void)out_size;
    const float* q    = (const float*)d_in[0];
    const float* s    = (const float*)d_in[1];
    const float* tsw  = (const float*)d_in[2];
    const float* tsb  = (const float*)d_in[3];
    const float* bsg  = (const float*)d_in[4];
    const float* bsb  = (const float*)d_in[5];
    const float* bsm  = (const float*)d_in[6];
    const float* bsv  = (const float*)d_in[7];
    const float* tqw  = (const float*)d_in[8];
    const float* tqb  = (const float*)d_in[9];
    const float* bqg  = (const float*)d_in[10];
    const float* bqb  = (const float*)d_in[11];
    const float* bqm  = (const float*)d_in[12];
    const float* bqv  = (const float*)d_in[13];
    const float* vqw  = (const float*)d_in[14];
    const float* vqb  = (const float*)d_in[15];
    const float* vsw  = (const float*)d_in[16];
    const float* vsb  = (const float*)d_in[17];
    const float* keyw = (const float*)d_in[18];
    const float* keyb = (const float*)d_in[19];
    const float* qryw = (const float*)d_in[20];
    const float* qryb = (const float*)d_in[21];
    const float* gw1  = (const float*)d_in[22];
    const float* gb1  = (const float*)d_in[23];
    const float* gw2  = (const float*)d_in[24];
    const float* gb2  = (const float*)d_in[25];
    const float* cw   = (const float*)d_in[26];
    const float* cg   = (const float*)d_in[27];
    const float* cb   = (const float*)d_in[28];
    const float* cm   = (const float*)d_in[29];
    const float* cv   = (const float*)d_in[30];

    float *p_qt, *p_st, *p_kx, *p_qx, *p_pq, *p_ps, *p_cwr;
    unsigned short *p_vqh, *p_vsh;
    cudaGetSymbolAddress((void**)&p_qt,  g_qt);
    cudaGetSymbolAddress((void**)&p_st,  g_st);
    cudaGetSymbolAddress((void**)&p_kx,  g_kx);
    cudaGetSymbolAddress((void**)&p_qx,  g_qx);
    cudaGetSymbolAddress((void**)&p_pq,  g_poolq);
    cudaGetSymbolAddress((void**)&p_ps,  g_pools);
    cudaGetSymbolAddress((void**)&p_cwr, g_cwr);
    cudaGetSymbolAddress((void**)&p_vqh, g_vqh);
    cudaGetSymbolAddress((void**)&p_vsh, g_vsh);

    float* feat = (float*)d_out;
    float* Eq   = feat + (size_t)BATCH*CC*NPIX;
    float* Es   = Eq   + (size_t)BATCH*CC*NPIX;

    dim3 g18(18, BATCH);

    init_bmax<<<1, 32>>>();
    prep_cw<<<1152, 256>>>(cw, p_cwr);
    gemm_wx_t<<<g18, 256>>>(q, tqw, tqb, bqg, bqb, bqm, bqv, p_qt, CIN, p_pq, 0);
    gemm_wx_t<<<g18, 256>>>(s, tsw, tsb, bsg, bsb, bsm, bsv, p_st, CIN, p_ps, 0);
    gemm_wx_t<<<g18, 256>>>(p_qt, vqw,  vqb,  0, 0, 0, 0, 0,    CC, 0, p_vqh);
    gemm_wx_t<<<g18, 256>>>(p_qt, qryw, qryb, 0, 0, 0, 0, p_qx, CC, 0, 0);
    gemm_wx_t<<<g18, 256>>>(p_st, vsw,  vsb,  0, 0, 0, 0, 0,    CC, 0, p_vsh);
    gemm_wx_t<<<g18, 256>>>(p_st, keyw, keyb, 0, 0, 0, 0, p_kx, CC, 0, 0);

    score_t<<<dim3(18, 18, BATCH), 256>>>();
    gate_kernel<<<dim3(2, BATCH), 128>>>(gw1, gb1, gw2, gb2);

    attn_s_t<<<g18, 256>>>(Es);
    attn_q_t<<<g18, 256>>>(Eq);

    conv_t<<<g18, 256>>>(p_cwr, cg, cb, cm, cv, Eq, Es, feat);
}

// round 8
// speedup vs baseline: 3.2691x; 1.1230x over previous
#include <cuda_runtime.h>
#include <cuda_bf16.h>

#define BATCH 8
#define CIN   256
#define CC    128
#define NPIX  2304
#define EPSB  1e-5f

// ---------------- scratch ------------------------------------------------------
__device__ __align__(16) float g_qt[BATCH*CC*NPIX];
__device__ __align__(16) float g_st[BATCH*CC*NPIX];
__device__ __align__(16) float g_kx[BATCH*CC*NPIX];
__device__ __align__(16) float g_qx[BATCH*CC*NPIX];
__device__ __align__(16) unsigned short g_vqh[BATCH*CC*NPIX];   // bf16 v_q
__device__ __align__(16) unsigned short g_vsh[BATCH*CC*NPIX];   // bf16 v_s
__device__ __align__(16) unsigned short g_e[(size_t)BATCH*NPIX*NPIX]; // bf16 exp(A-lm)
__device__ __align__(16) float g_cwr[CC*2304];                  // tf32-rounded conv w
__device__ float g_tmax[BATCH*18*18];
__device__ float g_rpart[BATCH*18*NPIX];   // [b][mblock][n] row partial sums
__device__ float g_cpart[BATCH*18*NPIX];   // [b][nblock][m] col partial sums
__device__ unsigned g_bmaxk[BATCH];
__device__ float g_poolq[BATCH*18*CC];
__device__ float g_pools[BATCH*18*CC];
__device__ float g_gq[BATCH*CC];
__device__ float g_gs[BATCH*CC];

// ---------------- helpers ------------------------------------------------------
__device__ __forceinline__ float tf(float x) {
    unsigned u;
    asm("cvt.rna.tf32.f32 %0, %1;" : "=r"(u) : "f"(x));
    return __uint_as_float(u);
}
__device__ __forceinline__ float4 tf4(float4 v) {
    v.x = tf(v.x); v.y = tf(v.y); v.z = tf(v.z); v.w = tf(v.w); return v;
}
__device__ __forceinline__ unsigned fkey(float x) {
    int i = __float_as_int(x);
    return (i >= 0) ? ((unsigned)i | 0x80000000u) : ~(unsigned)i;
}
__device__ __forceinline__ float fdekey(unsigned u) {
    int i = (u & 0x80000000u) ? (int)(u & 0x7fffffffu) : ~(int)u;
    return __int_as_float(i);
}
__device__ __forceinline__ unsigned packbf(float a, float b) {
    __nv_bfloat162 h = __floats2bfloat162_rn(a, b);
    return *(unsigned*)&h;
}
__device__ __forceinline__ int cpos(int j) { return ((j & 3) << 2) | (j >> 2); }

__device__ __forceinline__ void mma_tf32(float* c,
    unsigned a0, unsigned a1, unsigned a2, unsigned a3, unsigned b0, unsigned b1)
{
    asm volatile(
        "mma.sync.aligned.m16n8k8.row.col.f32.tf32.tf32.f32 "
        "{%0,%1,%2,%3}, {%4,%5,%6,%7}, {%8,%9}, {%0,%1,%2,%3};"
        : "+f"(c[0]), "+f"(c[1]), "+f"(c[2]), "+f"(c[3])
        : "r"(a0), "r"(a1), "r"(a2), "r"(a3), "r"(b0), "r"(b1));
}
__device__ __forceinline__ void mma_bf16(float* c,
    unsigned a0, unsigned a1, unsigned a2, unsigned a3, unsigned b0, unsigned b1)
{
    asm volatile(
        "mma.sync.aligned.m16n8k16.row.col.f32.bf16.bf16.f32 "
        "{%0,%1,%2,%3}, {%4,%5,%6,%7}, {%8,%9}, {%0,%1,%2,%3};"
        : "+f"(c[0]), "+f"(c[1]), "+f"(c[2]), "+f"(c[3])
        : "r"(a0), "r"(a1), "r"(a2), "r"(a3), "r"(b0), "r"(b1));
}

// ---- fp32/tf32 path: block 128x128x16, warp 64x32 -----------------------------
__device__ __forceinline__ void mma_AB(float acc[4][4][4],
    const float* As, const float* Bs, int wm, int wn, int lane)
{
    const int gid = lane >> 2, t4 = lane & 3;
    const float4* As4 = (const float4*)As;
    float4 va[4][2];
#pragma unroll
    for (int mf = 0; mf < 4; ++mf) {
        int rb = wm*64 + mf*16 + gid;
        va[mf][0] = As4[rb*5 + t4];
        va[mf][1] = As4[(rb+8)*5 + t4];
    }
#pragma unroll
    for (int ko = 0; ko < 2; ++ko) {
        unsigned bf[4][2];
#pragma unroll
        for (int nf = 0; nf < 4; ++nf) {
            int nb = wn*32 + nf*8 + gid;
            bf[nf][0] = __float_as_uint(Bs[(ko*8+t4  )*136 + nb]);
            bf[nf][1] = __float_as_uint(Bs[(ko*8+t4+4)*136 + nb]);
        }
#pragma unroll
        for (int mf = 0; mf < 4; ++mf) {
            unsigned a0, a1, a2, a3;
            if (ko == 0) {
                a0 = __float_as_uint(va[mf][0].x); a1 = __float_as_uint(va[mf][1].x);
                a2 = __float_as_uint(va[mf][0].y); a3 = __float_as_uint(va[mf][1].y);
            } else {
                a0 = __float_as_uint(va[mf][0].z); a1 = __float_as_uint(va[mf][1].z);
                a2 = __float_as_uint(va[mf][0].w); a3 = __float_as_uint(va[mf][1].w);
            }
#pragma unroll
            for (int nf = 0; nf < 4; ++nf)
                mma_tf32(acc[mf][nf], a0, a1, a2, a3, bf[nf][0], bf[nf][1]);
        }
    }
}
__device__ __forceinline__ void stA(float* As, int m, int aq, float4 v) {
    float* p = &As[m*20 + aq];
    p[0] = tf(v.x); p[4] = tf(v.y); p[8] = tf(v.z); p[12] = tf(v.w);
}
__device__ __forceinline__ void stAraw(float* As, int m, int aq, float4 v) {
    float* p = &As[m*20 + aq];
    p[0] = v.x; p[4] = v.y; p[8] = v.z; p[12] = v.w;
}

// ---- bf16 path: block 128x128x32, warp 64x32; A,B crosswise-uint stride 20 ----
__device__ __forceinline__ void mma_AB16(float acc[4][4][4],
    const unsigned* As, const unsigned* Bs, int wm, int wn, int lane)
{
    const int gid = lane >> 2, t4 = lane & 3;
    const uint4* A4 = (const uint4*)As;
    const uint4* B4 = (const uint4*)Bs;
    uint4 va[4][2], vb[4];
#pragma unroll
    for (int mf = 0; mf < 4; ++mf) {
        int rb = wm*64 + mf*16 + gid;
        va[mf][0] = A4[rb*5 + t4];
        va[mf][1] = A4[(rb+8)*5 + t4];
    }
#pragma unroll
    for (int nf = 0; nf < 4; ++nf) {
        int nb = wn*32 + nf*8 + gid;
        vb[nf] = B4[nb*5 + t4];
    }
#pragma unroll
    for (int mf = 0; mf < 4; ++mf)
#pragma unroll
        for (int nf = 0; nf < 4; ++nf)
            mma_bf16(acc[mf][nf], va[mf][0].x, va[mf][1].x, va[mf][0].y, va[mf][1].y,
                     vb[nf].x, vb[nf].y);
#pragma unroll
    for (int mf = 0; mf < 4; ++mf)
#pragma unroll
        for (int nf = 0; nf < 4; ++nf)
            mma_bf16(acc[mf][nf], va[mf][0].z, va[mf][1].z, va[mf][0].w, va[mf][1].w,
                     vb[nf].z, vb[nf].w);
}

#define ASZ (128*20)
#define BSZ (16*136)

__global__ void init_bmax() { if (threadIdx.x < BATCH) g_bmaxk[threadIdx.x] = 0u; }

__global__ void prep_cw(const float* __restrict__ cw, float* __restrict__ cwr) {
    int i = blockIdx.x*256 + threadIdx.x;
    if (i < CC*2304) cwr[i] = tf(cw[i]);
}

// ---------------- batched 1x1 conv GEMM jobs ------------------------------------
struct GemmJob {
    const float* x; const float* w; const float* bias;
    const float* bng; const float* bnb; const float* bnm; const float* bnv;
    float* out; unsigned short* outh; float* poolpart;
};
struct GemmJobs { GemmJob j[4]; };

__global__ __launch_bounds__(256, 2) void gemm_wx_t(GemmJobs jobs, int K)
{
    const GemmJob job = jobs.j[blockIdx.z];
    const int b  = blockIdx.y;
    const int p0 = blockIdx.x * 128;
    const float* xb = job.x + (size_t)b*K*NPIX;
    float* ob = job.out ? job.out + (size_t)b*CC*NPIX : 0;
    unsigned short* ohb = job.outh ? job.outh + (size_t)b*CC*NPIX : 0;
    const float* w = job.w;
    __shared__ __align__(16) float As[2][ASZ];
    __shared__ __align__(16) float Bs[2][BSZ];
    const int tid = threadIdx.x, lane = tid & 31, wid = tid >> 5;
    const int wm = wid & 1, wn = wid >> 1;
    const int gid = lane >> 2, t4 = lane & 3;
    const int am = tid >> 1, aq0 = 2*(tid & 1), aq1 = aq0 + 1;
    const int bk = tid >> 4, bq = tid & 15;
    float acc[4][4][4] = {};
    float4 pa0, pa1, pb0, pb1;
    pa0 = *(const float4*)&w[am*K + aq0*4];
    pa1 = *(const float4*)&w[am*K + aq1*4];
    pb0 = *(const float4*)&xb[(size_t)bk*NPIX + p0 + bq*4];
    pb1 = *(const float4*)&xb[(size_t)bk*NPIX + p0 + 64 + bq*4];
    stA(As[0], am, aq0, pa0); stA(As[0], am, aq1, pa1);
    *(float4*)&Bs[0][bk*136 + bq*4]      = tf4(pb0);
    *(float4*)&Bs[0][bk*136 + 64 + bq*4] = tf4(pb1);
    __syncthreads();
    const int iters = K / 16;
    for (int it = 0; it < iters; ++it) {
        if (it + 1 < iters) {
            int k0 = (it+1)*16;
            pa0 = *(const float4*)&w[am*K + k0 + aq0*4];
            pa1 = *(const float4*)&w[am*K + k0 + aq1*4];
            pb0 = *(const float4*)&xb[(size_t)(k0+bk)*NPIX + p0 + bq*4];
            pb1 = *(const float4*)&xb[(size_t)(k0+bk)*NPIX + p0 + 64 + bq*4];
        }
        mma_AB(acc, As[it & 1], Bs[it & 1], wm, wn, lane);
        if (it + 1 < iters) {
            int nb = (it+1) & 1;
            stA(As[nb], am, aq0, pa0); stA(As[nb], am, aq1, pa1);
            *(float4*)&Bs[nb][bk*136 + bq*4]      = tf4(pb0);
            *(float4*)&Bs[nb][bk*136 + 64 + bq*4] = tf4(pb1);
        }
        __syncthreads();
    }
    float rsum[8];
#pragma unroll
    for (int mf = 0; mf < 4; ++mf)
#pragma unroll
        for (int h = 0; h < 2; ++h) {
            int o = wm*64 + mf*16 + gid + h*8;
            float sc = 1.0f, cb = job.bias[o];
            if (job.bng) {
                sc = job.bng[o] * rsqrtf(job.bnv[o] + EPSB);
                cb = (job.bias[o] - job.bnm[o]) * sc + job.bnb[o];
            }
            float sm = 0.f;
#pragma unroll
            for (int nf = 0; nf < 4; ++nf) {
                int cl = wn*32 + nf*8 + t4*2;
                float2 r;
                r.x = acc[mf][nf][2*h+0]*sc + cb;
                r.y = acc[mf][nf][2*h+1]*sc + cb;
                sm += r.x + r.y;
                if (ohb)
                    *(unsigned*)&ohb[(size_t)o*NPIX + p0 + cl] = packbf(r.x, r.y);
                else
                    *(float2*)&ob[(size_t)o*NPIX + p0 + cl] = r;
            }
            rsum[mf*2+h] = sm;
        }
    if (job.poolpart) {
        float* redp = (float*)As;
        __syncthreads();
#pragma unroll
        for (int j = 0; j < 8; ++j) {
            float v = rsum[j];
            v += __shfl_xor_sync(~0u, v, 1);
            v += __shfl_xor_sync(~0u, v, 2);
            if (t4 == 0) {
                int row = wm*64 + (j>>1)*16 + gid + (j&1)*8;
                redp[wn*128 + row] = v;
            }
        }
        __syncthreads();
        if (tid < 128)
            job.poolpart[((size_t)b*18 + blockIdx.x)*CC + tid] =
                redp[tid] + redp[128+tid] + redp[256+tid] + redp[384+tid];
    }
}

// ---------------- score: e = bf16(exp(A - blkmax)); maxima + partial sums -------
__global__ __launch_bounds__(256, 2) void score_t()
{
    const int b  = blockIdx.z;
    const int n0 = blockIdx.y * 128;
    const int m0 = blockIdx.x * 128;
    const float* kx = g_kx + (size_t)b*CC*NPIX;
    const float* qx = g_qx + (size_t)b*CC*NPIX;
    unsigned short* eb = g_e + (size_t)b*NPIX*NPIX;
    __shared__ __align__(16) float As[2][BSZ];
    __shared__ __align__(16) float Bs[2][BSZ];
    __shared__ float smax[8];
    const int tid = threadIdx.x, lane = tid & 31, wid = tid >> 5;
    const int wm = wid & 1, wn = wid >> 1;
    const int gid = lane >> 2, t4 = lane & 3;
    const int ak = tid >> 4, aq = tid & 15;
    float acc[4][4][4] = {};
    float4 pa0, pa1, pb0, pb1;
    pa0 = *(const float4*)&kx[(size_t)ak*NPIX + n0 + aq*4];
    pa1 = *(const float4*)&kx[(size_t)ak*NPIX + n0 + 64 + aq*4];
    pb0 = *(const float4*)&qx[(size_t)ak*NPIX + m0 + aq*4];
    pb1 = *(const float4*)&qx[(size_t)ak*NPIX + m0 + 64 + aq*4];
    *(float4*)&As[0][ak*136 + aq*4]      = tf4(pa0);
    *(float4*)&As[0][ak*136 + 64 + aq*4] = tf4(pa1);
    *(float4*)&Bs[0][ak*136 + aq*4]      = tf4(pb0);
    *(float4*)&Bs[0][ak*136 + 64 + aq*4] = tf4(pb1);
    __syncthreads();
    for (int it = 0; it < CC/16; ++it) {
        if (it + 1 < CC/16) {
            int k0 = (it+1)*16;
            pa0 = *(const float4*)&kx[(size_t)(k0+ak)*NPIX + n0 + aq*4];
            pa1 = *(const float4*)&kx[(size_t)(k0+ak)*NPIX + n0 + 64 + aq*4];
            pb0 = *(const float4*)&qx[(size_t)(k0+ak)*NPIX + m0 + aq*4];
            pb1 = *(const float4*)&qx[(size_t)(k0+ak)*NPIX + m0 + 64 + aq*4];
        }
        {
            const float* Asb = As[it & 1];
            const float* Bsb = Bs[it & 1];
#pragma unroll
            for (int ko = 0; ko < 2; ++ko) {
                unsigned bf[4][2];
#pragma unroll
                for (int nf = 0; nf < 4; ++nf) {
                    int nb = wn*32 + nf*8 + gid;
                    bf[nf][0] = __float_as_uint(Bsb[(ko*8+t4  )*136 + nb]);
                    bf[nf][1] = __float_as_uint(Bsb[(ko*8+t4+4)*136 + nb]);
                }
#pragma unroll
                for (int mf = 0; mf < 4; ++mf) {
                    int rb = wm*64 + mf*16 + gid;
                    unsigned a0 = __float_as_uint(Asb[(ko*8+t4  )*136 + rb]);
                    unsigned a1 = __float_as_uint(Asb[(ko*8+t4  )*136 + rb+8]);
                    unsigned a2 = __float_as_uint(Asb[(ko*8+t4+4)*136 + rb]);
                    unsigned a3 = __float_as_uint(Asb[(ko*8+t4+4)*136 + rb+8]);
#pragma unroll
                    for (int nf = 0; nf < 4; ++nf)
                        mma_tf32(acc[mf][nf], a0, a1, a2, a3, bf[nf][0], bf[nf][1]);
                }
            }
        }
        if (it + 1 < CC/16) {
            int nb = (it+1) & 1;
            *(float4*)&As[nb][ak*136 + aq*4]      = tf4(pa0);
            *(float4*)&As[nb][ak*136 + 64 + aq*4] = tf4(pa1);
            *(float4*)&Bs[nb][ak*136 + aq*4]      = tf4(pb0);
            *(float4*)&Bs[nb][ak*136 + 64 + aq*4] = tf4(pb1);
        }
        __syncthreads();
    }
    float mx = -1e30f;
#pragma unroll
    for (int mf = 0; mf < 4; ++mf)
#pragma unroll
        for (int nf = 0; nf < 4; ++nf)
#pragma unroll
            for (int v = 0; v < 4; ++v) mx = fmaxf(mx, acc[mf][nf][v]);
#pragma unroll
    for (int o = 16; o; o >>= 1) mx = fmaxf(mx, __shfl_xor_sync(~0u, mx, o));
    if (lane == 0) smax[wid] = mx;
    __syncthreads();
    float lm = smax[0];
#pragma unroll
    for (int j = 1; j < 8; ++j) lm = fmaxf(lm, smax[j]);
    float rowp[8] = {};
    float colp[8] = {};
#pragma unroll
    for (int mf = 0; mf < 4; ++mf)
#pragma unroll
        for (int h = 0; h < 2; ++h) {
            int n = n0 + wm*64 + mf*16 + gid + h*8;
#pragma unroll
            for (int nf = 0; nf < 4; ++nf) {
                int cl = wn*32 + nf*8 + t4*2;
                float e0 = __expf(acc[mf][nf][2*h+0] - lm);
                float e1 = __expf(acc[mf][nf][2*h+1] - lm);
                *(unsigned*)(eb + (size_t)n*NPIX + m0 + cl) = packbf(e0, e1);
                rowp[mf*2+h] += e0 + e1;
                colp[nf*2+0] += e0;
                colp[nf*2+1] += e1;
            }
        }
    float* rowred = (float*)As;           // 4 x 128
    float* colred = rowred + 512;         // 16 x 132
    __syncthreads();
#pragma unroll
    for (int j = 0; j < 8; ++j) {
        float v = rowp[j];
        v += __shfl_xor_sync(~0u, v, 1);
        v += __shfl_xor_sync(~0u, v, 2);
        if (t4 == 0)
            rowred[wn*128 + wm*64 + (j>>1)*16 + gid + (j&1)*8] = v;
    }
#pragma unroll
    for (int j = 0; j < 8; ++j) {
        int cl = wn*32 + (j>>1)*8 + t4*2 + (j&1);
        colred[(wm*8+gid)*132 + cl] = colp[j];
    }
    __syncthreads();
    if (tid < 128) {
        float r = rowred[tid] + rowred[128+tid] + rowred[256+tid] + rowred[384+tid];
        g_rpart[((size_t)b*18 + blockIdx.x)*NPIX + n0 + tid] = r;
        float c = 0.f;
#pragma unroll
        for (int i = 0; i < 16; ++i) c += colred[i*132 + tid];
        g_cpart[((size_t)b*18 + blockIdx.y)*NPIX + m0 + tid] = c;
    }
    if (tid == 0) {
        g_tmax[(b*18 + blockIdx.y)*18 + blockIdx.x] = lm;
        atomicMax(&g_bmaxk[b], fkey(lm));
    }
}

// ---------------- channel gate --------------------------------------------------
__global__ __launch_bounds__(128) void gate_kernel(
    const float* __restrict__ w1, const float* __restrict__ b1,
    const float* __restrict__ w2, const float* __restrict__ b2)
{
    const int b = blockIdx.y;
    const float* pp = (blockIdx.x == 0 ? g_poolq : g_pools) + (size_t)b*18*CC;
    float* go = (blockIdx.x == 0 ? g_gq : g_gs) + b*CC;
    __shared__ float pool[CC];
    __shared__ float hsh[8];
    const int tid = threadIdx.x;
    {
        float s = 0.f;
#pragma unroll
        for (int j = 0; j < 18; ++j) s += pp[j*CC + tid];
        pool[tid] = s * (1.0f/NPIX);
    }
    __syncthreads();
    if (tid < 8) {
        float h = b1[tid];
        for (int i = 0; i < CC; ++i) h += pool[i] * w1[tid*CC + i];
        hsh[tid] = fmaxf(h, 0.f);
    }
    __syncthreads();
    float z = b2[tid];
#pragma unroll
    for (int j = 0; j < 8; ++j) z += hsh[j] * w2[tid*8 + j];
    go[tid] = 1.0f / (1.0f + __expf(-z));
}

// ---------------- merged attention: z=0 -> E_s, z=1 -> E_q ----------------------
__global__ __launch_bounds__(256, 2) void attn_t(float* __restrict__ Es,
                                                 float* __restrict__ Eq)
{
    const int z  = blockIdx.z;
    const int b  = blockIdx.y;
    const int x0 = blockIdx.x * 128;       // n0 (z=0) or m0 (z=1)
    const unsigned short* eb = g_e + (size_t)b*NPIX*NPIX;
    const unsigned* vh = (const unsigned*)(z == 0 ? g_vsh : g_vqh)
                       + (size_t)b*CC*(NPIX/2);
    const float* resb = (z == 0 ? g_st : g_qt) + (size_t)b*CC*NPIX;
    const float* gt   = (z == 0 ? g_gs : g_gq) + b*CC;
    float* Eb = (z == 0 ? Es : Eq) + (size_t)b*CC*NPIX;
    __shared__ unsigned As[2][ASZ];
    __shared__ unsigned Bs[2][ASZ];
    __shared__ float tmx[18];
    __shared__ int   ordsh[18];
    __shared__ float ratio[18];
    __shared__ float inv_s[128];
    const int tid = threadIdx.x, lane = tid & 31, wid = tid >> 5;
    const int wm = wid & 1, wn = wid >> 1;
    const int gid = lane >> 2, t4 = lane & 3;
    const int am = tid >> 1, half = tid & 1;
    const float bmax = fdekey(g_bmaxk[b]);
    if (tid < 18)
        tmx[tid] = (z == 0) ? g_tmax[(b*18 + blockIdx.x)*18 + tid]
                            : g_tmax[(b*18 + tid)*18 + blockIdx.x];
    __syncthreads();
    if (tid < 18) {
        float mine = tmx[tid];
        int rank = 0;
        for (int j = 0; j < 18; ++j) {
            float o = tmx[j];
            rank += (o < mine) || (o == mine && j < tid);
        }
        ordsh[rank] = tid;
    }
    __syncthreads();
    if (tid < 18)
        ratio[tid] = (tid == 0) ? 1.0f : __expf(tmx[ordsh[tid-1]] - tmx[ordsh[tid]]);
    if (tid >= 32 && tid < 160) {
        int i = tid - 32;
        const float* part = (z == 0 ? g_rpart : g_cpart);
        float s = 0.f;
#pragma unroll
        for (int t = 0; t < 18; ++t)
            s += __expf(tmx[t] - bmax) * part[((size_t)b*18 + t)*NPIX + x0 + i];
        inv_s[i] = s;
    }
    __syncthreads();
    if (tid < 128) {
        float slast = __expf(tmx[ordsh[17]] - bmax);
        inv_s[tid] = slast / inv_s[tid];
    }
    float acc[4][4][4] = {};
    const unsigned* arow = vh + (size_t)am*(NPIX/2) + half*8;

    if (z == 0) {
        // -------- E_s mainloop: B = same-row contiguous exp(A) -----------------
        const unsigned* erow = (const unsigned*)(eb + (size_t)(x0+am)*NPIX) + half*8;
        uint4 pa0, pa1, pb0, pb1;
        {
            int ko2 = ordsh[0]*64;
            pa0 = *(const uint4*)&arow[ko2];  pa1 = *(const uint4*)&arow[ko2+4];
            pb0 = *(const uint4*)&erow[ko2];  pb1 = *(const uint4*)&erow[ko2+4];
        }
        auto store = [&](int buf) {
            unsigned* Ap = &As[buf][am*20];
            unsigned* Bp = &Bs[buf][am*20];
            unsigned ua[8] = {pa0.x,pa0.y,pa0.z,pa0.w, pa1.x,pa1.y,pa1.z,pa1.w};
            unsigned ub[8] = {pb0.x,pb0.y,pb0.z,pb0.w, pb1.x,pb1.y,pb1.z,pb1.w};
#pragma unroll
            for (int i = 0; i < 8; ++i) {
                int c = cpos(half*8 + i);
                Ap[c] = ua[i];
                Bp[c] = ub[i];
            }
        };
        store(0);
        __syncthreads();
        for (int it = 0; it < 72; ++it) {
            if (it + 1 < 72) {
                int nit = it + 1;
                int ko2 = ordsh[nit>>2]*64 + (nit&3)*16;
                pa0 = *(const uint4*)&arow[ko2];  pa1 = *(const uint4*)&arow[ko2+4];
                pb0 = *(const uint4*)&erow[ko2];  pb1 = *(const uint4*)&erow[ko2+4];
            }
            if ((it & 3) == 0 && it) {
                float r = ratio[it>>2];
#pragma unroll
                for (int mf = 0; mf < 4; ++mf)
#pragma unroll
                    for (int nf = 0; nf < 4; ++nf)
#pragma unroll
                        for (int v = 0; v < 4; ++v) acc[mf][nf][v] *= r;
            }
            mma_AB16(acc, As[it & 1], Bs[it & 1], wm, wn, lane);
            if (it + 1 < 72) store((it+1) & 1);
            __syncthreads();
        }
    } else {
        // -------- E_q mainloop: B = strided rows of exp(A) + byte_perm ---------
        const int np = tid >> 4, mseg = tid & 15;
        const unsigned* ebase = (const unsigned*)eb + x0/2 + mseg*4;
        const int ppos = cpos(np);
        uint4 pa0, pa1, pb0, pb1;
        {
            int k0 = ordsh[0]*128;
            pa0 = *(const uint4*)&arow[ordsh[0]*64];
            pa1 = *(const uint4*)&arow[ordsh[0]*64 + 4];
            pb0 = *(const uint4*)&ebase[(size_t)(k0 + 2*np    )*(NPIX/2)];
            pb1 = *(const uint4*)&ebase[(size_t)(k0 + 2*np + 1)*(NPIX/2)];
        }
        auto store = [&](int buf) {
            unsigned* Ap = &As[buf][am*20];
            unsigned ua[8] = {pa0.x,pa0.y,pa0.z,pa0.w, pa1.x,pa1.y,pa1.z,pa1.w};
#pragma unroll
            for (int i = 0; i < 8; ++i) Ap[cpos(half*8 + i)] = ua[i];
            unsigned u0[4] = {pb0.x, pb0.y, pb0.z, pb0.w};
            unsigned u1[4] = {pb1.x, pb1.y, pb1.z, pb1.w};
#pragma unroll
            for (int jj = 0; jj < 4; ++jj) {
                unsigned q0 = __byte_perm(u0[jj], u1[jj], 0x5410);
                unsigned q1 = __byte_perm(u0[jj], u1[jj], 0x7632);
                int ml = mseg*8 + 2*jj;
                Bs[buf][ml*20 + ppos]     = q0;
                Bs[buf][(ml+1)*20 + ppos] = q1;
            }
        };
        store(0);
        __syncthreads();
        for (int it = 0; it < 72; ++it) {
            if (it + 1 < 72) {
                int nit = it + 1;
                int kt = ordsh[nit>>2];
                int k0 = kt*128 + (nit&3)*32;
                pa0 = *(const uint4*)&arow[kt*64 + (nit&3)*16];
                pa1 = *(const uint4*)&arow[kt*64 + (nit&3)*16 + 4];
                pb0 = *(const uint4*)&ebase[(size_t)(k0 + 2*np    )*(NPIX/2)];
                pb1 = *(const uint4*)&ebase[(size_t)(k0 + 2*np + 1)*(NPIX/2)];
            }
            if ((it & 3) == 0 && it) {
                float r = ratio[it>>2];
#pragma unroll
                for (int mf = 0; mf < 4; ++mf)
#pragma unroll
                    for (int nf = 0; nf < 4; ++nf)
#pragma unroll
                        for (int v = 0; v < 4; ++v) acc[mf][nf][v] *= r;
            }
            mma_AB16(acc, As[it & 1], Bs[it & 1], wm, wn, lane);
            if (it + 1 < 72) store((it+1) & 1);
            __syncthreads();
        }
    }
#pragma unroll
    for (int mf = 0; mf < 4; ++mf)
#pragma unroll
        for (int h = 0; h < 2; ++h) {
            int co = wm*64 + mf*16 + gid + h*8;
            float g = gt[co];
#pragma unroll
            for (int nf = 0; nf < 4; ++nf) {
                int cl = wn*32 + nf*8 + t4*2;
                float2 res = *(const float2*)&resb[(size_t)co*NPIX + x0 + cl];
                float2 r;
                r.x = g*acc[mf][nf][2*h+0]*inv_s[cl]   + res.x;
                r.y = g*acc[mf][nf][2*h+1]*inv_s[cl+1] + res.y;
                *(float2*)&Eb[(size_t)co*NPIX + x0 + cl] = r;
            }
        }
}

// ---------------- 3x3 conv (tf32 implicit GEMM) + BN + ReLU ---------------------
__global__ __launch_bounds__(256) void conv_t(
    const float* __restrict__ cwr, const float* __restrict__ cg,
    const float* __restrict__ cb, const float* __restrict__ cm,
    const float* __restrict__ cv,
    const float* __restrict__ Eq, const float* __restrict__ Es,
    float* __restrict__ feat)
{
    const int b  = blockIdx.y;
    const int p0 = blockIdx.x * 128;
    const float* Eqb = Eq + (size_t)b*CC*NPIX;
    const float* Esb = Es + (size_t)b*CC*NPIX;
    float* fb = feat + (size_t)b*CC*NPIX;
    __shared__ __align__(16) float As[2][ASZ];
    __shared__ __align__(16) float Bs[2][BSZ];
    const int tid = threadIdx.x, lane = tid & 31, wid = tid >> 5;
    const int wm = wid & 1, wn = wid >> 1;
    const int gid = lane >> 2, t4 = lane & 3;
    const int am = tid >> 1, aq0 = 2*(tid & 1), aq1 = aq0 + 1;
    const int bk = tid >> 4, mq = tid & 15;
    int hh[8], ww[8];
#pragma unroll
    for (int j = 0; j < 8; ++j) {
        int p = p0 + mq*4 + (j & 3) + (j >> 2)*64;
        hh[j] = p / 48; ww[j] = p - hh[j]*48;
    }
    auto loadB = [&](int k0, float4& v0, float4& v1) {
        int kap = k0 + bk;
        int ic = kap / 9, kk = kap - ic*9;
        int dh = kk/3 - 1, dw = kk - (kk/3)*3 - 1;
        const float* src = (ic < CC) ? Eqb : Esb;
        const float* sp = src + (size_t)(ic & (CC-1))*NPIX;
        float* v = (float*)&v0;
#pragma unroll
        for (int j = 0; j < 8; ++j) {
            int ih = hh[j] + dh, iw = ww[j] + dw;
            float val = ((unsigned)ih < 48u && (unsigned)iw < 48u)
                      ? sp[ih*48 + iw] : 0.f;
            if (j < 4) v[j] = val; else ((float*)&v1)[j-4] = val;
        }
    };
    float acc[4][4][4] = {};
    float4 pa0, pa1, pb0, pb1;
    pa0 = *(const float4*)&cwr[am*2304 + aq0*4];
    pa1 = *(const float4*)&cwr[am*2304 + aq1*4];
    loadB(0, pb0, pb1);
    stAraw(As[0], am, aq0, pa0); stAraw(As[0], am, aq1, pa1);
    *(float4*)&Bs[0][bk*136 + mq*4]      = tf4(pb0);
    *(float4*)&Bs[0][bk*136 + 64 + mq*4] = tf4(pb1);
    __syncthreads();
    for (int it = 0; it < 144; ++it) {
        if (it + 1 < 144) {
            int k0 = (it+1)*16;
            pa0 = *(const float4*)&cwr[am*2304 + k0 + aq0*4];
            pa1 = *(const float4*)&cwr[am*2304 + k0 + aq1*4];
            loadB(k0, pb0, pb1);
        }
        mma_AB(acc, As[it & 1], Bs[it & 1], wm, wn, lane);
        if (it + 1 < 144) {
            int nb = (it+1) & 1;
            stAraw(As[nb], am, aq0, pa0); stAraw(As[nb], am, aq1, pa1);
            *(float4*)&Bs[nb][bk*136 + mq*4]      = tf4(pb0);
            *(float4*)&Bs[nb][bk*136 + 64 + mq*4] = tf4(pb1);
        }
        __syncthreads();
    }
#pragma unroll
    for (int mf = 0; mf < 4; ++mf)
#pragma unroll
        for (int h = 0; h < 2; ++h) {
            int o = wm*64 + mf*16 + gid + h*8;
            float sc  = cg[o] * rsqrtf(cv[o] + EPSB);
            float cbv = cb[o] - cm[o]*sc;
#pragma unroll
            for (int nf = 0; nf < 4; ++nf) {
                int cl = wn*32 + nf*8 + t4*2;
                float2 r;
                r.x = fmaxf(acc[mf][nf][2*h+0]*sc + cbv, 0.f);
                r.y = fmaxf(acc[mf][nf][2*h+1]*sc + cbv, 0.f);
                *(float2*)&fb[(size_t)o*NPIX + p0 + cl] = r;
            }
        }
}

// ---------------- host ----------------------------------------------------------
extern "C" void kernel_launch(void* const* d_in, const int* in_sizes, int n_in,
                              void* d_out, int out_size)
{
    (void)in_sizes; (void)n_in; (void)out_size;
    const float* q    = (const float*)d_in[0];
    const float* s    = (const float*)d_in[1];
    const float* tsw  = (const float*)d_in[2];
    const float* tsb  = (const float*)d_in[3];
    const float* bsg  = (const float*)d_in[4];
    const float* bsb  = (const float*)d_in[5];
    const float* bsm  = (const float*)d_in[6];
    const float* bsv  = (const float*)d_in[7];
    const float* tqw  = (const float*)d_in[8];
    const float* tqb  = (const float*)d_in[9];
    const float* bqg  = (const float*)d_in[10];
    const float* bqb  = (const float*)d_in[11];
    const float* bqm  = (const float*)d_in[12];
    const float* bqv  = (const float*)d_in[13];
    const float* vqw  = (const float*)d_in[14];
    const float* vqb  = (const float*)d_in[15];
    const float* vsw  = (const float*)d_in[16];
    const float* vsb  = (const float*)d_in[17];
    const float* keyw = (const float*)d_in[18];
    const float* keyb = (const float*)d_in[19];
    const float* qryw = (const float*)d_in[20];
    const float* qryb = (const float*)d_in[21];
    const float* gw1  = (const float*)d_in[22];
    const float* gb1  = (const float*)d_in[23];
    const float* gw2  = (const float*)d_in[24];
    const float* gb2  = (const float*)d_in[25];
    const float* cw   = (const float*)d_in[26];
    const float* cg   = (const float*)d_in[27];
    const float* cb   = (const float*)d_in[28];
    const float* cm   = (const float*)d_in[29];
    const float* cv   = (const float*)d_in[30];

    float *p_qt, *p_st, *p_kx, *p_qx, *p_pq, *p_ps, *p_cwr;
    unsigned short *p_vqh, *p_vsh;
    cudaGetSymbolAddress((void**)&p_qt,  g_qt);
    cudaGetSymbolAddress((void**)&p_st,  g_st);
    cudaGetSymbolAddress((void**)&p_kx,  g_kx);
    cudaGetSymbolAddress((void**)&p_qx,  g_qx);
    cudaGetSymbolAddress((void**)&p_pq,  g_poolq);
    cudaGetSymbolAddress((void**)&p_ps,  g_pools);
    cudaGetSymbolAddress((void**)&p_cwr, g_cwr);
    cudaGetSymbolAddress((void**)&p_vqh, g_vqh);
    cudaGetSymbolAddress((void**)&p_vsh, g_vsh);

    float* feat = (float*)d_out;
    float* Eq   = feat + (size_t)BATCH*CC*NPIX;
    float* Es   = Eq   + (size_t)BATCH*CC*NPIX;

    init_bmax<<<1, 32>>>();
    prep_cw<<<1152, 256>>>(cw, p_cwr);

    // trans pair: z=0 -> q', z=1 -> s'
    {
        GemmJobs jt = {};
        jt.j[0] = { q, tqw, tqb, bqg, bqb, bqm, bqv, p_qt, 0, p_pq };
        jt.j[1] = { s, tsw, tsb, bsg, bsb, bsm, bsv, p_st, 0, p_ps };
        gemm_wx_t<<<dim3(18, BATCH, 2), 256>>>(jt, CIN);
    }
    // projection quad: v_q(bf16), q_x, v_s(bf16), k_x
    {
        GemmJobs jp = {};
        jp.j[0] = { p_qt, vqw,  vqb,  0, 0, 0, 0, 0,    p_vqh, 0 };
        jp.j[1] = { p_qt, qryw, qryb, 0, 0, 0, 0, p_qx, 0,     0 };
        jp.j[2] = { p_st, vsw,  vsb,  0, 0, 0, 0, 0,    p_vsh, 0 };
        jp.j[3] = { p_st, keyw, keyb, 0, 0, 0, 0, p_kx, 0,     0 };
        gemm_wx_t<<<dim3(18, BATCH, 4), 256>>>(jp, CC);
    }

    score_t<<<dim3(18, 18, BATCH), 256>>>();
    gate_kernel<<<dim3(2, BATCH), 128>>>(gw1, gb1, gw2, gb2);

    attn_t<<<dim3(18, BATCH, 2), 256>>>(Es, Eq);

    conv_t<<<dim3(18, BATCH), 256>>>(p_cwr, cg, cb, cm, cv, Eq, Es, feat);
}

// round 9
// speedup vs baseline: 3.3731x; 1.0318x over previous
#include <cuda_runtime.h>
#include <cuda_bf16.h>

#define BATCH 8
#define CIN   256
#define CC    128
#define NPIX  2304
#define EPSB  1e-5f

// ---------------- scratch ------------------------------------------------------
__device__ __align__(16) float g_qt[BATCH*CC*NPIX];
__device__ __align__(16) float g_st[BATCH*CC*NPIX];
__device__ __align__(16) float g_kx[BATCH*CC*NPIX];
__device__ __align__(16) float g_qx[BATCH*CC*NPIX];
__device__ __align__(16) unsigned short g_vqh[BATCH*CC*NPIX];   // bf16 v_q
__device__ __align__(16) unsigned short g_vsh[BATCH*CC*NPIX];   // bf16 v_s
__device__ __align__(16) unsigned short g_e[(size_t)BATCH*NPIX*NPIX]; // bf16 exp(A-lm)
__device__ __align__(16) float g_cwr[CC*2304];                  // tf32-rounded conv w
__device__ float g_tmax[BATCH*18*18];
__device__ float g_rpart[BATCH*18*NPIX];   // [b][mblock][n] row partial sums
__device__ float g_cpart[BATCH*18*NPIX];   // [b][nblock][m] col partial sums
__device__ unsigned g_bmaxk[BATCH];
__device__ float g_poolq[BATCH*18*CC];
__device__ float g_pools[BATCH*18*CC];
__device__ float g_gq[BATCH*CC];
__device__ float g_gs[BATCH*CC];

// ---------------- helpers ------------------------------------------------------
__device__ __forceinline__ float tf(float x) {
    unsigned u;
    asm("cvt.rna.tf32.f32 %0, %1;" : "=r"(u) : "f"(x));
    return __uint_as_float(u);
}
__device__ __forceinline__ float4 tf4(float4 v) {
    v.x = tf(v.x); v.y = tf(v.y); v.z = tf(v.z); v.w = tf(v.w); return v;
}
__device__ __forceinline__ unsigned fkey(float x) {
    int i = __float_as_int(x);
    return (i >= 0) ? ((unsigned)i | 0x80000000u) : ~(unsigned)i;
}
__device__ __forceinline__ float fdekey(unsigned u) {
    int i = (u & 0x80000000u) ? (int)(u & 0x7fffffffu) : ~(int)u;
    return __int_as_float(i);
}
__device__ __forceinline__ unsigned packbf(float a, float b) {
    __nv_bfloat162 h = __floats2bfloat162_rn(a, b);
    return *(unsigned*)&h;
}
__device__ __forceinline__ int cpos(int j) { return ((j & 3) << 2) | (j >> 2); }

__device__ __forceinline__ void mma_tf32(float* c,
    unsigned a0, unsigned a1, unsigned a2, unsigned a3, unsigned b0, unsigned b1)
{
    asm volatile(
        "mma.sync.aligned.m16n8k8.row.col.f32.tf32.tf32.f32 "
        "{%0,%1,%2,%3}, {%4,%5,%6,%7}, {%8,%9}, {%0,%1,%2,%3};"
        : "+f"(c[0]), "+f"(c[1]), "+f"(c[2]), "+f"(c[3])
        : "r"(a0), "r"(a1), "r"(a2), "r"(a3), "r"(b0), "r"(b1));
}
__device__ __forceinline__ void mma_bf16(float* c,
    unsigned a0, unsigned a1, unsigned a2, unsigned a3, unsigned b0, unsigned b1)
{
    asm volatile(
        "mma.sync.aligned.m16n8k16.row.col.f32.bf16.bf16.f32 "
        "{%0,%1,%2,%3}, {%4,%5,%6,%7}, {%8,%9}, {%0,%1,%2,%3};"
        : "+f"(c[0]), "+f"(c[1]), "+f"(c[2]), "+f"(c[3])
        : "r"(a0), "r"(a1), "r"(a2), "r"(a3), "r"(b0), "r"(b1));
}

// ---- fp32/tf32 path, 256-thread: block 128x128x16, warp 64x32 -----------------
__device__ __forceinline__ void mma_AB(float acc[4][4][4],
    const float* As, const float* Bs, int wm, int wn, int lane)
{
    const int gid = lane >> 2, t4 = lane & 3;
    const float4* As4 = (const float4*)As;
    float4 va[4][2];
#pragma unroll
    for (int mf = 0; mf < 4; ++mf) {
        int rb = wm*64 + mf*16 + gid;
        va[mf][0] = As4[rb*5 + t4];
        va[mf][1] = As4[(rb+8)*5 + t4];
    }
#pragma unroll
    for (int ko = 0; ko < 2; ++ko) {
        unsigned bf[4][2];
#pragma unroll
        for (int nf = 0; nf < 4; ++nf) {
            int nb = wn*32 + nf*8 + gid;
            bf[nf][0] = __float_as_uint(Bs[(ko*8+t4  )*136 + nb]);
            bf[nf][1] = __float_as_uint(Bs[(ko*8+t4+4)*136 + nb]);
        }
#pragma unroll
        for (int mf = 0; mf < 4; ++mf) {
            unsigned a0, a1, a2, a3;
            if (ko == 0) {
                a0 = __float_as_uint(va[mf][0].x); a1 = __float_as_uint(va[mf][1].x);
                a2 = __float_as_uint(va[mf][0].y); a3 = __float_as_uint(va[mf][1].y);
            } else {
                a0 = __float_as_uint(va[mf][0].z); a1 = __float_as_uint(va[mf][1].z);
                a2 = __float_as_uint(va[mf][0].w); a3 = __float_as_uint(va[mf][1].w);
            }
#pragma unroll
            for (int nf = 0; nf < 4; ++nf)
                mma_tf32(acc[mf][nf], a0, a1, a2, a3, bf[nf][0], bf[nf][1]);
        }
    }
}
// 512-thread variant: warp tile 32x32 (wm in 0..3)
__device__ __forceinline__ void mma_AB32(float acc[2][4][4],
    const float* As, const float* Bs, int wm, int wn, int lane)
{
    const int gid = lane >> 2, t4 = lane & 3;
    const float4* As4 = (const float4*)As;
    float4 va[2][2];
#pragma unroll
    for (int mf = 0; mf < 2; ++mf) {
        int rb = wm*32 + mf*16 + gid;
        va[mf][0] = As4[rb*5 + t4];
        va[mf][1] = As4[(rb+8)*5 + t4];
    }
#pragma unroll
    for (int ko = 0; ko < 2; ++ko) {
        unsigned bf[4][2];
#pragma unroll
        for (int nf = 0; nf < 4; ++nf) {
            int nb = wn*32 + nf*8 + gid;
            bf[nf][0] = __float_as_uint(Bs[(ko*8+t4  )*136 + nb]);
            bf[nf][1] = __float_as_uint(Bs[(ko*8+t4+4)*136 + nb]);
        }
#pragma unroll
        for (int mf = 0; mf < 2; ++mf) {
            unsigned a0, a1, a2, a3;
            if (ko == 0) {
                a0 = __float_as_uint(va[mf][0].x); a1 = __float_as_uint(va[mf][1].x);
                a2 = __float_as_uint(va[mf][0].y); a3 = __float_as_uint(va[mf][1].y);
            } else {
                a0 = __float_as_uint(va[mf][0].z); a1 = __float_as_uint(va[mf][1].z);
                a2 = __float_as_uint(va[mf][0].w); a3 = __float_as_uint(va[mf][1].w);
            }
#pragma unroll
            for (int nf = 0; nf < 4; ++nf)
                mma_tf32(acc[mf][nf], a0, a1, a2, a3, bf[nf][0], bf[nf][1]);
        }
    }
}
__device__ __forceinline__ void stA(float* As, int m, int aq, float4 v) {
    float* p = &As[m*20 + aq];
    p[0] = tf(v.x); p[4] = tf(v.y); p[8] = tf(v.z); p[12] = tf(v.w);
}
__device__ __forceinline__ void stAraw(float* As, int m, int aq, float4 v) {
    float* p = &As[m*20 + aq];
    p[0] = v.x; p[4] = v.y; p[8] = v.z; p[12] = v.w;
}

// ---- bf16 path: block 128x128x32, warp 64x32; A,B crosswise-uint stride 20 ----
__device__ __forceinline__ void mma_AB16(float acc[4][4][4],
    const unsigned* As, const unsigned* Bs, int wm, int wn, int lane)
{
    const int gid = lane >> 2, t4 = lane & 3;
    const uint4* A4 = (const uint4*)As;
    const uint4* B4 = (const uint4*)Bs;
    uint4 va[4][2], vb[4];
#pragma unroll
    for (int mf = 0; mf < 4; ++mf) {
        int rb = wm*64 + mf*16 + gid;
        va[mf][0] = A4[rb*5 + t4];
        va[mf][1] = A4[(rb+8)*5 + t4];
    }
#pragma unroll
    for (int nf = 0; nf < 4; ++nf) {
        int nb = wn*32 + nf*8 + gid;
        vb[nf] = B4[nb*5 + t4];
    }
#pragma unroll
    for (int mf = 0; mf < 4; ++mf)
#pragma unroll
        for (int nf = 0; nf < 4; ++nf)
            mma_bf16(acc[mf][nf], va[mf][0].x, va[mf][1].x, va[mf][0].y, va[mf][1].y,
                     vb[nf].x, vb[nf].y);
#pragma unroll
    for (int mf = 0; mf < 4; ++mf)
#pragma unroll
        for (int nf = 0; nf < 4; ++nf)
            mma_bf16(acc[mf][nf], va[mf][0].z, va[mf][1].z, va[mf][0].w, va[mf][1].w,
                     vb[nf].z, vb[nf].w);
}

#define ASZ (128*20)
#define BSZ (16*136)

__global__ void init_bmax() { if (threadIdx.x < BATCH) g_bmaxk[threadIdx.x] = 0u; }

__global__ void prep_cw(const float* __restrict__ cw, float* __restrict__ cwr) {
    int i = blockIdx.x*256 + threadIdx.x;
    if (i < CC*2304) cwr[i] = tf(cw[i]);
}

// ---------------- batched 1x1 conv GEMM jobs ------------------------------------
struct GemmJob {
    const float* x; const float* w; const float* bias;
    const float* bng; const float* bnb; const float* bnm; const float* bnv;
    float* out; unsigned short* outh; float* poolpart;
};
struct GemmJobs { GemmJob j[4]; };

__global__ __launch_bounds__(256, 2) void gemm_wx_t(GemmJobs jobs, int K)
{
    const GemmJob job = jobs.j[blockIdx.z];
    const int b  = blockIdx.y;
    const int p0 = blockIdx.x * 128;
    const float* xb = job.x + (size_t)b*K*NPIX;
    float* ob = job.out ? job.out + (size_t)b*CC*NPIX : 0;
    unsigned short* ohb = job.outh ? job.outh + (size_t)b*CC*NPIX : 0;
    const float* w = job.w;
    __shared__ __align__(16) float As[2][ASZ];
    __shared__ __align__(16) float Bs[2][BSZ];
    const int tid = threadIdx.x, lane = tid & 31, wid = tid >> 5;
    const int wm = wid & 1, wn = wid >> 1;
    const int gid = lane >> 2, t4 = lane & 3;
    const int am = tid >> 1, aq0 = 2*(tid & 1), aq1 = aq0 + 1;
    const int bk = tid >> 4, bq = tid & 15;
    float acc[4][4][4] = {};
    float4 pa0, pa1, pb0, pb1;
    pa0 = *(const float4*)&w[am*K + aq0*4];
    pa1 = *(const float4*)&w[am*K + aq1*4];
    pb0 = *(const float4*)&xb[(size_t)bk*NPIX + p0 + bq*4];
    pb1 = *(const float4*)&xb[(size_t)bk*NPIX + p0 + 64 + bq*4];
    stA(As[0], am, aq0, pa0); stA(As[0], am, aq1, pa1);
    *(float4*)&Bs[0][bk*136 + bq*4]      = tf4(pb0);
    *(float4*)&Bs[0][bk*136 + 64 + bq*4] = tf4(pb1);
    __syncthreads();
    const int iters = K / 16;
    for (int it = 0; it < iters; ++it) {
        if (it + 1 < iters) {
            int k0 = (it+1)*16;
            pa0 = *(const float4*)&w[am*K + k0 + aq0*4];
            pa1 = *(const float4*)&w[am*K + k0 + aq1*4];
            pb0 = *(const float4*)&xb[(size_t)(k0+bk)*NPIX + p0 + bq*4];
            pb1 = *(const float4*)&xb[(size_t)(k0+bk)*NPIX + p0 + 64 + bq*4];
        }
        mma_AB(acc, As[it & 1], Bs[it & 1], wm, wn, lane);
        if (it + 1 < iters) {
            int nb = (it+1) & 1;
            stA(As[nb], am, aq0, pa0); stA(As[nb], am, aq1, pa1);
            *(float4*)&Bs[nb][bk*136 + bq*4]      = tf4(pb0);
            *(float4*)&Bs[nb][bk*136 + 64 + bq*4] = tf4(pb1);
        }
        __syncthreads();
    }
    float rsum[8];
#pragma unroll
    for (int mf = 0; mf < 4; ++mf)
#pragma unroll
        for (int h = 0; h < 2; ++h) {
            int o = wm*64 + mf*16 + gid + h*8;
            float sc = 1.0f, cb = job.bias[o];
            if (job.bng) {
                sc = job.bng[o] * rsqrtf(job.bnv[o] + EPSB);
                cb = (job.bias[o] - job.bnm[o]) * sc + job.bnb[o];
            }
            float sm = 0.f;
#pragma unroll
            for (int nf = 0; nf < 4; ++nf) {
                int cl = wn*32 + nf*8 + t4*2;
                float2 r;
                r.x = acc[mf][nf][2*h+0]*sc + cb;
                r.y = acc[mf][nf][2*h+1]*sc + cb;
                sm += r.x + r.y;
                if (ohb)
                    *(unsigned*)&ohb[(size_t)o*NPIX + p0 + cl] = packbf(r.x, r.y);
                else
                    *(float2*)&ob[(size_t)o*NPIX + p0 + cl] = r;
            }
            rsum[mf*2+h] = sm;
        }
    if (job.poolpart) {
        float* redp = (float*)As;
        __syncthreads();
#pragma unroll
        for (int j = 0; j < 8; ++j) {
            float v = rsum[j];
            v += __shfl_xor_sync(~0u, v, 1);
            v += __shfl_xor_sync(~0u, v, 2);
            if (t4 == 0) {
                int row = wm*64 + (j>>1)*16 + gid + (j&1)*8;
                redp[wn*128 + row] = v;
            }
        }
        __syncthreads();
        if (tid < 128)
            job.poolpart[((size_t)b*18 + blockIdx.x)*CC + tid] =
                redp[tid] + redp[128+tid] + redp[256+tid] + redp[384+tid];
    }
}

// ---------------- score: e = bf16(exp(A - blkmax)); maxima + partial sums -------
__global__ __launch_bounds__(256, 2) void score_t()
{
    const int b  = blockIdx.z;
    const int n0 = blockIdx.y * 128;
    const int m0 = blockIdx.x * 128;
    const float* kx = g_kx + (size_t)b*CC*NPIX;
    const float* qx = g_qx + (size_t)b*CC*NPIX;
    unsigned short* eb = g_e + (size_t)b*NPIX*NPIX;
    __shared__ __align__(16) float As[2][BSZ];
    __shared__ __align__(16) float Bs[2][BSZ];
    __shared__ float smax[8];
    const int tid = threadIdx.x, lane = tid & 31, wid = tid >> 5;
    const int wm = wid & 1, wn = wid >> 1;
    const int gid = lane >> 2, t4 = lane & 3;
    const int ak = tid >> 4, aq = tid & 15;
    float acc[4][4][4] = {};
    float4 pa0, pa1, pb0, pb1;
    pa0 = *(const float4*)&kx[(size_t)ak*NPIX + n0 + aq*4];
    pa1 = *(const float4*)&kx[(size_t)ak*NPIX + n0 + 64 + aq*4];
    pb0 = *(const float4*)&qx[(size_t)ak*NPIX + m0 + aq*4];
    pb1 = *(const float4*)&qx[(size_t)ak*NPIX + m0 + 64 + aq*4];
    *(float4*)&As[0][ak*136 + aq*4]      = tf4(pa0);
    *(float4*)&As[0][ak*136 + 64 + aq*4] = tf4(pa1);
    *(float4*)&Bs[0][ak*136 + aq*4]      = tf4(pb0);
    *(float4*)&Bs[0][ak*136 + 64 + aq*4] = tf4(pb1);
    __syncthreads();
    for (int it = 0; it < CC/16; ++it) {
        if (it + 1 < CC/16) {
            int k0 = (it+1)*16;
            pa0 = *(const float4*)&kx[(size_t)(k0+ak)*NPIX + n0 + aq*4];
            pa1 = *(const float4*)&kx[(size_t)(k0+ak)*NPIX + n0 + 64 + aq*4];
            pb0 = *(const float4*)&qx[(size_t)(k0+ak)*NPIX + m0 + aq*4];
            pb1 = *(const float4*)&qx[(size_t)(k0+ak)*NPIX + m0 + 64 + aq*4];
        }
        {
            const float* Asb = As[it & 1];
            const float* Bsb = Bs[it & 1];
#pragma unroll
            for (int ko = 0; ko < 2; ++ko) {
                unsigned bf[4][2];
#pragma unroll
                for (int nf = 0; nf < 4; ++nf) {
                    int nb = wn*32 + nf*8 + gid;
                    bf[nf][0] = __float_as_uint(Bsb[(ko*8+t4  )*136 + nb]);
                    bf[nf][1] = __float_as_uint(Bsb[(ko*8+t4+4)*136 + nb]);
                }
#pragma unroll
                for (int mf = 0; mf < 4; ++mf) {
                    int rb = wm*64 + mf*16 + gid;
                    unsigned a0 = __float_as_uint(Asb[(ko*8+t4  )*136 + rb]);
                    unsigned a1 = __float_as_uint(Asb[(ko*8+t4  )*136 + rb+8]);
                    unsigned a2 = __float_as_uint(Asb[(ko*8+t4+4)*136 + rb]);
                    unsigned a3 = __float_as_uint(Asb[(ko*8+t4+4)*136 + rb+8]);
#pragma unroll
                    for (int nf = 0; nf < 4; ++nf)
                        mma_tf32(acc[mf][nf], a0, a1, a2, a3, bf[nf][0], bf[nf][1]);
                }
            }
        }
        if (it + 1 < CC/16) {
            int nb = (it+1) & 1;
            *(float4*)&As[nb][ak*136 + aq*4]      = tf4(pa0);
            *(float4*)&As[nb][ak*136 + 64 + aq*4] = tf4(pa1);
            *(float4*)&Bs[nb][ak*136 + aq*4]      = tf4(pb0);
            *(float4*)&Bs[nb][ak*136 + 64 + aq*4] = tf4(pb1);
        }
        __syncthreads();
    }
    float mx = -1e30f;
#pragma unroll
    for (int mf = 0; mf < 4; ++mf)
#pragma unroll
        for (int nf = 0; nf < 4; ++nf)
#pragma unroll
            for (int v = 0; v < 4; ++v) mx = fmaxf(mx, acc[mf][nf][v]);
#pragma unroll
    for (int o = 16; o; o >>= 1) mx = fmaxf(mx, __shfl_xor_sync(~0u, mx, o));
    if (lane == 0) smax[wid] = mx;
    __syncthreads();
    float lm = smax[0];
#pragma unroll
    for (int j = 1; j < 8; ++j) lm = fmaxf(lm, smax[j]);
    float rowp[8] = {};
    float colp[8] = {};
#pragma unroll
    for (int mf = 0; mf < 4; ++mf)
#pragma unroll
        for (int h = 0; h < 2; ++h) {
            int n = n0 + wm*64 + mf*16 + gid + h*8;
#pragma unroll
            for (int nf = 0; nf < 4; ++nf) {
                int cl = wn*32 + nf*8 + t4*2;
                float e0 = __expf(acc[mf][nf][2*h+0] - lm);
                float e1 = __expf(acc[mf][nf][2*h+1] - lm);
                *(unsigned*)(eb + (size_t)n*NPIX + m0 + cl) = packbf(e0, e1);
                rowp[mf*2+h] += e0 + e1;
                colp[nf*2+0] += e0;
                colp[nf*2+1] += e1;
            }
        }
    float* rowred = (float*)As;           // 4 x 128
    float* colred = rowred + 512;         // 16 x 132
    __syncthreads();
#pragma unroll
    for (int j = 0; j < 8; ++j) {
        float v = rowp[j];
        v += __shfl_xor_sync(~0u, v, 1);
        v += __shfl_xor_sync(~0u, v, 2);
        if (t4 == 0)
            rowred[wn*128 + wm*64 + (j>>1)*16 + gid + (j&1)*8] = v;
    }
#pragma unroll
    for (int j = 0; j < 8; ++j) {
        int cl = wn*32 + (j>>1)*8 + t4*2 + (j&1);
        colred[(wm*8+gid)*132 + cl] = colp[j];
    }
    __syncthreads();
    if (tid < 128) {
        float r = rowred[tid] + rowred[128+tid] + rowred[256+tid] + rowred[384+tid];
        g_rpart[((size_t)b*18 + blockIdx.x)*NPIX + n0 + tid] = r;
        float c = 0.f;
#pragma unroll
        for (int i = 0; i < 16; ++i) c += colred[i*132 + tid];
        g_cpart[((size_t)b*18 + blockIdx.y)*NPIX + m0 + tid] = c;
    }
    if (tid == 0) {
        g_tmax[(b*18 + blockIdx.y)*18 + blockIdx.x] = lm;
        atomicMax(&g_bmaxk[b], fkey(lm));
    }
}

// ---------------- channel gate --------------------------------------------------
__global__ __launch_bounds__(128) void gate_kernel(
    const float* __restrict__ w1, const float* __restrict__ b1,
    const float* __restrict__ w2, const float* __restrict__ b2)
{
    const int b = blockIdx.y;
    const float* pp = (blockIdx.x == 0 ? g_poolq : g_pools) + (size_t)b*18*CC;
    float* go = (blockIdx.x == 0 ? g_gq : g_gs) + b*CC;
    __shared__ float pool[CC];
    __shared__ float hsh[8];
    const int tid = threadIdx.x;
    {
        float s = 0.f;
#pragma unroll
        for (int j = 0; j < 18; ++j) s += pp[j*CC + tid];
        pool[tid] = s * (1.0f/NPIX);
    }
    __syncthreads();
    if (tid < 8) {
        float h = b1[tid];
        for (int i = 0; i < CC; ++i) h += pool[i] * w1[tid*CC + i];
        hsh[tid] = fmaxf(h, 0.f);
    }
    __syncthreads();
    float z = b2[tid];
#pragma unroll
    for (int j = 0; j < 8; ++j) z += hsh[j] * w2[tid*8 + j];
    go[tid] = 1.0f / (1.0f + __expf(-z));
}

// ---------------- merged attention: z=0 -> E_s, z=1 -> E_q ----------------------
__global__ __launch_bounds__(256, 2) void attn_t(float* __restrict__ Es,
                                                 float* __restrict__ Eq)
{
    const int z  = blockIdx.z;
    const int b  = blockIdx.y;
    const int x0 = blockIdx.x * 128;       // n0 (z=0) or m0 (z=1)
    const unsigned short* eb = g_e + (size_t)b*NPIX*NPIX;
    const unsigned* vh = (const unsigned*)(z == 0 ? g_vsh : g_vqh)
                       + (size_t)b*CC*(NPIX/2);
    const float* resb = (z == 0 ? g_st : g_qt) + (size_t)b*CC*NPIX;
    const float* gt   = (z == 0 ? g_gs : g_gq) + b*CC;
    float* Eb = (z == 0 ? Es : Eq) + (size_t)b*CC*NPIX;
    __shared__ unsigned As[2][ASZ];
    __shared__ unsigned Bs[2][ASZ];
    __shared__ float tmx[18];
    __shared__ int   ordsh[18];
    __shared__ float ratio[18];
    __shared__ float inv_s[128];
    const int tid = threadIdx.x, lane = tid & 31, wid = tid >> 5;
    const int wm = wid & 1, wn = wid >> 1;
    const int gid = lane >> 2, t4 = lane & 3;
    const int am = tid >> 1, half = tid & 1;
    const float bmax = fdekey(g_bmaxk[b]);
    if (tid < 18)
        tmx[tid] = (z == 0) ? g_tmax[(b*18 + blockIdx.x)*18 + tid]
                            : g_tmax[(b*18 + tid)*18 + blockIdx.x];
    __syncthreads();
    if (tid < 18) {
        float mine = tmx[tid];
        int rank = 0;
        for (int j = 0; j < 18; ++j) {
            float o = tmx[j];
            rank += (o < mine) || (o == mine && j < tid);
        }
        ordsh[rank] = tid;
    }
    __syncthreads();
    if (tid < 18)
        ratio[tid] = (tid == 0) ? 1.0f : __expf(tmx[ordsh[tid-1]] - tmx[ordsh[tid]]);
    if (tid >= 32 && tid < 160) {
        int i = tid - 32;
        const float* part = (z == 0 ? g_rpart : g_cpart);
        float s = 0.f;
#pragma unroll
        for (int t = 0; t < 18; ++t)
            s += __expf(tmx[t] - bmax) * part[((size_t)b*18 + t)*NPIX + x0 + i];
        inv_s[i] = s;
    }
    __syncthreads();
    if (tid < 128) {
        float slast = __expf(tmx[ordsh[17]] - bmax);
        inv_s[tid] = slast / inv_s[tid];
    }
    float acc[4][4][4] = {};
    const unsigned* arow = vh + (size_t)am*(NPIX/2) + half*8;

    if (z == 0) {
        const unsigned* erow = (const unsigned*)(eb + (size_t)(x0+am)*NPIX) + half*8;
        uint4 pa0, pa1, pb0, pb1;
        {
            int ko2 = ordsh[0]*64;
            pa0 = *(const uint4*)&arow[ko2];  pa1 = *(const uint4*)&arow[ko2+4];
            pb0 = *(const uint4*)&erow[ko2];  pb1 = *(const uint4*)&erow[ko2+4];
        }
        auto store = [&](int buf) {
            unsigned* Ap = &As[buf][am*20];
            unsigned* Bp = &Bs[buf][am*20];
            unsigned ua[8] = {pa0.x,pa0.y,pa0.z,pa0.w, pa1.x,pa1.y,pa1.z,pa1.w};
            unsigned ub[8] = {pb0.x,pb0.y,pb0.z,pb0.w, pb1.x,pb1.y,pb1.z,pb1.w};
#pragma unroll
            for (int i = 0; i < 8; ++i) {
                int c = cpos(half*8 + i);
                Ap[c] = ua[i];
                Bp[c] = ub[i];
            }
        };
        store(0);
        __syncthreads();
        for (int it = 0; it < 72; ++it) {
            if (it + 1 < 72) {
                int nit = it + 1;
                int ko2 = ordsh[nit>>2]*64 + (nit&3)*16;
                pa0 = *(const uint4*)&arow[ko2];  pa1 = *(const uint4*)&arow[ko2+4];
                pb0 = *(const uint4*)&erow[ko2];  pb1 = *(const uint4*)&erow[ko2+4];
            }
            if ((it & 3) == 0 && it) {
                float r = ratio[it>>2];
#pragma unroll
                for (int mf = 0; mf < 4; ++mf)
#pragma unroll
                    for (int nf = 0; nf < 4; ++nf)
#pragma unroll
                        for (int v = 0; v < 4; ++v) acc[mf][nf][v] *= r;
            }
            mma_AB16(acc, As[it & 1], Bs[it & 1], wm, wn, lane);
            if (it + 1 < 72) store((it+1) & 1);
            __syncthreads();
        }
    } else {
        const int np = tid >> 4, mseg = tid & 15;
        const unsigned* ebase = (const unsigned*)eb + x0/2 + mseg*4;
        const int ppos = cpos(np);
        uint4 pa0, pa1, pb0, pb1;
        {
            int k0 = ordsh[0]*128;
            pa0 = *(const uint4*)&arow[ordsh[0]*64];
            pa1 = *(const uint4*)&arow[ordsh[0]*64 + 4];
            pb0 = *(const uint4*)&ebase[(size_t)(k0 + 2*np    )*(NPIX/2)];
            pb1 = *(const uint4*)&ebase[(size_t)(k0 + 2*np + 1)*(NPIX/2)];
        }
        auto store = [&](int buf) {
            unsigned* Ap = &As[buf][am*20];
            unsigned ua[8] = {pa0.x,pa0.y,pa0.z,pa0.w, pa1.x,pa1.y,pa1.z,pa1.w};
#pragma unroll
            for (int i = 0; i < 8; ++i) Ap[cpos(half*8 + i)] = ua[i];
            unsigned u0[4] = {pb0.x, pb0.y, pb0.z, pb0.w};
            unsigned u1[4] = {pb1.x, pb1.y, pb1.z, pb1.w};
#pragma unroll
            for (int jj = 0; jj < 4; ++jj) {
                unsigned q0 = __byte_perm(u0[jj], u1[jj], 0x5410);
                unsigned q1 = __byte_perm(u0[jj], u1[jj], 0x7632);
                int ml = mseg*8 + 2*jj;
                Bs[buf][ml*20 + ppos]     = q0;
                Bs[buf][(ml+1)*20 + ppos] = q1;
            }
        };
        store(0);
        __syncthreads();
        for (int it = 0; it < 72; ++it) {
            if (it + 1 < 72) {
                int nit = it + 1;
                int kt = ordsh[nit>>2];
                int k0 = kt*128 + (nit&3)*32;
                pa0 = *(const uint4*)&arow[kt*64 + (nit&3)*16];
                pa1 = *(const uint4*)&arow[kt*64 + (nit&3)*16 + 4];
                pb0 = *(const uint4*)&ebase[(size_t)(k0 + 2*np    )*(NPIX/2)];
                pb1 = *(const uint4*)&ebase[(size_t)(k0 + 2*np + 1)*(NPIX/2)];
            }
            if ((it & 3) == 0 && it) {
                float r = ratio[it>>2];
#pragma unroll
                for (int mf = 0; mf < 4; ++mf)
#pragma unroll
                    for (int nf = 0; nf < 4; ++nf)
#pragma unroll
                        for (int v = 0; v < 4; ++v) acc[mf][nf][v] *= r;
            }
            mma_AB16(acc, As[it & 1], Bs[it & 1], wm, wn, lane);
            if (it + 1 < 72) store((it+1) & 1);
            __syncthreads();
        }
    }
#pragma unroll
    for (int mf = 0; mf < 4; ++mf)
#pragma unroll
        for (int h = 0; h < 2; ++h) {
            int co = wm*64 + mf*16 + gid + h*8;
            float g = gt[co];
#pragma unroll
            for (int nf = 0; nf < 4; ++nf) {
                int cl = wn*32 + nf*8 + t4*2;
                float2 res = *(const float2*)&resb[(size_t)co*NPIX + x0 + cl];
                float2 r;
                r.x = g*acc[mf][nf][2*h+0]*inv_s[cl]   + res.x;
                r.y = g*acc[mf][nf][2*h+1]*inv_s[cl+1] + res.y;
                *(float2*)&Eb[(size_t)co*NPIX + x0 + cl] = r;
            }
        }
}

// ---------------- 3x3 conv: 512 threads, warp tile 32x32, tf32 ------------------
__global__ __launch_bounds__(512) void conv_t(
    const float* __restrict__ cwr, const float* __restrict__ cg,
    const float* __restrict__ cb, const float* __restrict__ cm,
    const float* __restrict__ cv,
    const float* __restrict__ Eq, const float* __restrict__ Es,
    float* __restrict__ feat)
{
    const int b  = blockIdx.y;
    const int p0 = blockIdx.x * 128;
    const float* Eqb = Eq + (size_t)b*CC*NPIX;
    const float* Esb = Es + (size_t)b*CC*NPIX;
    float* fb = feat + (size_t)b*CC*NPIX;
    __shared__ __align__(16) float As[2][ASZ];
    __shared__ __align__(16) float Bs[2][BSZ];
    const int tid = threadIdx.x, lane = tid & 31, wid = tid >> 5;
    const int wm = wid & 3, wn = wid >> 2;           // 4 x 4 warps
    const int gid = lane >> 2, t4 = lane & 3;
    const int am = tid >> 2, aq = tid & 3;           // A: 1 float4 / thread
    const int bk = tid >> 5, bq = tid & 31;          // B: 4 pixels / thread
    int hh[4], ww[4];
#pragma unroll
    for (int j = 0; j < 4; ++j) {
        int p = p0 + bq*4 + j;
        hh[j] = p / 48; ww[j] = p - hh[j]*48;
    }
    auto loadB = [&](int k0, float4& v) {
        int kap = k0 + bk;
        int ic = kap / 9, kk = kap - ic*9;
        int dh = kk/3 - 1, dw = kk - (kk/3)*3 - 1;
        const float* src = (ic < CC) ? Eqb : Esb;
        const float* sp = src + (size_t)(ic & (CC-1))*NPIX;
        float* vp = (float*)&v;
#pragma unroll
        for (int j = 0; j < 4; ++j) {
            int ih = hh[j] + dh, iw = ww[j] + dw;
            vp[j] = ((unsigned)ih < 48u && (unsigned)iw < 48u)
                  ? sp[ih*48 + iw] : 0.f;
        }
    };
    float acc[2][4][4] = {};
    float4 pa, pb;
    pa = *(const float4*)&cwr[am*2304 + aq*4];
    loadB(0, pb);
    stAraw(As[0], am, aq, pa);
    *(float4*)&Bs[0][bk*136 + bq*4] = tf4(pb);
    __syncthreads();
    for (int it = 0; it < 144; ++it) {
        if (it + 1 < 144) {
            int k0 = (it+1)*16;
            pa = *(const float4*)&cwr[am*2304 + k0 + aq*4];
            loadB(k0, pb);
        }
        mma_AB32(acc, As[it & 1], Bs[it & 1], wm, wn, lane);
        if (it + 1 < 144) {
            int nb = (it+1) & 1;
            stAraw(As[nb], am, aq, pa);
            *(float4*)&Bs[nb][bk*136 + bq*4] = tf4(pb);
        }
        __syncthreads();
    }
#pragma unroll
    for (int mf = 0; mf < 2; ++mf)
#pragma unroll
        for (int h = 0; h < 2; ++h) {
            int o = wm*32 + mf*16 + gid + h*8;
            float sc  = cg[o] * rsqrtf(cv[o] + EPSB);
            float cbv = cb[o] - cm[o]*sc;
#pragma unroll
            for (int nf = 0; nf < 4; ++nf) {
                int cl = wn*32 + nf*8 + t4*2;
                float2 r;
                r.x = fmaxf(acc[mf][nf][2*h+0]*sc + cbv, 0.f);
                r.y = fmaxf(acc[mf][nf][2*h+1]*sc + cbv, 0.f);
                *(float2*)&fb[(size_t)o*NPIX + p0 + cl] = r;
            }
        }
}

// ---------------- host ----------------------------------------------------------
extern "C" void kernel_launch(void* const* d_in, const int* in_sizes, int n_in,
                              void* d_out, int out_size)
{
    (void)in_sizes; (void)n_in; (void)out_size;
    const float* q    = (const float*)d_in[0];
    const float* s    = (const float*)d_in[1];
    const float* tsw  = (const float*)d_in[2];
    const float* tsb  = (const float*)d_in[3];
    const float* bsg  = (const float*)d_in[4];
    const float* bsb  = (const float*)d_in[5];
    const float* bsm  = (const float*)d_in[6];
    const float* bsv  = (const float*)d_in[7];
    const float* tqw  = (const float*)d_in[8];
    const float* tqb  = (const float*)d_in[9];
    const float* bqg  = (const float*)d_in[10];
    const float* bqb  = (const float*)d_in[11];
    const float* bqm  = (const float*)d_in[12];
    const float* bqv  = (const float*)d_in[13];
    const float* vqw  = (const float*)d_in[14];
    const float* vqb  = (const float*)d_in[15];
    const float* vsw  = (const float*)d_in[16];
    const float* vsb  = (const float*)d_in[17];
    const float* keyw = (const float*)d_in[18];
    const float* keyb = (const float*)d_in[19];
    const float* qryw = (const float*)d_in[20];
    const float* qryb = (const float*)d_in[21];
    const float* gw1  = (const float*)d_in[22];
    const float* gb1  = (const float*)d_in[23];
    const float* gw2  = (const float*)d_in[24];
    const float* gb2  = (const float*)d_in[25];
    const float* cw   = (const float*)d_in[26];
    const float* cg   = (const float*)d_in[27];
    const float* cb   = (const float*)d_in[28];
    const float* cm   = (const float*)d_in[29];
    const float* cv   = (const float*)d_in[30];

    float *p_qt, *p_st, *p_kx, *p_qx, *p_pq, *p_ps, *p_cwr;
    unsigned short *p_vqh, *p_vsh;
    cudaGetSymbolAddress((void**)&p_qt,  g_qt);
    cudaGetSymbolAddress((void**)&p_st,  g_st);
    cudaGetSymbolAddress((void**)&p_kx,  g_kx);
    cudaGetSymbolAddress((void**)&p_qx,  g_qx);
    cudaGetSymbolAddress((void**)&p_pq,  g_poolq);
    cudaGetSymbolAddress((void**)&p_ps,  g_pools);
    cudaGetSymbolAddress((void**)&p_cwr, g_cwr);
    cudaGetSymbolAddress((void**)&p_vqh, g_vqh);
    cudaGetSymbolAddress((void**)&p_vsh, g_vsh);

    float* feat = (float*)d_out;
    float* Eq   = feat + (size_t)BATCH*CC*NPIX;
    float* Es   = Eq   + (size_t)BATCH*CC*NPIX;

    init_bmax<<<1, 32>>>();
    prep_cw<<<1152, 256>>>(cw, p_cwr);

    // trans pair: z=0 -> q', z=1 -> s'
    {
        GemmJobs jt = {};
        jt.j[0] = { q, tqw, tqb, bqg, bqb, bqm, bqv, p_qt, 0, p_pq };
        jt.j[1] = { s, tsw, tsb, bsg, bsb, bsm, bsv, p_st, 0, p_ps };
        gemm_wx_t<<<dim3(18, BATCH, 2), 256>>>(jt, CIN);
    }
    // projection quad: v_q(bf16), q_x, v_s(bf16), k_x
    {
        GemmJobs jp = {};
        jp.j[0] = { p_qt, vqw,  vqb,  0, 0, 0, 0, 0,    p_vqh, 0 };
        jp.j[1] = { p_qt, qryw, qryb, 0, 0, 0, 0, p_qx, 0,     0 };
        jp.j[2] = { p_st, vsw,  vsb,  0, 0, 0, 0, 0,    p_vsh, 0 };
        jp.j[3] = { p_st, keyw, keyb, 0, 0, 0, 0, p_kx, 0,     0 };
        gemm_wx_t<<<dim3(18, BATCH, 4), 256>>>(jp, CC);
    }

    score_t<<<dim3(18, 18, BATCH), 256>>>();
    gate_kernel<<<dim3(2, BATCH), 128>>>(gw1, gb1, gw2, gb2);

    attn_t<<<dim3(18, BATCH, 2), 256>>>(Es, Eq);

    conv_t<<<dim3(18, BATCH), 512>>>(p_cwr, cg, cb, cm, cv, Eq, Es, feat);
}